// round 4
// baseline (speedup 1.0000x reference)
#include <cuda_runtime.h>
#include <cuda_bf16.h>
#include <math.h>
#include <stdint.h>

#define BSZ 8
#define LSEQ 2048
#define DM 512
#define NS 64
#define EMB 512
#define CHK 8
#define TCH 256   // LSEQ / CHK

typedef unsigned long long ull;

// Scratch (allocation-free rule: __device__ globals)
__device__ float g_xn[BSZ * LSEQ * DM];            // LayerNorm output
__device__ float g_yp[BSZ * LSEQ * DM];            // partial y (pre-fixup), f32
__device__ __nv_bfloat16 g_y2h[BSZ * LSEQ * DM];   // y2 hi split
__device__ __nv_bfloat16 g_y2l[BSZ * LSEQ * DM];   // y2 lo split
__device__ __nv_bfloat16 g_Wh[2 * DM * DM];        // W hi split
__device__ __nv_bfloat16 g_Wl[2 * DM * DM];        // W lo split
__device__ float g_film[BSZ * 2 * DM];
__device__ ull g_str[BSZ * CHK * DM * 32];         // local end-state (real, f32x2 pairs)
__device__ ull g_sti[BSZ * CHK * DM * 32];         // local end-state (imag)

// ---------------------------------------------------------------------------
// f32x2 packed-math helpers
// ---------------------------------------------------------------------------
__device__ __forceinline__ ull pk2(float a, float b) {
    ull r;
    asm("mov.b64 %0, {%1, %2};" : "=l"(r) : "f"(a), "f"(b));
    return r;
}
__device__ __forceinline__ float2 upk2(ull v) {
    float2 f;
    asm("mov.b64 {%0, %1}, %2;" : "=f"(f.x), "=f"(f.y) : "l"(v));
    return f;
}
__device__ __forceinline__ ull fma2(ull a, ull b, ull c) {
    ull d;
    asm("fma.rn.f32x2 %0, %1, %2, %3;" : "=l"(d) : "l"(a), "l"(b), "l"(c));
    return d;
}
__device__ __forceinline__ ull mul2(ull a, ull b) {
    ull d;
    asm("mul.rn.f32x2 %0, %1, %2;" : "=l"(d) : "l"(a), "l"(b));
    return d;
}
__device__ __forceinline__ ull add2(ull a, ull b) {
    ull d;
    asm("add.rn.f32x2 %0, %1, %2;" : "=l"(d) : "l"(a), "l"(b));
    return d;
}

__device__ __forceinline__ void cpa16(uint32_t dst, const void* src) {
    asm volatile("cp.async.cg.shared.global [%0], [%1], 16;" :: "r"(dst), "l"(src));
}

// ---------------------------------------------------------------------------
// Kernel 1: LayerNorm
// ---------------------------------------------------------------------------
__global__ void ln_kernel(const float* __restrict__ x,
                          const float* __restrict__ gamma,
                          const float* __restrict__ beta) {
    const int row = blockIdx.x;
    const int t = threadIdx.x;
    const float4* xr = (const float4*)(x + (size_t)row * DM);
    float4 v = xr[t];
    float s  = v.x + v.y + v.z + v.w;
    float ss = v.x * v.x + v.y * v.y + v.z * v.z + v.w * v.w;

    __shared__ float sh[8];
    #pragma unroll
    for (int o = 16; o; o >>= 1) {
        s  += __shfl_xor_sync(0xffffffffu, s, o);
        ss += __shfl_xor_sync(0xffffffffu, ss, o);
    }
    int w = t >> 5;
    if ((t & 31) == 0) { sh[w] = s; sh[4 + w] = ss; }
    __syncthreads();
    float S  = sh[0] + sh[1] + sh[2] + sh[3];
    float SS = sh[4] + sh[5] + sh[6] + sh[7];

    const float inv = 1.0f / (float)DM;
    float mu = S * inv;
    float var = SS * inv - mu * mu;
    float rs = rsqrtf(var + 1e-5f);

    float4 g4 = ((const float4*)gamma)[t];
    float4 b4 = ((const float4*)beta)[t];
    float4 o4;
    o4.x = (v.x - mu) * rs * g4.x + b4.x;
    o4.y = (v.y - mu) * rs * g4.y + b4.y;
    o4.z = (v.z - mu) * rs * g4.z + b4.z;
    o4.w = (v.w - mu) * rs * g4.w + b4.w;
    ((float4*)(g_xn + (size_t)row * DM))[t] = o4;
}

// ---------------------------------------------------------------------------
// Kernel 2: FiLM params
// ---------------------------------------------------------------------------
__global__ void film_kernel(const float* __restrict__ emb,
                            const float* __restrict__ Wf,
                            const float* __restrict__ bf) {
    __shared__ float se[EMB];
    const int b = blockIdx.x;
    for (int i = threadIdx.x; i < EMB; i += blockDim.x) {
        float e = emb[b * EMB + i];
        se[i] = e / (1.0f + expf(-e));
    }
    __syncthreads();
    for (int j = threadIdx.x; j < 2 * DM; j += blockDim.x) {
        const float4* wr = (const float4*)(Wf + (size_t)j * EMB);
        const float4* sr = (const float4*)se;
        float acc = bf[j];
        #pragma unroll 4
        for (int q = 0; q < EMB / 4; q++) {
            float4 w = wr[q], sv = sr[q];
            acc += w.x * sv.x + w.y * sv.y + w.z * sv.z + w.w * sv.w;
        }
        g_film[b * 2 * DM + j] = acc;
    }
}

// ---------------------------------------------------------------------------
// Kernel 2b: split W into bf16 hi/lo
// ---------------------------------------------------------------------------
__global__ void prep_w(const float* __restrict__ W) {
    int i = blockIdx.x * blockDim.x + threadIdx.x;
    float4 v = ((const float4*)W)[i];
    float e[4] = {v.x, v.y, v.z, v.w};
    ushort4 h4, l4;
    unsigned short* hp = &h4.x;
    unsigned short* lp = &l4.x;
    #pragma unroll
    for (int j = 0; j < 4; j++) {
        __nv_bfloat16 h = __float2bfloat16_rn(e[j]);
        __nv_bfloat16 l = __float2bfloat16_rn(e[j] - __bfloat162float(h));
        hp[j] = __bfloat16_as_ushort(h);
        lp[j] = __bfloat16_as_ushort(l);
    }
    ((ushort4*)g_Wh)[i] = h4;
    ((ushort4*)g_Wl)[i] = l4;
}

// ---------------------------------------------------------------------------
// Kernel 3a: local S4D scan over one chunk of TCH steps (zero initial state).
// 16 lanes per d, 2 f32x2 complex pairs per lane. Block = 8 d of one (b,c).
// Writes v_partial (f32) incl. D-skip + FiLM; dumps end states.
// ---------------------------------------------------------------------------
__global__ void scan_local(const float* __restrict__ A_real,
                           const float* __restrict__ A_imag,
                           const float* __restrict__ Cp,
                           const float* __restrict__ log_dt,
                           const float* __restrict__ B_ssm,
                           const float* __restrict__ D_skip) {
    const int t = threadIdx.x;
    const int grp = t >> 4;           // 0..7
    const int g = t & 15;
    const int blk = blockIdx.x;
    const int c = blk & 7;
    const int rest = blk >> 3;        // 0..511
    const int gid = rest * 8 + grp;
    const int b = gid >> 9;
    const int d = gid & 511;
    const int d0 = (rest * 8) & 511;

    const float dt = expf(log_dt[d]);
    ull Abr[2], Abi[2], nAbi[2], Ccr[2], nCci[2], s_r[2], s_i[2];
    #pragma unroll
    for (int p = 0; p < 2; p++) {
        float abr[2], abi[2], ccr[2], cci[2];
        #pragma unroll
        for (int j = 0; j < 2; j++) {
            int n = g * 4 + p * 2 + j;
            float ar = dt * A_real[d * NS + n];
            float ai = dt * A_imag[d * NS + n];
            float er = expf(ar), sb, cb;
            sincosf(ai, &sb, &cb);
            abr[j] = er * cb;
            abi[j] = er * sb;
            float bs = B_ssm[d * NS + n];
            ccr[j] = Cp[(d * NS + n) * 2 + 0] * bs;
            cci[j] = Cp[(d * NS + n) * 2 + 1] * bs;
        }
        Abr[p]  = pk2(abr[0], abr[1]);
        Abi[p]  = pk2(abi[0], abi[1]);
        nAbi[p] = pk2(-abi[0], -abi[1]);
        Ccr[p]  = pk2(ccr[0], ccr[1]);
        nCci[p] = pk2(-cci[0], -cci[1]);
        s_r[p] = 0ull; s_i[p] = 0ull;
    }
    const float dsk = D_skip[d];
    const float mult  = 1.0f + g_film[b * 2 * DM + d];
    const float shift = g_film[b * 2 * DM + DM + d];

    __shared__ float sx[2][64][8];
    const float* xbase = g_xn + (size_t)b * LSEQ * DM + (size_t)c * TCH * DM + d0;
    float* ybase = g_yp + (size_t)b * LSEQ * DM + (size_t)c * TCH * DM + d;

    const int ll = t >> 1, half = t & 1;
    *(float4*)&sx[0][ll][half * 4] =
        *(const float4*)(xbase + (size_t)ll * DM + half * 4);
    __syncthreads();

    for (int ch = 0; ch < TCH / 64; ch++) {
        const int cur = ch & 1;
        float4 nld;
        const bool more = (ch + 1 < TCH / 64);
        if (more) {
            nld = *(const float4*)(xbase + (size_t)((ch + 1) * 64 + ll) * DM + half * 4);
        }
        #pragma unroll 4
        for (int i = 0; i < 64; i++) {
            float xv = sx[cur][i][grp];
            ull x2 = pk2(xv, xv);
            ull acc = 0ull;
            #pragma unroll
            for (int p = 0; p < 2; p++) {
                ull t1 = fma2(nAbi[p], s_i[p], x2);
                ull nr = fma2(Abr[p], s_r[p], t1);
                ull u  = mul2(Abi[p], s_r[p]);
                ull ni = fma2(Abr[p], s_i[p], u);
                s_r[p] = nr; s_i[p] = ni;
                acc = fma2(Ccr[p], nr, acc);
                acc = fma2(nCci[p], ni, acc);
            }
            float2 ac = upk2(acc);
            float tsum = ac.x + ac.y;
            #pragma unroll
            for (int o = 8; o; o >>= 1)
                tsum += __shfl_xor_sync(0xffffffffu, tsum, o);
            if (g == 0) {
                float o = dt * tsum + dsk * xv;
                ybase[(size_t)(ch * 64 + i) * DM] = o * mult + shift;
            }
        }
        if (more) {
            *(float4*)&sx[cur ^ 1][ll][half * 4] = nld;
        }
        __syncthreads();
    }

    // dump end states
    size_t sb = ((size_t)(b * CHK + c) * DM + d) * 32 + g * 2;
    g_str[sb + 0] = s_r[0];
    g_str[sb + 1] = s_r[1];
    g_sti[sb + 0] = s_i[0];
    g_sti[sb + 1] = s_i[1];
}

// ---------------------------------------------------------------------------
// Kernel 3b: fixup. For chunk c>0: s_in = sum_{c'<c} lam^{(c-1-c')T} s_loc(c'),
// w = Cc*s_in*dt*mult, then w <- lam*w each step; v += Re(sum w).
// Emits bf16 hi/lo splits. Chunk 0 just converts.
// ---------------------------------------------------------------------------
__global__ void scan_fixup(const float* __restrict__ A_real,
                           const float* __restrict__ A_imag,
                           const float* __restrict__ Cp,
                           const float* __restrict__ log_dt,
                           const float* __restrict__ B_ssm) {
    const int t = threadIdx.x;
    const int grp = t >> 4;
    const int g = t & 15;
    const int blk = blockIdx.x;
    const int c = blk & 7;
    const int rest = blk >> 3;
    const int gid = rest * 8 + grp;
    const int b = gid >> 9;
    const int d = gid & 511;
    const int d0 = (rest * 8) & 511;

    if (c == 0) {
        // pure conversion for chunk 0
        const float* yp = g_yp + (size_t)b * LSEQ * DM + d0;
        __nv_bfloat16* yh = g_y2h + (size_t)b * LSEQ * DM + d0;
        __nv_bfloat16* yl = g_y2l + (size_t)b * LSEQ * DM + d0;
        for (int idx = t; idx < TCH * 8; idx += 128) {
            int i = idx >> 3, dd = idx & 7;
            size_t off = (size_t)i * DM + dd;
            float v = yp[off];
            __nv_bfloat16 h = __float2bfloat16_rn(v);
            __nv_bfloat16 l = __float2bfloat16_rn(v - __bfloat162float(h));
            yh[off] = h;
            yl[off] = l;
        }
        return;
    }

    const float dt = expf(log_dt[d]);
    const float k = dt * (1.0f + g_film[b * 2 * DM + d]);

    ull Lr[2], Li[2], nLi[2], LTr[2], LTi[2], nLTi[2], Ccr[2], Cci[2], nCci[2];
    #pragma unroll
    for (int p = 0; p < 2; p++) {
        float lr[2], li[2], ltr[2], lti[2], ccr[2], cci[2];
        #pragma unroll
        for (int j = 0; j < 2; j++) {
            int n = g * 4 + p * 2 + j;
            float ar = dt * A_real[d * NS + n];
            float ai = dt * A_imag[d * NS + n];
            float er = expf(ar), sb, cb;
            sincosf(ai, &sb, &cb);
            lr[j] = er * cb;
            li[j] = er * sb;
            // lam^TCH via 8 squarings (TCH = 256 = 2^8)
            float pr = lr[j], pi = li[j];
            #pragma unroll
            for (int q = 0; q < 8; q++) {
                float nr2 = pr * pr - pi * pi;
                pi = 2.0f * pr * pi;
                pr = nr2;
            }
            ltr[j] = pr; lti[j] = pi;
            float bs = B_ssm[d * NS + n];
            ccr[j] = Cp[(d * NS + n) * 2 + 0] * bs * k;
            cci[j] = Cp[(d * NS + n) * 2 + 1] * bs * k;
        }
        Lr[p]   = pk2(lr[0], lr[1]);
        Li[p]   = pk2(li[0], li[1]);
        nLi[p]  = pk2(-li[0], -li[1]);
        LTr[p]  = pk2(ltr[0], ltr[1]);
        LTi[p]  = pk2(lti[0], lti[1]);
        nLTi[p] = pk2(-lti[0], -lti[1]);
        Ccr[p]  = pk2(ccr[0], ccr[1]);
        Cci[p]  = pk2(cci[0], cci[1]);
        nCci[p] = pk2(-cci[0], -cci[1]);
    }

    // combine local end-states: ascending Horner  acc = lamT*acc + s_loc[c']
    ull ar_[2] = {0ull, 0ull}, ai_[2] = {0ull, 0ull};
    size_t sb0 = ((size_t)(b * CHK) * DM + d) * 32 + g * 2;
    for (int cp = 0; cp < c; cp++) {
        size_t sb = sb0 + (size_t)cp * DM * 32;
        #pragma unroll
        for (int p = 0; p < 2; p++) {
            ull sr = g_str[sb + p];
            ull si = g_sti[sb + p];
            ull t1 = fma2(nLTi[p], ai_[p], sr);
            ull nr = fma2(LTr[p], ar_[p], t1);
            ull t2 = fma2(LTi[p], ar_[p], si);
            ull ni = fma2(LTr[p], ai_[p], t2);
            ar_[p] = nr; ai_[p] = ni;
        }
    }

    // w = Cc (pre-scaled by k) * s_in
    ull Wr[2], Wi[2];
    #pragma unroll
    for (int p = 0; p < 2; p++) {
        Wr[p] = fma2(Ccr[p], ar_[p], mul2(nCci[p], ai_[p]));
        Wi[p] = fma2(Ccr[p], ai_[p], mul2(Cci[p], ar_[p]));
    }

    const float* ypb = g_yp + (size_t)b * LSEQ * DM + (size_t)c * TCH * DM + d;
    __nv_bfloat16* yh = g_y2h + (size_t)b * LSEQ * DM + (size_t)c * TCH * DM + d;
    __nv_bfloat16* yl = g_y2l + (size_t)b * LSEQ * DM + (size_t)c * TCH * DM + d;

    #pragma unroll 4
    for (int i = 0; i < TCH; i++) {
        #pragma unroll
        for (int p = 0; p < 2; p++) {
            ull t1 = mul2(nLi[p], Wi[p]);
            ull nr = fma2(Lr[p], Wr[p], t1);
            ull t2 = mul2(Li[p], Wr[p]);
            ull ni = fma2(Lr[p], Wi[p], t2);
            Wr[p] = nr; Wi[p] = ni;
        }
        ull acc = add2(Wr[0], Wr[1]);
        float2 a2 = upk2(acc);
        float tsum = a2.x + a2.y;
        #pragma unroll
        for (int o = 8; o; o >>= 1)
            tsum += __shfl_xor_sync(0xffffffffu, tsum, o);
        if (g == 0) {
            float v = ypb[(size_t)i * DM] + tsum;
            __nv_bfloat16 h = __float2bfloat16_rn(v);
            __nv_bfloat16 l = __float2bfloat16_rn(v - __bfloat162float(h));
            yh[(size_t)i * DM] = h;
            yl[(size_t)i * DM] = l;
        }
    }
}

// ---------------------------------------------------------------------------
// Kernel 4: out_proj GEMM via 3-pass bf16 split mma.m16n8k16 + GLU + residual.
// ---------------------------------------------------------------------------
#define TBM 128
#define TBK 32
#define ROWW 20
#define TILEW (128 * ROWW)

#define OFF_AH(st) ((st) * TILEW)
#define OFF_AL(st) (2 * TILEW + (st) * TILEW)
#define OFF_BH(st) (4 * TILEW + (st) * TILEW)
#define OFF_BL(st) (6 * TILEW + (st) * TILEW)
#define SMEM_BYTES (8 * TILEW * 4)

__device__ __forceinline__ void mma_bf16(float d[4], const uint32_t a[4],
                                         const uint32_t b0, const uint32_t b1) {
    asm volatile(
        "mma.sync.aligned.m16n8k16.row.col.f32.bf16.bf16.f32 "
        "{%0,%1,%2,%3}, {%4,%5,%6,%7}, {%8,%9}, {%0,%1,%2,%3};\n"
        : "+f"(d[0]), "+f"(d[1]), "+f"(d[2]), "+f"(d[3])
        : "r"(a[0]), "r"(a[1]), "r"(a[2]), "r"(a[3]), "r"(b0), "r"(b1));
}

__global__ void __launch_bounds__(256, 2)
gemm_glu_tc(const float* __restrict__ bo,
            const float* __restrict__ resid,
            float* __restrict__ out) {
    extern __shared__ uint32_t sm[];
    const uint32_t sbase = (uint32_t)__cvta_generic_to_shared(sm);

    const int tid = threadIdx.x;
    const int m0 = blockIdx.x * TBM;
    const int c0 = blockIdx.y * 64;
    const int warp = tid >> 5, lane = tid & 31;
    const int wm = warp & 3, wn = warp >> 2;
    const int grp = lane >> 2, tig = lane & 3;

    float da[2][4][4];
    float dg[2][4][4];
    #pragma unroll
    for (int mt = 0; mt < 2; mt++)
        #pragma unroll
        for (int nt = 0; nt < 4; nt++)
            #pragma unroll
            for (int r = 0; r < 4; r++) { da[mt][nt][r] = 0.0f; dg[mt][nt][r] = 0.0f; }

    const int r0 = tid >> 2,         ch0 = tid & 3;
    const int r1 = (tid + 256) >> 2, ch1 = tid & 3;
    const int wrow0 = (r0 < 64) ? (c0 + r0) : (DM + c0 + r0 - 64);
    const int wrow1 = (r1 < 64) ? (c0 + r1) : (DM + c0 + r1 - 64);

    auto load_stage = [&](int st, int kt) {
        const __nv_bfloat16* a_h = g_y2h + (size_t)(m0 + r0) * DM + kt + ch0 * 8;
        const __nv_bfloat16* a_h1 = g_y2h + (size_t)(m0 + r1) * DM + kt + ch1 * 8;
        const __nv_bfloat16* a_l = g_y2l + (size_t)(m0 + r0) * DM + kt + ch0 * 8;
        const __nv_bfloat16* a_l1 = g_y2l + (size_t)(m0 + r1) * DM + kt + ch1 * 8;
        const __nv_bfloat16* b_h = g_Wh + (size_t)wrow0 * DM + kt + ch0 * 8;
        const __nv_bfloat16* b_h1 = g_Wh + (size_t)wrow1 * DM + kt + ch1 * 8;
        const __nv_bfloat16* b_l = g_Wl + (size_t)wrow0 * DM + kt + ch0 * 8;
        const __nv_bfloat16* b_l1 = g_Wl + (size_t)wrow1 * DM + kt + ch1 * 8;
        uint32_t d0 = (r0 * ROWW + ch0 * 4) * 4;
        uint32_t d1 = (r1 * ROWW + ch1 * 4) * 4;
        cpa16(sbase + OFF_AH(st) * 4 + d0, a_h);
        cpa16(sbase + OFF_AH(st) * 4 + d1, a_h1);
        cpa16(sbase + OFF_AL(st) * 4 + d0, a_l);
        cpa16(sbase + OFF_AL(st) * 4 + d1, a_l1);
        cpa16(sbase + OFF_BH(st) * 4 + d0, b_h);
        cpa16(sbase + OFF_BH(st) * 4 + d1, b_h1);
        cpa16(sbase + OFF_BL(st) * 4 + d0, b_l);
        cpa16(sbase + OFF_BL(st) * 4 + d1, b_l1);
    };

    load_stage(0, 0);
    asm volatile("cp.async.commit_group;");

    const int NKT = DM / TBK;
    for (int it = 0; it < NKT; it++) {
        const int cur = it & 1;
        if (it + 1 < NKT) {
            load_stage(cur ^ 1, (it + 1) * TBK);
            asm volatile("cp.async.commit_group;");
            asm volatile("cp.async.wait_group 1;");
        } else {
            asm volatile("cp.async.wait_group 0;");
        }
        __syncthreads();

        const uint32_t* Ah = sm + OFF_AH(cur);
        const uint32_t* Al = sm + OFF_AL(cur);
        const uint32_t* Bh = sm + OFF_BH(cur);
        const uint32_t* Bl = sm + OFF_BL(cur);

        #pragma unroll
        for (int kk = 0; kk < 2; kk++) {
            const int kw = kk * 8;
            uint32_t ah[2][4], al[2][4];
            #pragma unroll
            for (int mt = 0; mt < 2; mt++) {
                int m = wm * 32 + mt * 16;
                int i0 = (m + grp) * ROWW + kw + tig;
                int i1 = (m + grp + 8) * ROWW + kw + tig;
                ah[mt][0] = Ah[i0];     ah[mt][1] = Ah[i1];
                ah[mt][2] = Ah[i0 + 4]; ah[mt][3] = Ah[i1 + 4];
                al[mt][0] = Al[i0];     al[mt][1] = Al[i1];
                al[mt][2] = Al[i0 + 4]; al[mt][3] = Al[i1 + 4];
            }
            {
                uint32_t bh[4][2], bl[4][2];
                #pragma unroll
                for (int nt = 0; nt < 4; nt++) {
                    int n = wn * 32 + nt * 8 + grp;
                    int ib = n * ROWW + kw + tig;
                    bh[nt][0] = Bh[ib]; bh[nt][1] = Bh[ib + 4];
                    bl[nt][0] = Bl[ib]; bl[nt][1] = Bl[ib + 4];
                }
                #pragma unroll
                for (int mt = 0; mt < 2; mt++)
                    #pragma unroll
                    for (int nt = 0; nt < 4; nt++) {
                        mma_bf16(da[mt][nt], ah[mt], bh[nt][0], bh[nt][1]);
                        mma_bf16(da[mt][nt], ah[mt], bl[nt][0], bl[nt][1]);
                        mma_bf16(da[mt][nt], al[mt], bh[nt][0], bh[nt][1]);
                    }
            }
            {
                uint32_t bh[4][2], bl[4][2];
                #pragma unroll
                for (int nt = 0; nt < 4; nt++) {
                    int n = 64 + wn * 32 + nt * 8 + grp;
                    int ib = n * ROWW + kw + tig;
                    bh[nt][0] = Bh[ib]; bh[nt][1] = Bh[ib + 4];
                    bl[nt][0] = Bl[ib]; bl[nt][1] = Bl[ib + 4];
                }
                #pragma unroll
                for (int mt = 0; mt < 2; mt++)
                    #pragma unroll
                    for (int nt = 0; nt < 4; nt++) {
                        mma_bf16(dg[mt][nt], ah[mt], bh[nt][0], bh[nt][1]);
                        mma_bf16(dg[mt][nt], ah[mt], bl[nt][0], bl[nt][1]);
                        mma_bf16(dg[mt][nt], al[mt], bh[nt][0], bh[nt][1]);
                    }
            }
        }
        __syncthreads();
    }

    #pragma unroll
    for (int mt = 0; mt < 2; mt++) {
        #pragma unroll
        for (int nt = 0; nt < 4; nt++) {
            int col = c0 + wn * 32 + nt * 8 + tig * 2;
            float ba0 = bo[col], ba1 = bo[col + 1];
            float bg0 = bo[DM + col], bg1 = bo[DM + col + 1];
            #pragma unroll
            for (int half = 0; half < 2; half++) {
                int r = m0 + wm * 32 + mt * 16 + grp + half * 8;
                float a0 = da[mt][nt][half * 2 + 0] + ba0;
                float a1 = da[mt][nt][half * 2 + 1] + ba1;
                float g0 = dg[mt][nt][half * 2 + 0] + bg0;
                float g1 = dg[mt][nt][half * 2 + 1] + bg1;
                float2 res = *(const float2*)(resid + (size_t)r * DM + col);
                float2 o;
                o.x = res.x + a0 * (1.0f / (1.0f + expf(-g0)));
                o.y = res.y + a1 * (1.0f / (1.0f + expf(-g1)));
                *(float2*)(out + (size_t)r * DM + col) = o;
            }
        }
    }
}

// ---------------------------------------------------------------------------
extern "C" void kernel_launch(void* const* d_in, const int* in_sizes, int n_in,
                              void* d_out, int out_size) {
    const float* x      = (const float*)d_in[0];
    const float* emb    = (const float*)d_in[1];
    const float* A_real = (const float*)d_in[2];
    const float* A_imag = (const float*)d_in[3];
    const float* C      = (const float*)d_in[4];
    const float* log_dt = (const float*)d_in[5];
    const float* B_ssm  = (const float*)d_in[6];
    const float* D_skip = (const float*)d_in[7];
    const float* ln_g   = (const float*)d_in[8];
    const float* ln_b   = (const float*)d_in[9];
    const float* W_out  = (const float*)d_in[10];
    const float* b_out  = (const float*)d_in[11];
    const float* W_film = (const float*)d_in[12];
    const float* b_film = (const float*)d_in[13];
    float* out = (float*)d_out;

    static bool configured = false;
    if (!configured) {
        cudaFuncSetAttribute(gemm_glu_tc,
                             cudaFuncAttributeMaxDynamicSharedMemorySize,
                             SMEM_BYTES);
        configured = true;
    }

    ln_kernel<<<BSZ * LSEQ, 128>>>(x, ln_g, ln_b);
    film_kernel<<<BSZ, 256>>>(emb, W_film, b_film);
    prep_w<<<(2 * DM * DM / 4) / 256, 256>>>(W_out);
    scan_local<<<BSZ * (DM / 8) * CHK, 128>>>(A_real, A_imag, C, log_dt, B_ssm, D_skip);
    scan_fixup<<<BSZ * (DM / 8) * CHK, 128>>>(A_real, A_imag, C, log_dt, B_ssm);
    gemm_glu_tc<<<dim3((BSZ * LSEQ) / TBM, DM / 64), 256, SMEM_BYTES>>>(b_out, x, out);
}

// round 5
// speedup vs baseline: 1.2912x; 1.2912x over previous
#include <cuda_runtime.h>
#include <cuda_bf16.h>
#include <math.h>
#include <stdint.h>

#define BSZ 8
#define LSEQ 2048
#define DM 512
#define NS 64
#define EMB 512
#define CHK 8
#define TCH 256   // LSEQ / CHK

typedef unsigned long long ull;

// Scratch (allocation-free rule: __device__ globals)
__device__ float g_xn[BSZ * LSEQ * DM];            // LayerNorm output
__device__ float g_yp[BSZ * LSEQ * DM];            // partial y (pre-fixup), f32
__device__ __nv_bfloat16 g_y2h[BSZ * LSEQ * DM];   // y2 hi split
__device__ __nv_bfloat16 g_y2l[BSZ * LSEQ * DM];   // y2 lo split
__device__ __nv_bfloat16 g_Wh[2 * DM * DM];        // W hi split
__device__ __nv_bfloat16 g_Wl[2 * DM * DM];        // W lo split
__device__ float g_film[BSZ * 2 * DM];
__device__ ull g_str[BSZ * CHK * DM * 32];         // local end-state (real, f32x2 pairs)
__device__ ull g_sti[BSZ * CHK * DM * 32];         // local end-state (imag)

// ---------------------------------------------------------------------------
// f32x2 packed-math helpers
// ---------------------------------------------------------------------------
__device__ __forceinline__ ull pk2(float a, float b) {
    ull r;
    asm("mov.b64 %0, {%1, %2};" : "=l"(r) : "f"(a), "f"(b));
    return r;
}
__device__ __forceinline__ float2 upk2(ull v) {
    float2 f;
    asm("mov.b64 {%0, %1}, %2;" : "=f"(f.x), "=f"(f.y) : "l"(v));
    return f;
}
__device__ __forceinline__ ull fma2(ull a, ull b, ull c) {
    ull d;
    asm("fma.rn.f32x2 %0, %1, %2, %3;" : "=l"(d) : "l"(a), "l"(b), "l"(c));
    return d;
}
__device__ __forceinline__ ull mul2(ull a, ull b) {
    ull d;
    asm("mul.rn.f32x2 %0, %1, %2;" : "=l"(d) : "l"(a), "l"(b));
    return d;
}
__device__ __forceinline__ ull add2(ull a, ull b) {
    ull d;
    asm("add.rn.f32x2 %0, %1, %2;" : "=l"(d) : "l"(a), "l"(b));
    return d;
}

__device__ __forceinline__ void cpa16(uint32_t dst, const void* src) {
    asm volatile("cp.async.cg.shared.global [%0], [%1], 16;" :: "r"(dst), "l"(src));
}

// pack 4 floats into bf16 hi / lo splits (uint2 each)
__device__ __forceinline__ void pack_hl(float4 v, uint2& H, uint2& L) {
    unsigned short h[4], l[4];
    float e[4] = {v.x, v.y, v.z, v.w};
    #pragma unroll
    for (int j = 0; j < 4; j++) {
        __nv_bfloat16 hb = __float2bfloat16_rn(e[j]);
        float r = e[j] - __bfloat162float(hb);
        h[j] = __bfloat16_as_ushort(hb);
        l[j] = __bfloat16_as_ushort(__float2bfloat16_rn(r));
    }
    H.x = (uint32_t)h[0] | ((uint32_t)h[1] << 16);
    H.y = (uint32_t)h[2] | ((uint32_t)h[3] << 16);
    L.x = (uint32_t)l[0] | ((uint32_t)l[1] << 16);
    L.y = (uint32_t)l[2] | ((uint32_t)l[3] << 16);
}

// ---------------------------------------------------------------------------
// Kernel 1: LayerNorm
// ---------------------------------------------------------------------------
__global__ void ln_kernel(const float* __restrict__ x,
                          const float* __restrict__ gamma,
                          const float* __restrict__ beta) {
    const int row = blockIdx.x;
    const int t = threadIdx.x;
    const float4* xr = (const float4*)(x + (size_t)row * DM);
    float4 v = xr[t];
    float s  = v.x + v.y + v.z + v.w;
    float ss = v.x * v.x + v.y * v.y + v.z * v.z + v.w * v.w;

    __shared__ float sh[8];
    #pragma unroll
    for (int o = 16; o; o >>= 1) {
        s  += __shfl_xor_sync(0xffffffffu, s, o);
        ss += __shfl_xor_sync(0xffffffffu, ss, o);
    }
    int w = t >> 5;
    if ((t & 31) == 0) { sh[w] = s; sh[4 + w] = ss; }
    __syncthreads();
    float S  = sh[0] + sh[1] + sh[2] + sh[3];
    float SS = sh[4] + sh[5] + sh[6] + sh[7];

    const float inv = 1.0f / (float)DM;
    float mu = S * inv;
    float var = SS * inv - mu * mu;
    float rs = rsqrtf(var + 1e-5f);

    float4 g4 = ((const float4*)gamma)[t];
    float4 b4 = ((const float4*)beta)[t];
    float4 o4;
    o4.x = (v.x - mu) * rs * g4.x + b4.x;
    o4.y = (v.y - mu) * rs * g4.y + b4.y;
    o4.z = (v.z - mu) * rs * g4.z + b4.z;
    o4.w = (v.w - mu) * rs * g4.w + b4.w;
    ((float4*)(g_xn + (size_t)row * DM))[t] = o4;
}

// ---------------------------------------------------------------------------
// Kernel 2: FiLM params
// ---------------------------------------------------------------------------
__global__ void film_kernel(const float* __restrict__ emb,
                            const float* __restrict__ Wf,
                            const float* __restrict__ bf) {
    __shared__ float se[EMB];
    const int b = blockIdx.x;
    for (int i = threadIdx.x; i < EMB; i += blockDim.x) {
        float e = emb[b * EMB + i];
        se[i] = e / (1.0f + expf(-e));
    }
    __syncthreads();
    for (int j = threadIdx.x; j < 2 * DM; j += blockDim.x) {
        const float4* wr = (const float4*)(Wf + (size_t)j * EMB);
        const float4* sr = (const float4*)se;
        float acc = bf[j];
        #pragma unroll 4
        for (int q = 0; q < EMB / 4; q++) {
            float4 w = wr[q], sv = sr[q];
            acc += w.x * sv.x + w.y * sv.y + w.z * sv.z + w.w * sv.w;
        }
        g_film[b * 2 * DM + j] = acc;
    }
}

// ---------------------------------------------------------------------------
// Kernel 2b: split W into bf16 hi/lo
// ---------------------------------------------------------------------------
__global__ void prep_w(const float* __restrict__ W) {
    int i = blockIdx.x * blockDim.x + threadIdx.x;
    float4 v = ((const float4*)W)[i];
    float e[4] = {v.x, v.y, v.z, v.w};
    ushort4 h4, l4;
    unsigned short* hp = &h4.x;
    unsigned short* lp = &l4.x;
    #pragma unroll
    for (int j = 0; j < 4; j++) {
        __nv_bfloat16 h = __float2bfloat16_rn(e[j]);
        __nv_bfloat16 l = __float2bfloat16_rn(e[j] - __bfloat162float(h));
        hp[j] = __bfloat16_as_ushort(h);
        lp[j] = __bfloat16_as_ushort(l);
    }
    ((ushort4*)g_Wh)[i] = h4;
    ((ushort4*)g_Wl)[i] = l4;
}

// ---------------------------------------------------------------------------
// Kernel 3a: local S4D scan over one chunk (zero initial state).
// 16 lanes per d, 2 f32x2 complex pairs per lane. Block = 8 d of one (b,c).
// Outputs staged in SMEM, stored as vectors. Chunk 0 emits bf16 h/l directly;
// chunks >0 emit f32 partials for fixup.
// ---------------------------------------------------------------------------
__global__ void scan_local(const float* __restrict__ A_real,
                           const float* __restrict__ A_imag,
                           const float* __restrict__ Cp,
                           const float* __restrict__ log_dt,
                           const float* __restrict__ B_ssm,
                           const float* __restrict__ D_skip) {
    const int t = threadIdx.x;
    const int grp = t >> 4;           // 0..7
    const int g = t & 15;
    const int blk = blockIdx.x;
    const int c = blk & 7;
    const int rest = blk >> 3;        // 0..511
    const int gid = rest * 8 + grp;
    const int b = gid >> 9;
    const int d = gid & 511;
    const int d0 = (rest * 8) & 511;

    const float dt = expf(log_dt[d]);
    ull Abr[2], Abi[2], nAbi[2], Ccr[2], nCci[2], s_r[2], s_i[2];
    #pragma unroll
    for (int p = 0; p < 2; p++) {
        float abr[2], abi[2], ccr[2], cci[2];
        #pragma unroll
        for (int j = 0; j < 2; j++) {
            int n = g * 4 + p * 2 + j;
            float ar = dt * A_real[d * NS + n];
            float ai = dt * A_imag[d * NS + n];
            float er = expf(ar), sb, cb;
            sincosf(ai, &sb, &cb);
            abr[j] = er * cb;
            abi[j] = er * sb;
            float bs = B_ssm[d * NS + n];
            ccr[j] = Cp[(d * NS + n) * 2 + 0] * bs;
            cci[j] = Cp[(d * NS + n) * 2 + 1] * bs;
        }
        Abr[p]  = pk2(abr[0], abr[1]);
        Abi[p]  = pk2(abi[0], abi[1]);
        nAbi[p] = pk2(-abi[0], -abi[1]);
        Ccr[p]  = pk2(ccr[0], ccr[1]);
        nCci[p] = pk2(-cci[0], -cci[1]);
        s_r[p] = 0ull; s_i[p] = 0ull;
    }
    const float dsk = D_skip[d];
    const float mult  = 1.0f + g_film[b * 2 * DM + d];
    const float shift = g_film[b * 2 * DM + DM + d];

    __shared__ float sx[2][64][8];
    __shared__ float syb[2][64][8];
    const size_t cbase = (size_t)b * LSEQ * DM + (size_t)c * TCH * DM;
    const float* xbase = g_xn + cbase + d0;
    float* ypb = g_yp + cbase + d0;
    __nv_bfloat16* yhb = g_y2h + cbase + d0;
    __nv_bfloat16* ylb = g_y2l + cbase + d0;

    const int ll = t >> 1, half = t & 1;
    *(float4*)&sx[0][ll][half * 4] =
        *(const float4*)(xbase + (size_t)ll * DM + half * 4);
    __syncthreads();

    for (int ch = 0; ch < TCH / 64; ch++) {
        const int cur = ch & 1;
        float4 nld;
        const bool more = (ch + 1 < TCH / 64);
        if (more) {
            nld = *(const float4*)(xbase + (size_t)((ch + 1) * 64 + ll) * DM + half * 4);
        }
        #pragma unroll 4
        for (int i = 0; i < 64; i++) {
            float xv = sx[cur][i][grp];
            ull x2 = pk2(xv, xv);
            ull acc = 0ull;
            #pragma unroll
            for (int p = 0; p < 2; p++) {
                ull t1 = fma2(nAbi[p], s_i[p], x2);
                ull nr = fma2(Abr[p], s_r[p], t1);
                ull u  = mul2(Abi[p], s_r[p]);
                ull ni = fma2(Abr[p], s_i[p], u);
                s_r[p] = nr; s_i[p] = ni;
                acc = fma2(Ccr[p], nr, acc);
                acc = fma2(nCci[p], ni, acc);
            }
            float2 ac = upk2(acc);
            float tsum = ac.x + ac.y;
            #pragma unroll
            for (int o = 8; o; o >>= 1)
                tsum += __shfl_xor_sync(0xffffffffu, tsum, o);
            if (g == 0) {
                float o = dt * tsum + dsk * xv;
                syb[cur][i][grp] = o * mult + shift;
            }
        }
        if (more) {
            *(float4*)&sx[cur ^ 1][ll][half * 4] = nld;
        }
        __syncthreads();
        // vectorized store stage: 2 threads per l-row
        {
            const int r = t >> 1, hh = t & 1;
            float4 v = *(float4*)&syb[cur][r][hh * 4];
            size_t lrow = (size_t)(ch * 64 + r) * DM + hh * 4;
            if (c == 0) {
                uint2 H, L;
                pack_hl(v, H, L);
                *(uint2*)(yhb + lrow) = H;
                *(uint2*)(ylb + lrow) = L;
            } else {
                *(float4*)(ypb + lrow) = v;
            }
        }
    }

    // dump end states
    size_t sb = ((size_t)(b * CHK + c) * DM + d) * 32 + g * 2;
    g_str[sb + 0] = s_r[0];
    g_str[sb + 1] = s_r[1];
    g_sti[sb + 0] = s_i[0];
    g_sti[sb + 1] = s_i[1];
}

// ---------------------------------------------------------------------------
// Kernel 3b: fixup for chunks c=1..7. s_in = Horner over previous end states;
// w = Cc*s_in*dt*mult evolves by lam; v += Re(sum w). SMEM-staged vector I/O.
// ---------------------------------------------------------------------------
__global__ void scan_fixup(const float* __restrict__ A_real,
                           const float* __restrict__ A_imag,
                           const float* __restrict__ Cp,
                           const float* __restrict__ log_dt,
                           const float* __restrict__ B_ssm) {
    const int t = threadIdx.x;
    const int grp = t >> 4;
    const int g = t & 15;
    const int blk = blockIdx.x;
    const int c = 1 + blk % 7;
    const int rest = blk / 7;         // 0..511
    const int gid = rest * 8 + grp;
    const int b = gid >> 9;
    const int d = gid & 511;
    const int d0 = (rest * 8) & 511;

    const float dt = expf(log_dt[d]);
    const float k = dt * (1.0f + g_film[b * 2 * DM + d]);

    ull Lr[2], Li[2], nLi[2], LTr[2], LTi[2], nLTi[2], Ccr[2], Cci[2], nCci[2];
    #pragma unroll
    for (int p = 0; p < 2; p++) {
        float lr[2], li[2], ltr[2], lti[2], ccr[2], cci[2];
        #pragma unroll
        for (int j = 0; j < 2; j++) {
            int n = g * 4 + p * 2 + j;
            float ar = dt * A_real[d * NS + n];
            float ai = dt * A_imag[d * NS + n];
            float er = expf(ar), sb, cb;
            sincosf(ai, &sb, &cb);
            lr[j] = er * cb;
            li[j] = er * sb;
            float pr = lr[j], pi = li[j];
            #pragma unroll
            for (int q = 0; q < 8; q++) {       // lam^256
                float nr2 = pr * pr - pi * pi;
                pi = 2.0f * pr * pi;
                pr = nr2;
            }
            ltr[j] = pr; lti[j] = pi;
            float bs = B_ssm[d * NS + n];
            ccr[j] = Cp[(d * NS + n) * 2 + 0] * bs * k;
            cci[j] = Cp[(d * NS + n) * 2 + 1] * bs * k;
        }
        Lr[p]   = pk2(lr[0], lr[1]);
        Li[p]   = pk2(li[0], li[1]);
        nLi[p]  = pk2(-li[0], -li[1]);
        LTr[p]  = pk2(ltr[0], ltr[1]);
        LTi[p]  = pk2(lti[0], lti[1]);
        nLTi[p] = pk2(-lti[0], -lti[1]);
        Ccr[p]  = pk2(ccr[0], ccr[1]);
        Cci[p]  = pk2(cci[0], cci[1]);
        nCci[p] = pk2(-cci[0], -cci[1]);
    }

    // combine local end-states (ascending Horner)
    ull ar_[2] = {0ull, 0ull}, ai_[2] = {0ull, 0ull};
    size_t sb0 = ((size_t)(b * CHK) * DM + d) * 32 + g * 2;
    for (int cp = 0; cp < c; cp++) {
        size_t sb = sb0 + (size_t)cp * DM * 32;
        #pragma unroll
        for (int p = 0; p < 2; p++) {
            ull sr = g_str[sb + p];
            ull si = g_sti[sb + p];
            ull t1 = fma2(nLTi[p], ai_[p], sr);
            ull nr = fma2(LTr[p], ar_[p], t1);
            ull t2 = fma2(LTi[p], ar_[p], si);
            ull ni = fma2(LTr[p], ai_[p], t2);
            ar_[p] = nr; ai_[p] = ni;
        }
    }

    ull Wr[2], Wi[2];
    #pragma unroll
    for (int p = 0; p < 2; p++) {
        Wr[p] = fma2(Ccr[p], ar_[p], mul2(nCci[p], ai_[p]));
        Wi[p] = fma2(Ccr[p], ai_[p], mul2(Cci[p], ar_[p]));
    }

    __shared__ float syc[64][8];
    const size_t cbase = (size_t)b * LSEQ * DM + (size_t)c * TCH * DM;
    const float* ypb = g_yp + cbase + d0;
    __nv_bfloat16* yhb = g_y2h + cbase + d0;
    __nv_bfloat16* ylb = g_y2l + cbase + d0;

    for (int tile = 0; tile < TCH / 64; tile++) {
        #pragma unroll 4
        for (int i = 0; i < 64; i++) {
            #pragma unroll
            for (int p = 0; p < 2; p++) {
                ull t1 = mul2(nLi[p], Wi[p]);
                ull nr = fma2(Lr[p], Wr[p], t1);
                ull t2 = mul2(Li[p], Wr[p]);
                ull ni = fma2(Lr[p], Wi[p], t2);
                Wr[p] = nr; Wi[p] = ni;
            }
            ull acc = add2(Wr[0], Wr[1]);
            float2 a2 = upk2(acc);
            float tsum = a2.x + a2.y;
            #pragma unroll
            for (int o = 8; o; o >>= 1)
                tsum += __shfl_xor_sync(0xffffffffu, tsum, o);
            if (g == 0) syc[i][grp] = tsum;
        }
        __syncthreads();
        // vectorized read/modify/store
        {
            const int r = t >> 1, hh = t & 1;
            size_t lrow = (size_t)(tile * 64 + r) * DM + hh * 4;
            float4 v = *(const float4*)(ypb + lrow);
            v.x += syc[r][hh * 4 + 0];
            v.y += syc[r][hh * 4 + 1];
            v.z += syc[r][hh * 4 + 2];
            v.w += syc[r][hh * 4 + 3];
            uint2 H, L;
            pack_hl(v, H, L);
            *(uint2*)(yhb + lrow) = H;
            *(uint2*)(ylb + lrow) = L;
        }
        __syncthreads();
    }
}

// ---------------------------------------------------------------------------
// Kernel 4: out_proj GEMM via 3-pass bf16 split mma.m16n8k16 (+LDSM) + GLU +
// residual. Block tile 128m x 64 a-cols (+paired g-cols), BK=32, cp.async x2.
// ---------------------------------------------------------------------------
#define TBM 128
#define TBK 32
#define ROWW 20
#define TILEW (128 * ROWW)

#define OFF_AH(st) ((st) * TILEW)
#define OFF_AL(st) (2 * TILEW + (st) * TILEW)
#define OFF_BH(st) (4 * TILEW + (st) * TILEW)
#define OFF_BL(st) (6 * TILEW + (st) * TILEW)
#define SMEM_BYTES (8 * TILEW * 4)

__device__ __forceinline__ void mma_bf16(float d[4], const uint32_t a[4],
                                         const uint32_t b0, const uint32_t b1) {
    asm volatile(
        "mma.sync.aligned.m16n8k16.row.col.f32.bf16.bf16.f32 "
        "{%0,%1,%2,%3}, {%4,%5,%6,%7}, {%8,%9}, {%0,%1,%2,%3};\n"
        : "+f"(d[0]), "+f"(d[1]), "+f"(d[2]), "+f"(d[3])
        : "r"(a[0]), "r"(a[1]), "r"(a[2]), "r"(a[3]), "r"(b0), "r"(b1));
}

__device__ __forceinline__ void ldsm4(uint32_t* r, uint32_t byteaddr) {
    asm volatile("ldmatrix.sync.aligned.m8n8.x4.shared.b16 {%0,%1,%2,%3}, [%4];"
        : "=r"(r[0]), "=r"(r[1]), "=r"(r[2]), "=r"(r[3]) : "r"(byteaddr));
}

__global__ void __launch_bounds__(256, 2)
gemm_glu_tc(const float* __restrict__ bo,
            const float* __restrict__ resid,
            float* __restrict__ out) {
    extern __shared__ uint32_t sm[];
    const uint32_t sbase = (uint32_t)__cvta_generic_to_shared(sm);

    const int tid = threadIdx.x;
    const int m0 = blockIdx.x * TBM;
    const int c0 = blockIdx.y * 64;
    const int warp = tid >> 5, lane = tid & 31;
    const int wm = warp & 3, wn = warp >> 2;
    const int grp = lane >> 2, tig = lane & 3;

    // LDSM per-lane word offsets
    // A: mats = {rows m..m+7 k0, m+8..15 k0, m..7 k8, m+8..15 k8}
    const int aw = (wm * 32 + (lane & 15)) * ROWW + ((lane & 16) >> 2);
    // B: mats = {rows n..n+7 k0, same k8, n+8..15 k0, n+8..15 k8}
    const int bw = ((((lane & 16) >> 1) + (lane & 7))) * ROWW + ((lane & 8) >> 1);

    float da[2][4][4];
    float dg[2][4][4];
    #pragma unroll
    for (int mt = 0; mt < 2; mt++)
        #pragma unroll
        for (int nt = 0; nt < 4; nt++)
            #pragma unroll
            for (int r = 0; r < 4; r++) { da[mt][nt][r] = 0.0f; dg[mt][nt][r] = 0.0f; }

    const int r0 = tid >> 2,         ch0 = tid & 3;
    const int r1 = (tid + 256) >> 2, ch1 = tid & 3;
    const int wrow0 = (r0 < 64) ? (c0 + r0) : (DM + c0 + r0 - 64);
    const int wrow1 = (r1 < 64) ? (c0 + r1) : (DM + c0 + r1 - 64);

    auto load_stage = [&](int st, int kt) {
        const __nv_bfloat16* a_h = g_y2h + (size_t)(m0 + r0) * DM + kt + ch0 * 8;
        const __nv_bfloat16* a_h1 = g_y2h + (size_t)(m0 + r1) * DM + kt + ch1 * 8;
        const __nv_bfloat16* a_l = g_y2l + (size_t)(m0 + r0) * DM + kt + ch0 * 8;
        const __nv_bfloat16* a_l1 = g_y2l + (size_t)(m0 + r1) * DM + kt + ch1 * 8;
        const __nv_bfloat16* b_h = g_Wh + (size_t)wrow0 * DM + kt + ch0 * 8;
        const __nv_bfloat16* b_h1 = g_Wh + (size_t)wrow1 * DM + kt + ch1 * 8;
        const __nv_bfloat16* b_l = g_Wl + (size_t)wrow0 * DM + kt + ch0 * 8;
        const __nv_bfloat16* b_l1 = g_Wl + (size_t)wrow1 * DM + kt + ch1 * 8;
        uint32_t d0 = (r0 * ROWW + ch0 * 4) * 4;
        uint32_t d1 = (r1 * ROWW + ch1 * 4) * 4;
        cpa16(sbase + OFF_AH(st) * 4 + d0, a_h);
        cpa16(sbase + OFF_AH(st) * 4 + d1, a_h1);
        cpa16(sbase + OFF_AL(st) * 4 + d0, a_l);
        cpa16(sbase + OFF_AL(st) * 4 + d1, a_l1);
        cpa16(sbase + OFF_BH(st) * 4 + d0, b_h);
        cpa16(sbase + OFF_BH(st) * 4 + d1, b_h1);
        cpa16(sbase + OFF_BL(st) * 4 + d0, b_l);
        cpa16(sbase + OFF_BL(st) * 4 + d1, b_l1);
    };

    load_stage(0, 0);
    asm volatile("cp.async.commit_group;");

    const int NKT = DM / TBK;
    for (int it = 0; it < NKT; it++) {
        const int cur = it & 1;
        if (it + 1 < NKT) {
            load_stage(cur ^ 1, (it + 1) * TBK);
            asm volatile("cp.async.commit_group;");
            asm volatile("cp.async.wait_group 1;");
        } else {
            asm volatile("cp.async.wait_group 0;");
        }
        __syncthreads();

        const uint32_t bAH = sbase + OFF_AH(cur) * 4;
        const uint32_t bAL = sbase + OFF_AL(cur) * 4;
        const uint32_t bBH = sbase + OFF_BH(cur) * 4;
        const uint32_t bBL = sbase + OFF_BL(cur) * 4;

        #pragma unroll
        for (int kk = 0; kk < 2; kk++) {
            const int kw = kk * 8;
            uint32_t ah[2][4], al[2][4];
            #pragma unroll
            for (int mt = 0; mt < 2; mt++) {
                ldsm4(ah[mt], bAH + (aw + mt * 16 * ROWW + kw) * 4);
                ldsm4(al[mt], bAL + (aw + mt * 16 * ROWW + kw) * 4);
            }
            // a-gate (B rows 0..63)
            {
                uint32_t bh[8], bl[8];
                ldsm4(&bh[0], bBH + ((wn * 32 + 0)  * ROWW + bw + kw) * 4);
                ldsm4(&bh[4], bBH + ((wn * 32 + 16) * ROWW + bw + kw) * 4);
                ldsm4(&bl[0], bBL + ((wn * 32 + 0)  * ROWW + bw + kw) * 4);
                ldsm4(&bl[4], bBL + ((wn * 32 + 16) * ROWW + bw + kw) * 4);
                #pragma unroll
                for (int mt = 0; mt < 2; mt++)
                    #pragma unroll
                    for (int nt = 0; nt < 4; nt++) {
                        mma_bf16(da[mt][nt], ah[mt], bh[nt * 2], bh[nt * 2 + 1]);
                        mma_bf16(da[mt][nt], ah[mt], bl[nt * 2], bl[nt * 2 + 1]);
                        mma_bf16(da[mt][nt], al[mt], bh[nt * 2], bh[nt * 2 + 1]);
                    }
            }
            // g-gate (B rows 64..127)
            {
                uint32_t bh[8], bl[8];
                ldsm4(&bh[0], bBH + ((64 + wn * 32 + 0)  * ROWW + bw + kw) * 4);
                ldsm4(&bh[4], bBH + ((64 + wn * 32 + 16) * ROWW + bw + kw) * 4);
                ldsm4(&bl[0], bBL + ((64 + wn * 32 + 0)  * ROWW + bw + kw) * 4);
                ldsm4(&bl[4], bBL + ((64 + wn * 32 + 16) * ROWW + bw + kw) * 4);
                #pragma unroll
                for (int mt = 0; mt < 2; mt++)
                    #pragma unroll
                    for (int nt = 0; nt < 4; nt++) {
                        mma_bf16(dg[mt][nt], ah[mt], bh[nt * 2], bh[nt * 2 + 1]);
                        mma_bf16(dg[mt][nt], ah[mt], bl[nt * 2], bl[nt * 2 + 1]);
                        mma_bf16(dg[mt][nt], al[mt], bh[nt * 2], bh[nt * 2 + 1]);
                    }
            }
        }
        __syncthreads();
    }

    // epilogue: a*sigmoid(g) + residual
    #pragma unroll
    for (int mt = 0; mt < 2; mt++) {
        #pragma unroll
        for (int nt = 0; nt < 4; nt++) {
            int col = c0 + wn * 32 + nt * 8 + tig * 2;
            float ba0 = bo[col], ba1 = bo[col + 1];
            float bg0 = bo[DM + col], bg1 = bo[DM + col + 1];
            #pragma unroll
            for (int half = 0; half < 2; half++) {
                int r = m0 + wm * 32 + mt * 16 + grp + half * 8;
                float a0 = da[mt][nt][half * 2 + 0] + ba0;
                float a1 = da[mt][nt][half * 2 + 1] + ba1;
                float g0 = dg[mt][nt][half * 2 + 0] + bg0;
                float g1 = dg[mt][nt][half * 2 + 1] + bg1;
                float2 res = *(const float2*)(resid + (size_t)r * DM + col);
                float2 o;
                o.x = res.x + a0 * (1.0f / (1.0f + expf(-g0)));
                o.y = res.y + a1 * (1.0f / (1.0f + expf(-g1)));
                *(float2*)(out + (size_t)r * DM + col) = o;
            }
        }
    }
}

// ---------------------------------------------------------------------------
extern "C" void kernel_launch(void* const* d_in, const int* in_sizes, int n_in,
                              void* d_out, int out_size) {
    const float* x      = (const float*)d_in[0];
    const float* emb    = (const float*)d_in[1];
    const float* A_real = (const float*)d_in[2];
    const float* A_imag = (const float*)d_in[3];
    const float* C      = (const float*)d_in[4];
    const float* log_dt = (const float*)d_in[5];
    const float* B_ssm  = (const float*)d_in[6];
    const float* D_skip = (const float*)d_in[7];
    const float* ln_g   = (const float*)d_in[8];
    const float* ln_b   = (const float*)d_in[9];
    const float* W_out  = (const float*)d_in[10];
    const float* b_out  = (const float*)d_in[11];
    const float* W_film = (const float*)d_in[12];
    const float* b_film = (const float*)d_in[13];
    float* out = (float*)d_out;

    static bool configured = false;
    if (!configured) {
        cudaFuncSetAttribute(gemm_glu_tc,
                             cudaFuncAttributeMaxDynamicSharedMemorySize,
                             SMEM_BYTES);
        configured = true;
    }

    ln_kernel<<<BSZ * LSEQ, 128>>>(x, ln_g, ln_b);
    film_kernel<<<BSZ, 256>>>(emb, W_film, b_film);
    prep_w<<<(2 * DM * DM / 4) / 256, 256>>>(W_out);
    scan_local<<<BSZ * (DM / 8) * CHK, 128>>>(A_real, A_imag, C, log_dt, B_ssm, D_skip);
    scan_fixup<<<BSZ * (DM / 8) * (CHK - 1), 128>>>(A_real, A_imag, C, log_dt, B_ssm);
    gemm_glu_tc<<<dim3((BSZ * LSEQ) / TBM, DM / 64), 256, SMEM_BYTES>>>(b_out, x, out);
}

// round 6
// speedup vs baseline: 1.3088x; 1.0136x over previous
#include <cuda_runtime.h>
#include <cuda_bf16.h>
#include <math.h>
#include <stdint.h>

#define BSZ 8
#define LSEQ 2048
#define DM 512
#define NS 64
#define EMB 512
#define CHK 8
#define TCH 256   // LSEQ / CHK

typedef unsigned long long ull;

// Scratch (allocation-free rule: __device__ globals)
// g_y2h/l and g_Wh/l are stored PRE-TILED + PRE-SWIZZLED:
//   A tiles: [m/128][k/64] tiles of 128x64 bf16, rows 128B, chunk ^= row&7
//   W tiles: [r/64][k/64]  tiles of  64x64 bf16, same swizzle
__device__ __align__(1024) float g_xn[BSZ * LSEQ * DM];
__device__ __align__(1024) float g_yp[BSZ * LSEQ * DM];
__device__ __align__(1024) __nv_bfloat16 g_y2h[BSZ * LSEQ * DM];
__device__ __align__(1024) __nv_bfloat16 g_y2l[BSZ * LSEQ * DM];
__device__ __align__(1024) __nv_bfloat16 g_Wh[2 * DM * DM];
__device__ __align__(1024) __nv_bfloat16 g_Wl[2 * DM * DM];
__device__ float g_film[BSZ * 2 * DM];
__device__ ull g_str[BSZ * CHK * DM * 32];
__device__ ull g_sti[BSZ * CHK * DM * 32];

// tiled+swizzled element offset into A-layout arrays (y2 h/l)
__device__ __forceinline__ size_t a_tiled_off(int m, int d) {
    int row = m & 127;
    int chunk = ((d & 63) >> 3) ^ (row & 7);
    return ((size_t)((m >> 7) * 8 + (d >> 6)) << 13)
         + (size_t)row * 64 + (chunk << 3) + (d & 7);
}

// ---------------------------------------------------------------------------
// f32x2 packed-math helpers
// ---------------------------------------------------------------------------
__device__ __forceinline__ ull pk2(float a, float b) {
    ull r; asm("mov.b64 %0, {%1, %2};" : "=l"(r) : "f"(a), "f"(b)); return r;
}
__device__ __forceinline__ float2 upk2(ull v) {
    float2 f; asm("mov.b64 {%0, %1}, %2;" : "=f"(f.x), "=f"(f.y) : "l"(v)); return f;
}
__device__ __forceinline__ ull fma2(ull a, ull b, ull c) {
    ull d; asm("fma.rn.f32x2 %0, %1, %2, %3;" : "=l"(d) : "l"(a), "l"(b), "l"(c)); return d;
}
__device__ __forceinline__ ull mul2(ull a, ull b) {
    ull d; asm("mul.rn.f32x2 %0, %1, %2;" : "=l"(d) : "l"(a), "l"(b)); return d;
}
__device__ __forceinline__ ull add2(ull a, ull b) {
    ull d; asm("add.rn.f32x2 %0, %1, %2;" : "=l"(d) : "l"(a), "l"(b)); return d;
}

__device__ __forceinline__ void pack_hl(float4 v, uint2& H, uint2& L) {
    unsigned short h[4], l[4];
    float e[4] = {v.x, v.y, v.z, v.w};
    #pragma unroll
    for (int j = 0; j < 4; j++) {
        __nv_bfloat16 hb = __float2bfloat16_rn(e[j]);
        float r = e[j] - __bfloat162float(hb);
        h[j] = __bfloat16_as_ushort(hb);
        l[j] = __bfloat16_as_ushort(__float2bfloat16_rn(r));
    }
    H.x = (uint32_t)h[0] | ((uint32_t)h[1] << 16);
    H.y = (uint32_t)h[2] | ((uint32_t)h[3] << 16);
    L.x = (uint32_t)l[0] | ((uint32_t)l[1] << 16);
    L.y = (uint32_t)l[2] | ((uint32_t)l[3] << 16);
}

// mbarrier helpers
__device__ __forceinline__ void mbar_init(uint32_t a, uint32_t cnt) {
    asm volatile("mbarrier.init.shared.b64 [%0], %1;" :: "r"(a), "r"(cnt) : "memory");
}
__device__ __forceinline__ void mbar_expect_tx(uint32_t a, uint32_t tx) {
    asm volatile("mbarrier.arrive.expect_tx.shared.b64 _, [%0], %1;" :: "r"(a), "r"(tx) : "memory");
}
__device__ __forceinline__ void mbar_arrive(uint32_t a) {
    asm volatile("mbarrier.arrive.shared.b64 _, [%0];" :: "r"(a) : "memory");
}
__device__ __forceinline__ void mbar_wait(uint32_t a, int parity) {
    asm volatile(
        "{\n\t.reg .pred P;\n"
        "LW_%=:\n\t"
        "mbarrier.try_wait.parity.acquire.cta.shared::cta.b64 P, [%0], %1, 0x989680;\n\t"
        "@P bra.uni LD_%=;\n\t"
        "bra.uni LW_%=;\n"
        "LD_%=:\n\t}"
        :: "r"(a), "r"(parity) : "memory");
}
__device__ __forceinline__ void bulk_cp(uint32_t dst, const void* src,
                                        uint32_t bytes, uint32_t mbar) {
    asm volatile(
        "cp.async.bulk.shared::cta.global.mbarrier::complete_tx::bytes [%0], [%1], %2, [%3];"
        :: "r"(dst), "l"(src), "r"(bytes), "r"(mbar) : "memory");
}

// ---------------------------------------------------------------------------
// Kernel 1: LayerNorm
// ---------------------------------------------------------------------------
__global__ void ln_kernel(const float* __restrict__ x,
                          const float* __restrict__ gamma,
                          const float* __restrict__ beta) {
    const int row = blockIdx.x;
    const int t = threadIdx.x;
    const float4* xr = (const float4*)(x + (size_t)row * DM);
    float4 v = xr[t];
    float s  = v.x + v.y + v.z + v.w;
    float ss = v.x * v.x + v.y * v.y + v.z * v.z + v.w * v.w;

    __shared__ float sh[8];
    #pragma unroll
    for (int o = 16; o; o >>= 1) {
        s  += __shfl_xor_sync(0xffffffffu, s, o);
        ss += __shfl_xor_sync(0xffffffffu, ss, o);
    }
    int w = t >> 5;
    if ((t & 31) == 0) { sh[w] = s; sh[4 + w] = ss; }
    __syncthreads();
    float S  = sh[0] + sh[1] + sh[2] + sh[3];
    float SS = sh[4] + sh[5] + sh[6] + sh[7];

    const float inv = 1.0f / (float)DM;
    float mu = S * inv;
    float var = SS * inv - mu * mu;
    float rs = rsqrtf(var + 1e-5f);

    float4 g4 = ((const float4*)gamma)[t];
    float4 b4 = ((const float4*)beta)[t];
    float4 o4;
    o4.x = (v.x - mu) * rs * g4.x + b4.x;
    o4.y = (v.y - mu) * rs * g4.y + b4.y;
    o4.z = (v.z - mu) * rs * g4.z + b4.z;
    o4.w = (v.w - mu) * rs * g4.w + b4.w;
    ((float4*)(g_xn + (size_t)row * DM))[t] = o4;
}

// ---------------------------------------------------------------------------
// Kernel 2: FiLM params
// ---------------------------------------------------------------------------
__global__ void film_kernel(const float* __restrict__ emb,
                            const float* __restrict__ Wf,
                            const float* __restrict__ bf) {
    __shared__ float se[EMB];
    const int b = blockIdx.x;
    for (int i = threadIdx.x; i < EMB; i += blockDim.x) {
        float e = emb[b * EMB + i];
        se[i] = e / (1.0f + expf(-e));
    }
    __syncthreads();
    for (int j = threadIdx.x; j < 2 * DM; j += blockDim.x) {
        const float4* wr = (const float4*)(Wf + (size_t)j * EMB);
        const float4* sr = (const float4*)se;
        float acc = bf[j];
        #pragma unroll 4
        for (int q = 0; q < EMB / 4; q++) {
            float4 w = wr[q], sv = sr[q];
            acc += w.x * sv.x + w.y * sv.y + w.z * sv.z + w.w * sv.w;
        }
        g_film[b * 2 * DM + j] = acc;
    }
}

// ---------------------------------------------------------------------------
// Kernel 2b: split W into bf16 hi/lo, TILED (64x64 tiles, swizzled 128B rows)
// one thread per 16B chunk (8 k-elements): 65536 threads
// ---------------------------------------------------------------------------
__global__ void prep_w(const float* __restrict__ W) {
    int i = blockIdx.x * blockDim.x + threadIdx.x;   // 0 .. 65535
    int r = i >> 6;          // W row 0..1023
    int kc = i & 63;         // chunk-of-8 in k
    const float* src = W + (size_t)r * DM + kc * 8;
    float4 v0 = *(const float4*)src;
    float4 v1 = *(const float4*)(src + 4);
    float e[8] = {v0.x, v0.y, v0.z, v0.w, v1.x, v1.y, v1.z, v1.w};
    uint32_t hw[4], lw[4];
    #pragma unroll
    for (int j = 0; j < 4; j++) {
        unsigned short h0, h1, l0, l1;
        __nv_bfloat16 hb0 = __float2bfloat16_rn(e[j * 2]);
        __nv_bfloat16 hb1 = __float2bfloat16_rn(e[j * 2 + 1]);
        h0 = __bfloat16_as_ushort(hb0);
        h1 = __bfloat16_as_ushort(hb1);
        l0 = __bfloat16_as_ushort(__float2bfloat16_rn(e[j * 2] - __bfloat162float(hb0)));
        l1 = __bfloat16_as_ushort(__float2bfloat16_rn(e[j * 2 + 1] - __bfloat162float(hb1)));
        hw[j] = (uint32_t)h0 | ((uint32_t)h1 << 16);
        lw[j] = (uint32_t)l0 | ((uint32_t)l1 << 16);
    }
    int row = r & 63;
    int chunk = (kc & 7) ^ (row & 7);
    size_t off = ((size_t)((r >> 6) * 8 + (kc >> 3)) << 12)
               + (size_t)row * 64 + (chunk << 3);
    *(uint4*)(g_Wh + off) = make_uint4(hw[0], hw[1], hw[2], hw[3]);
    *(uint4*)(g_Wl + off) = make_uint4(lw[0], lw[1], lw[2], lw[3]);
}

// ---------------------------------------------------------------------------
// Kernel 3a: local S4D scan over one chunk (zero initial state).
// ---------------------------------------------------------------------------
__global__ void scan_local(const float* __restrict__ A_real,
                           const float* __restrict__ A_imag,
                           const float* __restrict__ Cp,
                           const float* __restrict__ log_dt,
                           const float* __restrict__ B_ssm,
                           const float* __restrict__ D_skip) {
    const int t = threadIdx.x;
    const int grp = t >> 4;
    const int g = t & 15;
    const int blk = blockIdx.x;
    const int c = blk & 7;
    const int rest = blk >> 3;
    const int gid = rest * 8 + grp;
    const int b = gid >> 9;
    const int d = gid & 511;
    const int d0 = (rest * 8) & 511;

    const float dt = expf(log_dt[d]);
    ull Abr[2], Abi[2], nAbi[2], Ccr[2], nCci[2], s_r[2], s_i[2];
    #pragma unroll
    for (int p = 0; p < 2; p++) {
        float abr[2], abi[2], ccr[2], cci[2];
        #pragma unroll
        for (int j = 0; j < 2; j++) {
            int n = g * 4 + p * 2 + j;
            float ar = dt * A_real[d * NS + n];
            float ai = dt * A_imag[d * NS + n];
            float er = expf(ar), sb, cb;
            sincosf(ai, &sb, &cb);
            abr[j] = er * cb;
            abi[j] = er * sb;
            float bs = B_ssm[d * NS + n];
            ccr[j] = Cp[(d * NS + n) * 2 + 0] * bs;
            cci[j] = Cp[(d * NS + n) * 2 + 1] * bs;
        }
        Abr[p]  = pk2(abr[0], abr[1]);
        Abi[p]  = pk2(abi[0], abi[1]);
        nAbi[p] = pk2(-abi[0], -abi[1]);
        Ccr[p]  = pk2(ccr[0], ccr[1]);
        nCci[p] = pk2(-cci[0], -cci[1]);
        s_r[p] = 0ull; s_i[p] = 0ull;
    }
    const float dsk = D_skip[d];
    const float mult  = 1.0f + g_film[b * 2 * DM + d];
    const float shift = g_film[b * 2 * DM + DM + d];

    __shared__ float sx[2][64][8];
    __shared__ float syb[2][64][8];
    const size_t cbase = (size_t)b * LSEQ * DM + (size_t)c * TCH * DM;
    const float* xbase = g_xn + cbase + d0;
    float* ypb = g_yp + cbase + d0;

    const int ll = t >> 1, half = t & 1;
    *(float4*)&sx[0][ll][half * 4] =
        *(const float4*)(xbase + (size_t)ll * DM + half * 4);
    __syncthreads();

    for (int ch = 0; ch < TCH / 64; ch++) {
        const int cur = ch & 1;
        float4 nld;
        const bool more = (ch + 1 < TCH / 64);
        if (more) {
            nld = *(const float4*)(xbase + (size_t)((ch + 1) * 64 + ll) * DM + half * 4);
        }
        #pragma unroll 4
        for (int i = 0; i < 64; i++) {
            float xv = sx[cur][i][grp];
            ull x2 = pk2(xv, xv);
            ull acc = 0ull;
            #pragma unroll
            for (int p = 0; p < 2; p++) {
                ull t1 = fma2(nAbi[p], s_i[p], x2);
                ull nr = fma2(Abr[p], s_r[p], t1);
                ull u  = mul2(Abi[p], s_r[p]);
                ull ni = fma2(Abr[p], s_i[p], u);
                s_r[p] = nr; s_i[p] = ni;
                acc = fma2(Ccr[p], nr, acc);
                acc = fma2(nCci[p], ni, acc);
            }
            float2 ac = upk2(acc);
            float tsum = ac.x + ac.y;
            #pragma unroll
            for (int o = 8; o; o >>= 1)
                tsum += __shfl_xor_sync(0xffffffffu, tsum, o);
            if (g == 0) {
                float o = dt * tsum + dsk * xv;
                syb[cur][i][grp] = o * mult + shift;
            }
        }
        if (more) {
            *(float4*)&sx[cur ^ 1][ll][half * 4] = nld;
        }
        __syncthreads();
        {
            const int r = t >> 1, hh = t & 1;
            float4 v = *(float4*)&syb[cur][r][hh * 4];
            if (c == 0) {
                int m = b * LSEQ + ch * 64 + r;
                size_t off = a_tiled_off(m, d0 + hh * 4);
                uint2 H, L;
                pack_hl(v, H, L);
                *(uint2*)(g_y2h + off) = H;
                *(uint2*)(g_y2l + off) = L;
            } else {
                *(float4*)(ypb + (size_t)(ch * 64 + r) * DM + hh * 4) = v;
            }
        }
    }

    size_t sb = ((size_t)(b * CHK + c) * DM + d) * 32 + g * 2;
    g_str[sb + 0] = s_r[0];
    g_str[sb + 1] = s_r[1];
    g_sti[sb + 0] = s_i[0];
    g_sti[sb + 1] = s_i[1];
}

// ---------------------------------------------------------------------------
// Kernel 3b: fixup for chunks c=1..7.
// ---------------------------------------------------------------------------
__global__ void scan_fixup(const float* __restrict__ A_real,
                           const float* __restrict__ A_imag,
                           const float* __restrict__ Cp,
                           const float* __restrict__ log_dt,
                           const float* __restrict__ B_ssm) {
    const int t = threadIdx.x;
    const int grp = t >> 4;
    const int g = t & 15;
    const int blk = blockIdx.x;
    const int c = 1 + blk % 7;
    const int rest = blk / 7;
    const int gid = rest * 8 + grp;
    const int b = gid >> 9;
    const int d = gid & 511;
    const int d0 = (rest * 8) & 511;

    const float dt = expf(log_dt[d]);
    const float k = dt * (1.0f + g_film[b * 2 * DM + d]);

    ull Lr[2], Li[2], nLi[2], LTr[2], LTi[2], nLTi[2], Ccr[2], Cci[2], nCci[2];
    #pragma unroll
    for (int p = 0; p < 2; p++) {
        float lr[2], li[2], ltr[2], lti[2], ccr[2], cci[2];
        #pragma unroll
        for (int j = 0; j < 2; j++) {
            int n = g * 4 + p * 2 + j;
            float ar = dt * A_real[d * NS + n];
            float ai = dt * A_imag[d * NS + n];
            float er = expf(ar), sb, cb;
            sincosf(ai, &sb, &cb);
            lr[j] = er * cb;
            li[j] = er * sb;
            float pr = lr[j], pi = li[j];
            #pragma unroll
            for (int q = 0; q < 8; q++) {
                float nr2 = pr * pr - pi * pi;
                pi = 2.0f * pr * pi;
                pr = nr2;
            }
            ltr[j] = pr; lti[j] = pi;
            float bs = B_ssm[d * NS + n];
            ccr[j] = Cp[(d * NS + n) * 2 + 0] * bs * k;
            cci[j] = Cp[(d * NS + n) * 2 + 1] * bs * k;
        }
        Lr[p]   = pk2(lr[0], lr[1]);
        Li[p]   = pk2(li[0], li[1]);
        nLi[p]  = pk2(-li[0], -li[1]);
        LTr[p]  = pk2(ltr[0], ltr[1]);
        LTi[p]  = pk2(lti[0], lti[1]);
        nLTi[p] = pk2(-lti[0], -lti[1]);
        Ccr[p]  = pk2(ccr[0], ccr[1]);
        Cci[p]  = pk2(cci[0], cci[1]);
        nCci[p] = pk2(-cci[0], -cci[1]);
    }

    ull ar_[2] = {0ull, 0ull}, ai_[2] = {0ull, 0ull};
    size_t sb0 = ((size_t)(b * CHK) * DM + d) * 32 + g * 2;
    for (int cp = 0; cp < c; cp++) {
        size_t sb = sb0 + (size_t)cp * DM * 32;
        #pragma unroll
        for (int p = 0; p < 2; p++) {
            ull sr = g_str[sb + p];
            ull si = g_sti[sb + p];
            ull t1 = fma2(nLTi[p], ai_[p], sr);
            ull nr = fma2(LTr[p], ar_[p], t1);
            ull t2 = fma2(LTi[p], ar_[p], si);
            ull ni = fma2(LTr[p], ai_[p], t2);
            ar_[p] = nr; ai_[p] = ni;
        }
    }

    ull Wr[2], Wi[2];
    #pragma unroll
    for (int p = 0; p < 2; p++) {
        Wr[p] = fma2(Ccr[p], ar_[p], mul2(nCci[p], ai_[p]));
        Wi[p] = fma2(Ccr[p], ai_[p], mul2(Cci[p], ar_[p]));
    }

    __shared__ float syc[64][8];
    const size_t cbase = (size_t)b * LSEQ * DM + (size_t)c * TCH * DM;
    const float* ypb = g_yp + cbase + d0;

    for (int tile = 0; tile < TCH / 64; tile++) {
        #pragma unroll 4
        for (int i = 0; i < 64; i++) {
            #pragma unroll
            for (int p = 0; p < 2; p++) {
                ull t1 = mul2(nLi[p], Wi[p]);
                ull nr = fma2(Lr[p], Wr[p], t1);
                ull t2 = mul2(Li[p], Wr[p]);
                ull ni = fma2(Lr[p], Wi[p], t2);
                Wr[p] = nr; Wi[p] = ni;
            }
            ull acc = add2(Wr[0], Wr[1]);
            float2 a2 = upk2(acc);
            float tsum = a2.x + a2.y;
            #pragma unroll
            for (int o = 8; o; o >>= 1)
                tsum += __shfl_xor_sync(0xffffffffu, tsum, o);
            if (g == 0) syc[i][grp] = tsum;
        }
        __syncthreads();
        {
            const int r = t >> 1, hh = t & 1;
            size_t lrow = (size_t)(tile * 64 + r) * DM + hh * 4;
            float4 v = *(const float4*)(ypb + lrow);
            v.x += syc[r][hh * 4 + 0];
            v.y += syc[r][hh * 4 + 1];
            v.z += syc[r][hh * 4 + 2];
            v.w += syc[r][hh * 4 + 3];
            int m = b * LSEQ + c * TCH + tile * 64 + r;
            size_t off = a_tiled_off(m, d0 + hh * 4);
            uint2 H, L;
            pack_hl(v, H, L);
            *(uint2*)(g_y2h + off) = H;
            *(uint2*)(g_y2l + off) = L;
        }
        __syncthreads();
    }
}

// ---------------------------------------------------------------------------
// Kernel 4: out_proj GEMM, bulk-copy pipeline (3 stages, BK=64) + LDSM(swz)
// + 3-pass bf16 split MMA + GLU + residual.
// ---------------------------------------------------------------------------
#define ASTG 32768   // bf16 elements per stage
#define NSTG 3
#define GSM_BYTES (NSTG * ASTG * 2)

__device__ __forceinline__ void mma_bf16(float d[4], const uint32_t a[4],
                                         const uint32_t b0, const uint32_t b1) {
    asm volatile(
        "mma.sync.aligned.m16n8k16.row.col.f32.bf16.bf16.f32 "
        "{%0,%1,%2,%3}, {%4,%5,%6,%7}, {%8,%9}, {%0,%1,%2,%3};\n"
        : "+f"(d[0]), "+f"(d[1]), "+f"(d[2]), "+f"(d[3])
        : "r"(a[0]), "r"(a[1]), "r"(a[2]), "r"(a[3]), "r"(b0), "r"(b1));
}
__device__ __forceinline__ void ldsm4(uint32_t* r, uint32_t byteaddr) {
    asm volatile("ldmatrix.sync.aligned.m8n8.x4.shared.b16 {%0,%1,%2,%3}, [%4];"
        : "=r"(r[0]), "=r"(r[1]), "=r"(r[2]), "=r"(r[3]) : "r"(byteaddr));
}

__global__ void __launch_bounds__(256, 1)
gemm_glu_tc(const float* __restrict__ bo,
            const float* __restrict__ resid,
            float* __restrict__ out) {
    extern __shared__ __nv_bfloat16 smb[];
    __shared__ uint64_t mbar_store[2 * NSTG];
    const uint32_t sb = (uint32_t)__cvta_generic_to_shared(smb);
    const uint32_t mb = (uint32_t)__cvta_generic_to_shared(mbar_store);

    const int tid = threadIdx.x;
    const int mblk = blockIdx.x;          // m0 = mblk*128
    const int cblk = blockIdx.y;          // c0 = cblk*64
    const int m0 = mblk * 128;
    const int c0 = cblk * 64;
    const int warp = tid >> 5, lane = tid & 31;
    const int wm = warp & 3, wn = warp >> 2;
    const int grp = lane >> 3, tig = lane & 3;  // grp recomputed below for epi

    if (tid == 0) {
        #pragma unroll
        for (int s = 0; s < NSTG; s++) {
            mbar_init(mb + s * 8, 1);                 // full: 1 arrive (expect_tx)
            mbar_init(mb + (NSTG + s) * 8, 256);      // empty: all threads
        }
    }
    __syncthreads();

    auto issue_stage = [&](int it) {
        int s = it % NSTG;
        uint32_t full = mb + s * 8;
        mbar_expect_tx(full, 65536);
        uint32_t st = sb + (uint32_t)(s * ASTG) * 2;
        // A tiles (128x64 = 16KB each)
        bulk_cp(st,             (const char*)g_y2h + (((size_t)mblk * 8 + it) << 14), 16384, full);
        bulk_cp(st + 16384,     (const char*)g_y2l + (((size_t)mblk * 8 + it) << 14), 16384, full);
        // B tiles (64x64 = 8KB each): a-gate rows c0.., g-gate rows 512+c0..
        bulk_cp(st + 32768,     (const char*)g_Wh + (((size_t)cblk * 8 + it) << 13), 8192, full);
        bulk_cp(st + 40960,     (const char*)g_Wh + (((size_t)(8 + cblk) * 8 + it) << 13), 8192, full);
        bulk_cp(st + 49152,     (const char*)g_Wl + (((size_t)cblk * 8 + it) << 13), 8192, full);
        bulk_cp(st + 57344,     (const char*)g_Wl + (((size_t)(8 + cblk) * 8 + it) << 13), 8192, full);
    };

    if (tid == 0) {
        issue_stage(0);
        issue_stage(1);
        issue_stage(2);
    }

    float da[2][4][4];
    float dg[2][4][4];
    #pragma unroll
    for (int mt = 0; mt < 2; mt++)
        #pragma unroll
        for (int nt = 0; nt < 4; nt++)
            #pragma unroll
            for (int r = 0; r < 4; r++) { da[mt][nt][r] = 0.0f; dg[mt][nt][r] = 0.0f; }

    // per-lane LDSM row indices
    const int rowA0 = wm * 32 + (lane & 15);           // + mt*16
    const int rowB0 = wn * 32 + ((lane & 16) >> 1) + (lane & 7);  // + go*16
    const int chA0 = (lane >> 4);                      // + 2*kk
    const int chB0 = (lane >> 3) & 1;                  // + 2*kk

    const int NKT = 8;   // 512 / 64
    for (int it = 0; it < NKT; it++) {
        const int s = it % NSTG;
        const int q = it / NSTG;
        mbar_wait(mb + s * 8, q & 1);

        const uint32_t stA = sb + (uint32_t)(s * ASTG) * 2;      // AH
        // byte offsets within stage: AH 0, AL 16384, BHa 32768, BHg 40960,
        // BLa 49152, BLg 57344

        #pragma unroll
        for (int kk = 0; kk < 4; kk++) {
            uint32_t ah[2][4], al[2][4];
            #pragma unroll
            for (int mt = 0; mt < 2; mt++) {
                int rowA = rowA0 + mt * 16;
                int ch = (2 * kk + chA0) ^ (rowA & 7);
                uint32_t ad = stA + (uint32_t)(rowA * 128 + ch * 16);
                ldsm4(ah[mt], ad);
                ldsm4(al[mt], ad + 16384);
            }
            // a-gate B
            {
                uint32_t bh[8], bl[8];
                #pragma unroll
                for (int go = 0; go < 2; go++) {
                    int rr = rowB0 + go * 16;
                    int cs = (2 * kk + chB0) ^ (rr & 7);
                    uint32_t bd = stA + 32768 + (uint32_t)(rr * 128 + cs * 16);
                    ldsm4(&bh[go * 4], bd);
                    ldsm4(&bl[go * 4], bd + 16384);
                }
                #pragma unroll
                for (int mt = 0; mt < 2; mt++)
                    #pragma unroll
                    for (int nt = 0; nt < 4; nt++) {
                        mma_bf16(da[mt][nt], ah[mt], bh[nt * 2], bh[nt * 2 + 1]);
                        mma_bf16(da[mt][nt], ah[mt], bl[nt * 2], bl[nt * 2 + 1]);
                        mma_bf16(da[mt][nt], al[mt], bh[nt * 2], bh[nt * 2 + 1]);
                    }
            }
            // g-gate B
            {
                uint32_t bh[8], bl[8];
                #pragma unroll
                for (int go = 0; go < 2; go++) {
                    int rr = rowB0 + go * 16;
                    int cs = (2 * kk + chB0) ^ (rr & 7);
                    uint32_t bd = stA + 40960 + (uint32_t)(rr * 128 + cs * 16);
                    ldsm4(&bh[go * 4], bd);
                    ldsm4(&bl[go * 4], bd + 16384);
                }
                #pragma unroll
                for (int mt = 0; mt < 2; mt++)
                    #pragma unroll
                    for (int nt = 0; nt < 4; nt++) {
                        mma_bf16(dg[mt][nt], ah[mt], bh[nt * 2], bh[nt * 2 + 1]);
                        mma_bf16(dg[mt][nt], ah[mt], bl[nt * 2], bl[nt * 2 + 1]);
                        mma_bf16(dg[mt][nt], al[mt], bh[nt * 2], bh[nt * 2 + 1]);
                    }
            }
        }

        // release stage
        mbar_arrive(mb + (NSTG + s) * 8);
        if (tid == 0 && it + NSTG < NKT) {
            mbar_wait(mb + (NSTG + s) * 8, q & 1);
            issue_stage(it + NSTG);
        }
    }

    // epilogue: a*sigmoid(g) + residual   (accumulator layout same as R5)
    const int egrp = lane >> 2;
    #pragma unroll
    for (int mt = 0; mt < 2; mt++) {
        #pragma unroll
        for (int nt = 0; nt < 4; nt++) {
            int col = c0 + wn * 32 + nt * 8 + tig * 2;
            float ba0 = bo[col], ba1 = bo[col + 1];
            float bg0 = bo[DM + col], bg1 = bo[DM + col + 1];
            #pragma unroll
            for (int half = 0; half < 2; half++) {
                int r = m0 + wm * 32 + mt * 16 + egrp + half * 8;
                float a0 = da[mt][nt][half * 2 + 0] + ba0;
                float a1 = da[mt][nt][half * 2 + 1] + ba1;
                float g0 = dg[mt][nt][half * 2 + 0] + bg0;
                float g1 = dg[mt][nt][half * 2 + 1] + bg1;
                float2 res = *(const float2*)(resid + (size_t)r * DM + col);
                float2 o;
                o.x = res.x + a0 * (1.0f / (1.0f + expf(-g0)));
                o.y = res.y + a1 * (1.0f / (1.0f + expf(-g1)));
                *(float2*)(out + (size_t)r * DM + col) = o;
            }
        }
    }
}

// ---------------------------------------------------------------------------
extern "C" void kernel_launch(void* const* d_in, const int* in_sizes, int n_in,
                              void* d_out, int out_size) {
    const float* x      = (const float*)d_in[0];
    const float* emb    = (const float*)d_in[1];
    const float* A_real = (const float*)d_in[2];
    const float* A_imag = (const float*)d_in[3];
    const float* C      = (const float*)d_in[4];
    const float* log_dt = (const float*)d_in[5];
    const float* B_ssm  = (const float*)d_in[6];
    const float* D_skip = (const float*)d_in[7];
    const float* ln_g   = (const float*)d_in[8];
    const float* ln_b   = (const float*)d_in[9];
    const float* W_out  = (const float*)d_in[10];
    const float* b_out  = (const float*)d_in[11];
    const float* W_film = (const float*)d_in[12];
    const float* b_film = (const float*)d_in[13];
    float* out = (float*)d_out;

    static bool configured = false;
    if (!configured) {
        cudaFuncSetAttribute(gemm_glu_tc,
                             cudaFuncAttributeMaxDynamicSharedMemorySize,
                             GSM_BYTES);
        configured = true;
    }

    ln_kernel<<<BSZ * LSEQ, 128>>>(x, ln_g, ln_b);
    film_kernel<<<BSZ, 256>>>(emb, W_film, b_film);
    prep_w<<<256, 256>>>(W_out);
    scan_local<<<BSZ * (DM / 8) * CHK, 128>>>(A_real, A_imag, C, log_dt, B_ssm, D_skip);
    scan_fixup<<<BSZ * (DM / 8) * (CHK - 1), 128>>>(A_real, A_imag, C, log_dt, B_ssm);
    gemm_glu_tc<<<dim3((BSZ * LSEQ) / 128, DM / 64), 256, GSM_BYTES>>>(b_out, x, out);
}

// round 8
// speedup vs baseline: 1.3610x; 1.0399x over previous
#include <cuda_runtime.h>
#include <cuda_bf16.h>
#include <math.h>
#include <stdint.h>

#define BSZ 8
#define LSEQ 2048
#define DM 512
#define NS 64
#define EMB 512
#define CHK 8
#define TCH 256   // LSEQ / CHK

typedef unsigned long long ull;

// Scratch (allocation-free rule: __device__ globals)
// g_y2h/l and g_Wh/l are stored PRE-TILED + PRE-SWIZZLED (SW128-equivalent):
//   A tiles: [m/128][k/64] tiles of 128x64 bf16, rows 128B, chunk ^= row&7
//   W tiles: [r/64][k/64]  tiles of  64x64 bf16, same swizzle
__device__ __align__(1024) float g_xn[BSZ * LSEQ * DM];
__device__ __align__(1024) float g_yp[BSZ * LSEQ * DM];
__device__ __align__(1024) __nv_bfloat16 g_y2h[BSZ * LSEQ * DM];
__device__ __align__(1024) __nv_bfloat16 g_y2l[BSZ * LSEQ * DM];
__device__ __align__(1024) __nv_bfloat16 g_Wh[2 * DM * DM];
__device__ __align__(1024) __nv_bfloat16 g_Wl[2 * DM * DM];
__device__ float g_film[BSZ * 2 * DM];
__device__ ull g_str[BSZ * CHK * DM * 32];
__device__ ull g_sti[BSZ * CHK * DM * 32];

// tiled+swizzled element offset into A-layout arrays (y2 h/l)
__device__ __forceinline__ size_t a_tiled_off(int m, int d) {
    int row = m & 127;
    int chunk = ((d & 63) >> 3) ^ (row & 7);
    return ((size_t)((m >> 7) * 8 + (d >> 6)) << 13)
         + (size_t)row * 64 + (chunk << 3) + (d & 7);
}

// ---------------------------------------------------------------------------
// f32x2 packed-math helpers
// ---------------------------------------------------------------------------
__device__ __forceinline__ ull pk2(float a, float b) {
    ull r; asm("mov.b64 %0, {%1, %2};" : "=l"(r) : "f"(a), "f"(b)); return r;
}
__device__ __forceinline__ float2 upk2(ull v) {
    float2 f; asm("mov.b64 {%0, %1}, %2;" : "=f"(f.x), "=f"(f.y) : "l"(v)); return f;
}
__device__ __forceinline__ ull fma2(ull a, ull b, ull c) {
    ull d; asm("fma.rn.f32x2 %0, %1, %2, %3;" : "=l"(d) : "l"(a), "l"(b), "l"(c)); return d;
}
__device__ __forceinline__ ull mul2(ull a, ull b) {
    ull d; asm("mul.rn.f32x2 %0, %1, %2;" : "=l"(d) : "l"(a), "l"(b)); return d;
}
__device__ __forceinline__ ull add2(ull a, ull b) {
    ull d; asm("add.rn.f32x2 %0, %1, %2;" : "=l"(d) : "l"(a), "l"(b)); return d;
}

__device__ __forceinline__ void pack_hl(float4 v, uint2& H, uint2& L) {
    unsigned short h[4], l[4];
    float e[4] = {v.x, v.y, v.z, v.w};
    #pragma unroll
    for (int j = 0; j < 4; j++) {
        __nv_bfloat16 hb = __float2bfloat16_rn(e[j]);
        float r = e[j] - __bfloat162float(hb);
        h[j] = __bfloat16_as_ushort(hb);
        l[j] = __bfloat16_as_ushort(__float2bfloat16_rn(r));
    }
    H.x = (uint32_t)h[0] | ((uint32_t)h[1] << 16);
    H.y = (uint32_t)h[2] | ((uint32_t)h[3] << 16);
    L.x = (uint32_t)l[0] | ((uint32_t)l[1] << 16);
    L.y = (uint32_t)l[2] | ((uint32_t)l[3] << 16);
}

// mbarrier helpers
__device__ __forceinline__ void mbar_init(uint32_t a, uint32_t cnt) {
    asm volatile("mbarrier.init.shared.b64 [%0], %1;" :: "r"(a), "r"(cnt) : "memory");
}
__device__ __forceinline__ void mbar_expect_tx(uint32_t a, uint32_t tx) {
    asm volatile("mbarrier.arrive.expect_tx.shared.b64 _, [%0], %1;" :: "r"(a), "r"(tx) : "memory");
}
__device__ __forceinline__ void mbar_arrive(uint32_t a) {
    asm volatile("mbarrier.arrive.shared.b64 _, [%0];" :: "r"(a) : "memory");
}
__device__ __forceinline__ void mbar_wait(uint32_t a, int parity) {
    asm volatile(
        "{\n\t.reg .pred P;\n"
        "LW_%=:\n\t"
        "mbarrier.try_wait.parity.acquire.cta.shared::cta.b64 P, [%0], %1, 0x989680;\n\t"
        "@P bra.uni LD_%=;\n\t"
        "bra.uni LW_%=;\n"
        "LD_%=:\n\t}"
        :: "r"(a), "r"(parity) : "memory");
}
__device__ __forceinline__ void bulk_cp(uint32_t dst, const void* src,
                                        uint32_t bytes, uint32_t mbar) {
    asm volatile(
        "cp.async.bulk.shared::cta.global.mbarrier::complete_tx::bytes [%0], [%1], %2, [%3];"
        :: "r"(dst), "l"(src), "r"(bytes), "r"(mbar) : "memory");
}

// ---------------------------------------------------------------------------
// Kernel 1: LayerNorm
// ---------------------------------------------------------------------------
__global__ void ln_kernel(const float* __restrict__ x,
                          const float* __restrict__ gamma,
                          const float* __restrict__ beta) {
    const int row = blockIdx.x;
    const int t = threadIdx.x;
    const float4* xr = (const float4*)(x + (size_t)row * DM);
    float4 v = xr[t];
    float s  = v.x + v.y + v.z + v.w;
    float ss = v.x * v.x + v.y * v.y + v.z * v.z + v.w * v.w;

    __shared__ float sh[8];
    #pragma unroll
    for (int o = 16; o; o >>= 1) {
        s  += __shfl_xor_sync(0xffffffffu, s, o);
        ss += __shfl_xor_sync(0xffffffffu, ss, o);
    }
    int w = t >> 5;
    if ((t & 31) == 0) { sh[w] = s; sh[4 + w] = ss; }
    __syncthreads();
    float S  = sh[0] + sh[1] + sh[2] + sh[3];
    float SS = sh[4] + sh[5] + sh[6] + sh[7];

    const float inv = 1.0f / (float)DM;
    float mu = S * inv;
    float var = SS * inv - mu * mu;
    float rs = rsqrtf(var + 1e-5f);

    float4 g4 = ((const float4*)gamma)[t];
    float4 b4 = ((const float4*)beta)[t];
    float4 o4;
    o4.x = (v.x - mu) * rs * g4.x + b4.x;
    o4.y = (v.y - mu) * rs * g4.y + b4.y;
    o4.z = (v.z - mu) * rs * g4.z + b4.z;
    o4.w = (v.w - mu) * rs * g4.w + b4.w;
    ((float4*)(g_xn + (size_t)row * DM))[t] = o4;
}

// ---------------------------------------------------------------------------
// Kernel 2: FiLM params
// ---------------------------------------------------------------------------
__global__ void film_kernel(const float* __restrict__ emb,
                            const float* __restrict__ Wf,
                            const float* __restrict__ bf) {
    __shared__ float se[EMB];
    const int b = blockIdx.x;
    for (int i = threadIdx.x; i < EMB; i += blockDim.x) {
        float e = emb[b * EMB + i];
        se[i] = e / (1.0f + expf(-e));
    }
    __syncthreads();
    for (int j = threadIdx.x; j < 2 * DM; j += blockDim.x) {
        const float4* wr = (const float4*)(Wf + (size_t)j * EMB);
        const float4* sr = (const float4*)se;
        float acc = bf[j];
        #pragma unroll 4
        for (int q = 0; q < EMB / 4; q++) {
            float4 w = wr[q], sv = sr[q];
            acc += w.x * sv.x + w.y * sv.y + w.z * sv.z + w.w * sv.w;
        }
        g_film[b * 2 * DM + j] = acc;
    }
}

// ---------------------------------------------------------------------------
// Kernel 2b: split W into bf16 hi/lo, TILED (64x64 tiles, swizzled 128B rows)
// ---------------------------------------------------------------------------
__global__ void prep_w(const float* __restrict__ W) {
    int i = blockIdx.x * blockDim.x + threadIdx.x;   // 0 .. 65535
    int r = i >> 6;
    int kc = i & 63;
    const float* src = W + (size_t)r * DM + kc * 8;
    float4 v0 = *(const float4*)src;
    float4 v1 = *(const float4*)(src + 4);
    float e[8] = {v0.x, v0.y, v0.z, v0.w, v1.x, v1.y, v1.z, v1.w};
    uint32_t hw[4], lw[4];
    #pragma unroll
    for (int j = 0; j < 4; j++) {
        unsigned short h0, h1, l0, l1;
        __nv_bfloat16 hb0 = __float2bfloat16_rn(e[j * 2]);
        __nv_bfloat16 hb1 = __float2bfloat16_rn(e[j * 2 + 1]);
        h0 = __bfloat16_as_ushort(hb0);
        h1 = __bfloat16_as_ushort(hb1);
        l0 = __bfloat16_as_ushort(__float2bfloat16_rn(e[j * 2] - __bfloat162float(hb0)));
        l1 = __bfloat16_as_ushort(__float2bfloat16_rn(e[j * 2 + 1] - __bfloat162float(hb1)));
        hw[j] = (uint32_t)h0 | ((uint32_t)h1 << 16);
        lw[j] = (uint32_t)l0 | ((uint32_t)l1 << 16);
    }
    int row = r & 63;
    int chunk = (kc & 7) ^ (row & 7);
    size_t off = ((size_t)((r >> 6) * 8 + (kc >> 3)) << 12)
               + (size_t)row * 64 + (chunk << 3);
    *(uint4*)(g_Wh + off) = make_uint4(hw[0], hw[1], hw[2], hw[3]);
    *(uint4*)(g_Wl + off) = make_uint4(lw[0], lw[1], lw[2], lw[3]);
}

// ---------------------------------------------------------------------------
// Kernel 3a: local S4D scan over one chunk (zero initial state).
// 16 lanes per d, 2 f32x2 complex pairs per lane. Block = 8 d of one (b,c).
// ---------------------------------------------------------------------------
__global__ void scan_local(const float* __restrict__ A_real,
                           const float* __restrict__ A_imag,
                           const float* __restrict__ Cp,
                           const float* __restrict__ log_dt,
                           const float* __restrict__ B_ssm,
                           const float* __restrict__ D_skip) {
    const int t = threadIdx.x;
    const int grp = t >> 4;
    const int g = t & 15;
    const int blk = blockIdx.x;
    const int c = blk & 7;
    const int rest = blk >> 3;
    const int gid = rest * 8 + grp;
    const int b = gid >> 9;
    const int d = gid & 511;
    const int d0 = (rest * 8) & 511;

    const float dt = expf(log_dt[d]);
    ull Abr[2], Abi[2], nAbi[2], Ccr[2], nCci[2], s_r[2], s_i[2];
    #pragma unroll
    for (int p = 0; p < 2; p++) {
        float abr[2], abi[2], ccr[2], cci[2];
        #pragma unroll
        for (int j = 0; j < 2; j++) {
            int n = g * 4 + p * 2 + j;
            float ar = dt * A_real[d * NS + n];
            float ai = dt * A_imag[d * NS + n];
            float er = expf(ar), sb, cb;
            sincosf(ai, &sb, &cb);
            abr[j] = er * cb;
            abi[j] = er * sb;
            float bs = B_ssm[d * NS + n];
            ccr[j] = Cp[(d * NS + n) * 2 + 0] * bs;
            cci[j] = Cp[(d * NS + n) * 2 + 1] * bs;
        }
        Abr[p]  = pk2(abr[0], abr[1]);
        Abi[p]  = pk2(abi[0], abi[1]);
        nAbi[p] = pk2(-abi[0], -abi[1]);
        Ccr[p]  = pk2(ccr[0], ccr[1]);
        nCci[p] = pk2(-cci[0], -cci[1]);
        s_r[p] = 0ull; s_i[p] = 0ull;
    }
    const float dsk = D_skip[d];
    const float mult  = 1.0f + g_film[b * 2 * DM + d];
    const float shift = g_film[b * 2 * DM + DM + d];

    __shared__ float sx[2][64][8];
    __shared__ float syb[2][64][8];
    const size_t cbase = (size_t)b * LSEQ * DM + (size_t)c * TCH * DM;
    const float* xbase = g_xn + cbase + d0;
    float* ypb = g_yp + cbase + d0;

    const int ll = t >> 1, half = t & 1;
    *(float4*)&sx[0][ll][half * 4] =
        *(const float4*)(xbase + (size_t)ll * DM + half * 4);
    __syncthreads();

    for (int ch = 0; ch < TCH / 64; ch++) {
        const int cur = ch & 1;
        float4 nld;
        const bool more = (ch + 1 < TCH / 64);
        if (more) {
            nld = *(const float4*)(xbase + (size_t)((ch + 1) * 64 + ll) * DM + half * 4);
        }
        #pragma unroll 4
        for (int i = 0; i < 64; i++) {
            float xv = sx[cur][i][grp];
            ull x2 = pk2(xv, xv);
            ull acc = 0ull;
            #pragma unroll
            for (int p = 0; p < 2; p++) {
                ull t1 = fma2(nAbi[p], s_i[p], x2);
                ull nr = fma2(Abr[p], s_r[p], t1);
                ull u  = mul2(Abi[p], s_r[p]);
                ull ni = fma2(Abr[p], s_i[p], u);
                s_r[p] = nr; s_i[p] = ni;
                acc = fma2(Ccr[p], nr, acc);
                acc = fma2(nCci[p], ni, acc);
            }
            float2 ac = upk2(acc);
            float tsum = ac.x + ac.y;
            #pragma unroll
            for (int o = 8; o; o >>= 1)
                tsum += __shfl_xor_sync(0xffffffffu, tsum, o);
            if (g == 0) {
                float o = dt * tsum + dsk * xv;
                syb[cur][i][grp] = o * mult + shift;
            }
        }
        if (more) {
            *(float4*)&sx[cur ^ 1][ll][half * 4] = nld;
        }
        __syncthreads();
        {
            const int r = t >> 1, hh = t & 1;
            float4 v = *(float4*)&syb[cur][r][hh * 4];
            if (c == 0) {
                int m = b * LSEQ + ch * 64 + r;
                size_t off = a_tiled_off(m, d0 + hh * 4);
                uint2 H, L;
                pack_hl(v, H, L);
                *(uint2*)(g_y2h + off) = H;
                *(uint2*)(g_y2l + off) = L;
            } else {
                *(float4*)(ypb + (size_t)(ch * 64 + r) * DM + hh * 4) = v;
            }
        }
    }

    size_t sb = ((size_t)(b * CHK + c) * DM + d) * 32 + g * 2;
    g_str[sb + 0] = s_r[0];
    g_str[sb + 1] = s_r[1];
    g_sti[sb + 0] = s_i[0];
    g_sti[sb + 1] = s_i[1];
}

// ---------------------------------------------------------------------------
// Kernel 3b: fixup for chunks c=1..7.
// ---------------------------------------------------------------------------
__global__ void scan_fixup(const float* __restrict__ A_real,
                           const float* __restrict__ A_imag,
                           const float* __restrict__ Cp,
                           const float* __restrict__ log_dt,
                           const float* __restrict__ B_ssm) {
    const int t = threadIdx.x;
    const int grp = t >> 4;
    const int g = t & 15;
    const int blk = blockIdx.x;
    const int c = 1 + blk % 7;
    const int rest = blk / 7;
    const int gid = rest * 8 + grp;
    const int b = gid >> 9;
    const int d = gid & 511;
    const int d0 = (rest * 8) & 511;

    const float dt = expf(log_dt[d]);
    const float k = dt * (1.0f + g_film[b * 2 * DM + d]);

    ull Lr[2], Li[2], nLi[2], LTr[2], LTi[2], nLTi[2], Ccr[2], Cci[2], nCci[2];
    #pragma unroll
    for (int p = 0; p < 2; p++) {
        float lr[2], li[2], ltr[2], lti[2], ccr[2], cci[2];
        #pragma unroll
        for (int j = 0; j < 2; j++) {
            int n = g * 4 + p * 2 + j;
            float ar = dt * A_real[d * NS + n];
            float ai = dt * A_imag[d * NS + n];
            float er = expf(ar), sb, cb;
            sincosf(ai, &sb, &cb);
            lr[j] = er * cb;
            li[j] = er * sb;
            float pr = lr[j], pi = li[j];
            #pragma unroll
            for (int q = 0; q < 8; q++) {
                float nr2 = pr * pr - pi * pi;
                pi = 2.0f * pr * pi;
                pr = nr2;
            }
            ltr[j] = pr; lti[j] = pi;
            float bs = B_ssm[d * NS + n];
            ccr[j] = Cp[(d * NS + n) * 2 + 0] * bs * k;
            cci[j] = Cp[(d * NS + n) * 2 + 1] * bs * k;
        }
        Lr[p]   = pk2(lr[0], lr[1]);
        Li[p]   = pk2(li[0], li[1]);
        nLi[p]  = pk2(-li[0], -li[1]);
        LTr[p]  = pk2(ltr[0], ltr[1]);
        LTi[p]  = pk2(lti[0], lti[1]);
        nLTi[p] = pk2(-lti[0], -lti[1]);
        Ccr[p]  = pk2(ccr[0], ccr[1]);
        Cci[p]  = pk2(cci[0], cci[1]);
        nCci[p] = pk2(-cci[0], -cci[1]);
    }

    ull ar_[2] = {0ull, 0ull}, ai_[2] = {0ull, 0ull};
    size_t sb0 = ((size_t)(b * CHK) * DM + d) * 32 + g * 2;
    for (int cp = 0; cp < c; cp++) {
        size_t sb = sb0 + (size_t)cp * DM * 32;
        #pragma unroll
        for (int p = 0; p < 2; p++) {
            ull sr = g_str[sb + p];
            ull si = g_sti[sb + p];
            ull t1 = fma2(nLTi[p], ai_[p], sr);
            ull nr = fma2(LTr[p], ar_[p], t1);
            ull t2 = fma2(LTi[p], ar_[p], si);
            ull ni = fma2(LTr[p], ai_[p], t2);
            ar_[p] = nr; ai_[p] = ni;
        }
    }

    ull Wr[2], Wi[2];
    #pragma unroll
    for (int p = 0; p < 2; p++) {
        Wr[p] = fma2(Ccr[p], ar_[p], mul2(nCci[p], ai_[p]));
        Wi[p] = fma2(Ccr[p], ai_[p], mul2(Cci[p], ar_[p]));
    }

    __shared__ float syc[64][8];
    const size_t cbase = (size_t)b * LSEQ * DM + (size_t)c * TCH * DM;
    const float* ypb = g_yp + cbase + d0;

    for (int tile = 0; tile < TCH / 64; tile++) {
        #pragma unroll 4
        for (int i = 0; i < 64; i++) {
            #pragma unroll
            for (int p = 0; p < 2; p++) {
                ull t1 = mul2(nLi[p], Wi[p]);
                ull nr = fma2(Lr[p], Wr[p], t1);
                ull t2 = mul2(Li[p], Wr[p]);
                ull ni = fma2(Lr[p], Wi[p], t2);
                Wr[p] = nr; Wi[p] = ni;
            }
            ull acc = add2(Wr[0], Wr[1]);
            float2 a2 = upk2(acc);
            float tsum = a2.x + a2.y;
            #pragma unroll
            for (int o = 8; o; o >>= 1)
                tsum += __shfl_xor_sync(0xffffffffu, tsum, o);
            if (g == 0) syc[i][grp] = tsum;
        }
        __syncthreads();
        {
            const int r = t >> 1, hh = t & 1;
            size_t lrow = (size_t)(tile * 64 + r) * DM + hh * 4;
            float4 v = *(const float4*)(ypb + lrow);
            v.x += syc[r][hh * 4 + 0];
            v.y += syc[r][hh * 4 + 1];
            v.z += syc[r][hh * 4 + 2];
            v.w += syc[r][hh * 4 + 3];
            int m = b * LSEQ + c * TCH + tile * 64 + r;
            size_t off = a_tiled_off(m, d0 + hh * 4);
            uint2 H, L;
            pack_hl(v, H, L);
            *(uint2*)(g_y2h + off) = H;
            *(uint2*)(g_y2l + off) = L;
        }
        __syncthreads();
    }
}

// ---------------------------------------------------------------------------
// Kernel 4: out_proj GEMM, mma.sync bf16 3-pass, block tile 64m x 128n
// (64 a-cols || 64 g-cols), BK=64, bulk-copy 2-stage pipe, 2 CTAs/SM.
// Stage layout (48KB): AH 0, AL 8K, BH 16K (64a+64g rows), BL 32K.
// ---------------------------------------------------------------------------
#define GSTG 49152
#define NSTG 2
#define GSM_BYTES (NSTG * GSTG)

__device__ __forceinline__ void mma_bf16(float d[4], const uint32_t a[4],
                                         const uint32_t b0, const uint32_t b1) {
    asm volatile(
        "mma.sync.aligned.m16n8k16.row.col.f32.bf16.bf16.f32 "
        "{%0,%1,%2,%3}, {%4,%5,%6,%7}, {%8,%9}, {%0,%1,%2,%3};\n"
        : "+f"(d[0]), "+f"(d[1]), "+f"(d[2]), "+f"(d[3])
        : "r"(a[0]), "r"(a[1]), "r"(a[2]), "r"(a[3]), "r"(b0), "r"(b1));
}
__device__ __forceinline__ void ldsm4(uint32_t* r, uint32_t byteaddr) {
    asm volatile("ldmatrix.sync.aligned.m8n8.x4.shared.b16 {%0,%1,%2,%3}, [%4];"
        : "=r"(r[0]), "=r"(r[1]), "=r"(r[2]), "=r"(r[3]) : "r"(byteaddr));
}

__global__ void __launch_bounds__(256, 2)
gemm_glu_tc(const float* __restrict__ bo,
            const float* __restrict__ resid,
            float* __restrict__ out) {
    extern __shared__ __align__(1024) char smb[];
    __shared__ uint64_t mbar_store[2 * NSTG];
    const uint32_t sbs = (uint32_t)__cvta_generic_to_shared(smb);
    const uint32_t mb = (uint32_t)__cvta_generic_to_shared(mbar_store);

    const int tid = threadIdx.x;
    const int mblk = blockIdx.x;          // m0 = mblk*64
    const int cblk = blockIdx.y;          // c0 = cblk*64
    const int m0 = mblk * 64;
    const int c0 = cblk * 64;
    const int warp = tid >> 5, lane = tid & 31;
    const int wm = warp >> 2;             // 0..1 (m)
    const int wn = warp & 3;              // 0..3 (n over 128 cols)
    const int grp = lane >> 2, tig = lane & 3;

    if (tid == 0) {
        #pragma unroll
        for (int s = 0; s < NSTG; s++) {
            mbar_init(mb + s * 8, 1);             // full (tx-based)
            mbar_init(mb + (NSTG + s) * 8, 256);  // empty (all threads)
        }
    }
    __syncthreads();

    const size_t mtile = mblk >> 1;
    const size_t ahalf = (size_t)(mblk & 1) * 8192;   // byte slice within A tile

    auto issue_stage = [&](int it) {
        int s = it & 1;
        uint32_t full = mb + s * 8;
        mbar_expect_tx(full, GSTG);
        uint32_t st = sbs + s * GSTG;
        bulk_cp(st,         (const char*)g_y2h + ((mtile * 8 + it) << 14) + ahalf, 8192, full);
        bulk_cp(st + 8192,  (const char*)g_y2l + ((mtile * 8 + it) << 14) + ahalf, 8192, full);
        bulk_cp(st + 16384, (const char*)g_Wh + (((size_t)cblk * 8 + it) << 13), 8192, full);
        bulk_cp(st + 24576, (const char*)g_Wh + (((size_t)(8 + cblk) * 8 + it) << 13), 8192, full);
        bulk_cp(st + 32768, (const char*)g_Wl + (((size_t)cblk * 8 + it) << 13), 8192, full);
        bulk_cp(st + 40960, (const char*)g_Wl + (((size_t)(8 + cblk) * 8 + it) << 13), 8192, full);
    };

    if (tid == 0) {
        issue_stage(0);
        issue_stage(1);
    }

    float dacc[2][4][4];
    #pragma unroll
    for (int mt = 0; mt < 2; mt++)
        #pragma unroll
        for (int nt = 0; nt < 4; nt++)
            #pragma unroll
            for (int r = 0; r < 4; r++) dacc[mt][nt][r] = 0.0f;

    // LDSM per-lane params (identical addressing scheme to round 6, proven)
    const int rowA0 = wm * 32 + (lane & 15);
    const int chA0 = lane >> 4;
    const int rowB0 = wn * 32 + ((lane & 16) >> 1) + (lane & 7);
    const int chB0 = (lane >> 3) & 1;

    const int NKT = 8;   // 512 / 64
    for (int it = 0; it < NKT; it++) {
        const int s = it & 1;
        const int q = it >> 1;
        mbar_wait(mb + s * 8, q & 1);
        const uint32_t st = sbs + s * GSTG;

        #pragma unroll
        for (int kk = 0; kk < 4; kk++) {
            uint32_t ah[2][4], al[2][4];
            #pragma unroll
            for (int mt = 0; mt < 2; mt++) {
                int rowA = rowA0 + mt * 16;
                int ch = (2 * kk + chA0) ^ (rowA & 7);
                uint32_t ad = st + (uint32_t)(rowA * 128 + ch * 16);
                ldsm4(ah[mt], ad);
                ldsm4(al[mt], ad + 8192);
            }
            uint32_t bh[8], bl[8];
            #pragma unroll
            for (int go = 0; go < 2; go++) {
                int rr = rowB0 + go * 16;
                int cs = (2 * kk + chB0) ^ (rr & 7);
                uint32_t bd = st + 16384 + (uint32_t)(rr * 128 + cs * 16);
                ldsm4(&bh[go * 4], bd);
                ldsm4(&bl[go * 4], bd + 16384);
            }
            #pragma unroll
            for (int mt = 0; mt < 2; mt++)
                #pragma unroll
                for (int nt = 0; nt < 4; nt++) {
                    mma_bf16(dacc[mt][nt], ah[mt], bh[nt * 2], bh[nt * 2 + 1]);
                    mma_bf16(dacc[mt][nt], ah[mt], bl[nt * 2], bl[nt * 2 + 1]);
                    mma_bf16(dacc[mt][nt], al[mt], bh[nt * 2], bh[nt * 2 + 1]);
                }
        }

        mbar_arrive(mb + (NSTG + s) * 8);
        if (tid == 0 && it + NSTG < NKT) {
            mbar_wait(mb + (NSTG + s) * 8, q & 1);
            issue_stage(it + NSTG);
        }
    }

    // ---- epilogue: GLU + residual ----
    __syncthreads();                 // pipeline smem free for reuse
    float* sig = (float*)smb;        // [64][68] padded

    if (wn >= 2) {                   // g-gate warps (cols 64..127)
        #pragma unroll
        for (int mt = 0; mt < 2; mt++) {
            #pragma unroll
            for (int nt = 0; nt < 4; nt++) {
                int gcol = (wn - 2) * 32 + nt * 8 + tig * 2;
                float bg0 = bo[DM + c0 + gcol];
                float bg1 = bo[DM + c0 + gcol + 1];
                #pragma unroll
                for (int half = 0; half < 2; half++) {
                    int ml = wm * 32 + mt * 16 + grp + half * 8;
                    float g0 = dacc[mt][nt][half * 2 + 0] + bg0;
                    float g1 = dacc[mt][nt][half * 2 + 1] + bg1;
                    sig[ml * 68 + gcol]     = 1.0f / (1.0f + expf(-g0));
                    sig[ml * 68 + gcol + 1] = 1.0f / (1.0f + expf(-g1));
                }
            }
        }
    }
    __syncthreads();
    if (wn < 2) {                    // a-gate warps (cols 0..63)
        #pragma unroll
        for (int mt = 0; mt < 2; mt++) {
            #pragma unroll
            for (int nt = 0; nt < 4; nt++) {
                int col = wn * 32 + nt * 8 + tig * 2;
                float ba0 = bo[c0 + col];
                float ba1 = bo[c0 + col + 1];
                #pragma unroll
                for (int half = 0; half < 2; half++) {
                    int ml = wm * 32 + mt * 16 + grp + half * 8;
                    int r = m0 + ml;
                    float a0 = dacc[mt][nt][half * 2 + 0] + ba0;
                    float a1 = dacc[mt][nt][half * 2 + 1] + ba1;
                    float s0 = sig[ml * 68 + col];
                    float s1 = sig[ml * 68 + col + 1];
                    float2 res = *(const float2*)(resid + (size_t)r * DM + c0 + col);
                    float2 o;
                    o.x = res.x + a0 * s0;
                    o.y = res.y + a1 * s1;
                    *(float2*)(out + (size_t)r * DM + c0 + col) = o;
                }
            }
        }
    }
}

// ---------------------------------------------------------------------------
extern "C" void kernel_launch(void* const* d_in, const int* in_sizes, int n_in,
                              void* d_out, int out_size) {
    const float* x      = (const float*)d_in[0];
    const float* emb    = (const float*)d_in[1];
    const float* A_real = (const float*)d_in[2];
    const float* A_imag = (const float*)d_in[3];
    const float* C      = (const float*)d_in[4];
    const float* log_dt = (const float*)d_in[5];
    const float* B_ssm  = (const float*)d_in[6];
    const float* D_skip = (const float*)d_in[7];
    const float* ln_g   = (const float*)d_in[8];
    const float* ln_b   = (const float*)d_in[9];
    const float* W_out  = (const float*)d_in[10];
    const float* b_out  = (const float*)d_in[11];
    const float* W_film = (const float*)d_in[12];
    const float* b_film = (const float*)d_in[13];
    float* out = (float*)d_out;

    static bool configured = false;
    if (!configured) {
        cudaFuncSetAttribute(gemm_glu_tc,
                             cudaFuncAttributeMaxDynamicSharedMemorySize,
                             GSM_BYTES);
        configured = true;
    }

    ln_kernel<<<BSZ * LSEQ, 128>>>(x, ln_g, ln_b);
    film_kernel<<<BSZ, 256>>>(emb, W_film, b_film);
    prep_w<<<256, 256>>>(W_out);
    scan_local<<<BSZ * (DM / 8) * CHK, 128>>>(A_real, A_imag, C, log_dt, B_ssm, D_skip);
    scan_fixup<<<BSZ * (DM / 8) * (CHK - 1), 128>>>(A_real, A_imag, C, log_dt, B_ssm);
    gemm_glu_tc<<<dim3((BSZ * LSEQ) / 64, DM / 64), 256, GSM_BYTES>>>(b_out, x, out);
}

// round 9
// speedup vs baseline: 1.5205x; 1.1171x over previous
#include <cuda_runtime.h>
#include <cuda_fp16.h>
#include <math.h>
#include <stdint.h>

#define BSZ 8
#define LSEQ 2048
#define DM 512
#define NS 64
#define EMB 512
#define CHK 8
#define TCH 256   // LSEQ / CHK

typedef unsigned long long ull;

// Scratch (allocation-free rule: __device__ globals)
// g_y2h/l and g_Wh stored PRE-TILED + PRE-SWIZZLED (SW128-equivalent), fp16:
//   A tiles: [m/128][k/64] tiles of 128x64, rows 128B, chunk ^= row&7
//   W tiles: [r/64][k/64]  tiles of  64x64, same swizzle
__device__ __align__(1024) float g_xn[BSZ * LSEQ * DM];
__device__ __align__(1024) float g_yp[BSZ * LSEQ * DM];
__device__ __align__(1024) unsigned short g_y2h[BSZ * LSEQ * DM];
__device__ __align__(1024) unsigned short g_y2l[BSZ * LSEQ * DM];
__device__ __align__(1024) unsigned short g_Wh[2 * DM * DM];
__device__ float g_film[BSZ * 2 * DM];
__device__ ull g_str[BSZ * CHK * DM * 32];
__device__ ull g_sti[BSZ * CHK * DM * 32];

// tiled+swizzled element offset into A-layout arrays (y2 h/l)
__device__ __forceinline__ size_t a_tiled_off(int m, int d) {
    int row = m & 127;
    int chunk = ((d & 63) >> 3) ^ (row & 7);
    return ((size_t)((m >> 7) * 8 + (d >> 6)) << 13)
         + (size_t)row * 64 + (chunk << 3) + (d & 7);
}

// ---------------------------------------------------------------------------
// f32x2 packed-math helpers
// ---------------------------------------------------------------------------
__device__ __forceinline__ ull pk2(float a, float b) {
    ull r; asm("mov.b64 %0, {%1, %2};" : "=l"(r) : "f"(a), "f"(b)); return r;
}
__device__ __forceinline__ float2 upk2(ull v) {
    float2 f; asm("mov.b64 {%0, %1}, %2;" : "=f"(f.x), "=f"(f.y) : "l"(v)); return f;
}
__device__ __forceinline__ ull fma2(ull a, ull b, ull c) {
    ull d; asm("fma.rn.f32x2 %0, %1, %2, %3;" : "=l"(d) : "l"(a), "l"(b), "l"(c)); return d;
}
__device__ __forceinline__ ull mul2(ull a, ull b) {
    ull d; asm("mul.rn.f32x2 %0, %1, %2;" : "=l"(d) : "l"(a), "l"(b)); return d;
}
__device__ __forceinline__ ull add2(ull a, ull b) {
    ull d; asm("add.rn.f32x2 %0, %1, %2;" : "=l"(d) : "l"(a), "l"(b)); return d;
}

// pack 4 floats into fp16 hi / lo splits (uint2 each)
__device__ __forceinline__ void pack_hl(float4 v, uint2& H, uint2& L) {
    unsigned short h[4], l[4];
    float e[4] = {v.x, v.y, v.z, v.w};
    #pragma unroll
    for (int j = 0; j < 4; j++) {
        __half hb = __float2half_rn(e[j]);
        float r = e[j] - __half2float(hb);
        h[j] = __half_as_ushort(hb);
        l[j] = __half_as_ushort(__float2half_rn(r));
    }
    H.x = (uint32_t)h[0] | ((uint32_t)h[1] << 16);
    H.y = (uint32_t)h[2] | ((uint32_t)h[3] << 16);
    L.x = (uint32_t)l[0] | ((uint32_t)l[1] << 16);
    L.y = (uint32_t)l[2] | ((uint32_t)l[3] << 16);
}

// mbarrier helpers
__device__ __forceinline__ void mbar_init(uint32_t a, uint32_t cnt) {
    asm volatile("mbarrier.init.shared.b64 [%0], %1;" :: "r"(a), "r"(cnt) : "memory");
}
__device__ __forceinline__ void mbar_expect_tx(uint32_t a, uint32_t tx) {
    asm volatile("mbarrier.arrive.expect_tx.shared.b64 _, [%0], %1;" :: "r"(a), "r"(tx) : "memory");
}
__device__ __forceinline__ void mbar_arrive(uint32_t a) {
    asm volatile("mbarrier.arrive.shared.b64 _, [%0];" :: "r"(a) : "memory");
}
__device__ __forceinline__ void mbar_wait(uint32_t a, int parity) {
    asm volatile(
        "{\n\t.reg .pred P;\n"
        "LW_%=:\n\t"
        "mbarrier.try_wait.parity.acquire.cta.shared::cta.b64 P, [%0], %1, 0x989680;\n\t"
        "@P bra.uni LD_%=;\n\t"
        "bra.uni LW_%=;\n"
        "LD_%=:\n\t}"
        :: "r"(a), "r"(parity) : "memory");
}
__device__ __forceinline__ void bulk_cp(uint32_t dst, const void* src,
                                        uint32_t bytes, uint32_t mbar) {
    asm volatile(
        "cp.async.bulk.shared::cta.global.mbarrier::complete_tx::bytes [%0], [%1], %2, [%3];"
        :: "r"(dst), "l"(src), "r"(bytes), "r"(mbar) : "memory");
}

// ---------------------------------------------------------------------------
// Kernel 1: LayerNorm
// ---------------------------------------------------------------------------
__global__ void ln_kernel(const float* __restrict__ x,
                          const float* __restrict__ gamma,
                          const float* __restrict__ beta) {
    const int row = blockIdx.x;
    const int t = threadIdx.x;
    const float4* xr = (const float4*)(x + (size_t)row * DM);
    float4 v = xr[t];
    float s  = v.x + v.y + v.z + v.w;
    float ss = v.x * v.x + v.y * v.y + v.z * v.z + v.w * v.w;

    __shared__ float sh[8];
    #pragma unroll
    for (int o = 16; o; o >>= 1) {
        s  += __shfl_xor_sync(0xffffffffu, s, o);
        ss += __shfl_xor_sync(0xffffffffu, ss, o);
    }
    int w = t >> 5;
    if ((t & 31) == 0) { sh[w] = s; sh[4 + w] = ss; }
    __syncthreads();
    float S  = sh[0] + sh[1] + sh[2] + sh[3];
    float SS = sh[4] + sh[5] + sh[6] + sh[7];

    const float inv = 1.0f / (float)DM;
    float mu = S * inv;
    float var = SS * inv - mu * mu;
    float rs = rsqrtf(var + 1e-5f);

    float4 g4 = ((const float4*)gamma)[t];
    float4 b4 = ((const float4*)beta)[t];
    float4 o4;
    o4.x = (v.x - mu) * rs * g4.x + b4.x;
    o4.y = (v.y - mu) * rs * g4.y + b4.y;
    o4.z = (v.z - mu) * rs * g4.z + b4.z;
    o4.w = (v.w - mu) * rs * g4.w + b4.w;
    ((float4*)(g_xn + (size_t)row * DM))[t] = o4;
}

// ---------------------------------------------------------------------------
// Kernel 2: FiLM params
// ---------------------------------------------------------------------------
__global__ void film_kernel(const float* __restrict__ emb,
                            const float* __restrict__ Wf,
                            const float* __restrict__ bf) {
    __shared__ float se[EMB];
    const int b = blockIdx.x;
    for (int i = threadIdx.x; i < EMB; i += blockDim.x) {
        float e = emb[b * EMB + i];
        se[i] = e / (1.0f + expf(-e));
    }
    __syncthreads();
    for (int j = threadIdx.x; j < 2 * DM; j += blockDim.x) {
        const float4* wr = (const float4*)(Wf + (size_t)j * EMB);
        const float4* sr = (const float4*)se;
        float acc = bf[j];
        #pragma unroll 4
        for (int q = 0; q < EMB / 4; q++) {
            float4 w = wr[q], sv = sr[q];
            acc += w.x * sv.x + w.y * sv.y + w.z * sv.z + w.w * sv.w;
        }
        g_film[b * 2 * DM + j] = acc;
    }
}

// ---------------------------------------------------------------------------
// Kernel 2b: W -> fp16 hi only, TILED (64x64 tiles, swizzled 128B rows)
// ---------------------------------------------------------------------------
__global__ void prep_w(const float* __restrict__ W) {
    int i = blockIdx.x * blockDim.x + threadIdx.x;   // 0 .. 65535
    int r = i >> 6;
    int kc = i & 63;
    const float* src = W + (size_t)r * DM + kc * 8;
    float4 v0 = *(const float4*)src;
    float4 v1 = *(const float4*)(src + 4);
    float e[8] = {v0.x, v0.y, v0.z, v0.w, v1.x, v1.y, v1.z, v1.w};
    uint32_t hw[4];
    #pragma unroll
    for (int j = 0; j < 4; j++) {
        unsigned short h0 = __half_as_ushort(__float2half_rn(e[j * 2]));
        unsigned short h1 = __half_as_ushort(__float2half_rn(e[j * 2 + 1]));
        hw[j] = (uint32_t)h0 | ((uint32_t)h1 << 16);
    }
    int row = r & 63;
    int chunk = (kc & 7) ^ (row & 7);
    size_t off = ((size_t)((r >> 6) * 8 + (kc >> 3)) << 12)
               + (size_t)row * 64 + (chunk << 3);
    *(uint4*)(g_Wh + off) = make_uint4(hw[0], hw[1], hw[2], hw[3]);
}

// ---------------------------------------------------------------------------
// Kernel 3a: local S4D scan over one chunk (zero initial state).
// 8 lanes per d, 4 f32x2 complex pairs per lane. Block = 16 d of one (b,c).
// ---------------------------------------------------------------------------
__global__ void __launch_bounds__(128)
scan_local(const float* __restrict__ A_real,
           const float* __restrict__ A_imag,
           const float* __restrict__ Cp,
           const float* __restrict__ log_dt,
           const float* __restrict__ B_ssm,
           const float* __restrict__ D_skip) {
    const int t = threadIdx.x;
    const int myd = t >> 3;           // 0..15
    const int g = t & 7;
    const int blk = blockIdx.x;
    const int c = blk & 7;
    const int rest = blk >> 3;        // 0..255
    const int gid = rest * 16 + myd;
    const int b = gid >> 9;
    const int d = gid & 511;
    const int d0 = (rest * 16) & 511;

    const float dt = expf(log_dt[d]);
    ull Abr[4], Abi[4], nAbi[4], Ccr[4], nCci[4], s_r[4], s_i[4];
    #pragma unroll
    for (int p = 0; p < 4; p++) {
        float abr[2], abi[2], ccr[2], cci[2];
        #pragma unroll
        for (int j = 0; j < 2; j++) {
            int n = g * 8 + p * 2 + j;
            float ar = dt * A_real[d * NS + n];
            float ai = dt * A_imag[d * NS + n];
            float er = expf(ar), sb, cb;
            sincosf(ai, &sb, &cb);
            abr[j] = er * cb;
            abi[j] = er * sb;
            float bs = B_ssm[d * NS + n];
            ccr[j] = Cp[(d * NS + n) * 2 + 0] * bs;
            cci[j] = Cp[(d * NS + n) * 2 + 1] * bs;
        }
        Abr[p]  = pk2(abr[0], abr[1]);
        Abi[p]  = pk2(abi[0], abi[1]);
        nAbi[p] = pk2(-abi[0], -abi[1]);
        Ccr[p]  = pk2(ccr[0], ccr[1]);
        nCci[p] = pk2(-cci[0], -cci[1]);
        s_r[p] = 0ull; s_i[p] = 0ull;
    }
    const float dsk = D_skip[d];
    const float mult  = 1.0f + g_film[b * 2 * DM + d];
    const float shift = g_film[b * 2 * DM + DM + d];

    __shared__ float sx[2][64][16];
    __shared__ float syb[2][64][16];
    const size_t cbase = (size_t)b * LSEQ * DM + (size_t)c * TCH * DM;
    const float* xbase = g_xn + cbase + d0;
    float* ypb = g_yp + cbase + d0;

    // load mapping: 64 rows x 4 float4 = 256 float4, 2 per thread
    const int l0 = t >> 2, q0 = t & 3;
    const int l1 = (t + 128) >> 2;

    *(float4*)&sx[0][l0][q0 * 4] = *(const float4*)(xbase + (size_t)l0 * DM + q0 * 4);
    *(float4*)&sx[0][l1][q0 * 4] = *(const float4*)(xbase + (size_t)l1 * DM + q0 * 4);
    __syncthreads();

    for (int ch = 0; ch < TCH / 64; ch++) {
        const int cur = ch & 1;
        float4 nld0, nld1;
        const bool more = (ch + 1 < TCH / 64);
        if (more) {
            const float* nb = xbase + (size_t)(ch + 1) * 64 * DM;
            nld0 = *(const float4*)(nb + (size_t)l0 * DM + q0 * 4);
            nld1 = *(const float4*)(nb + (size_t)l1 * DM + q0 * 4);
        }
        #pragma unroll 4
        for (int i = 0; i < 64; i++) {
            float xv = sx[cur][i][myd];
            ull x2 = pk2(xv, xv);
            ull acc = 0ull;
            #pragma unroll
            for (int p = 0; p < 4; p++) {
                ull t1 = fma2(nAbi[p], s_i[p], x2);
                ull nr = fma2(Abr[p], s_r[p], t1);
                ull u  = mul2(Abi[p], s_r[p]);
                ull ni = fma2(Abr[p], s_i[p], u);
                s_r[p] = nr; s_i[p] = ni;
                acc = fma2(Ccr[p], nr, acc);
                acc = fma2(nCci[p], ni, acc);
            }
            float2 ac = upk2(acc);
            float tsum = ac.x + ac.y;
            tsum += __shfl_xor_sync(0xffffffffu, tsum, 4);
            tsum += __shfl_xor_sync(0xffffffffu, tsum, 2);
            tsum += __shfl_xor_sync(0xffffffffu, tsum, 1);
            if (g == 0) {
                float o = dt * tsum + dsk * xv;
                syb[cur][i][myd] = o * mult + shift;
            }
        }
        if (more) {
            *(float4*)&sx[cur ^ 1][l0][q0 * 4] = nld0;
            *(float4*)&sx[cur ^ 1][l1][q0 * 4] = nld1;
        }
        __syncthreads();
        // vectorized store stage: 2 float4 per thread
        #pragma unroll
        for (int pass = 0; pass < 2; pass++) {
            int r = pass ? l1 : l0;
            float4 v = *(float4*)&syb[cur][r][q0 * 4];
            if (c == 0) {
                int m = b * LSEQ + ch * 64 + r;
                size_t off = a_tiled_off(m, d0 + q0 * 4);
                uint2 H, L;
                pack_hl(v, H, L);
                *(uint2*)(g_y2h + off) = H;
                *(uint2*)(g_y2l + off) = L;
            } else {
                *(float4*)(ypb + (size_t)(ch * 64 + r) * DM + q0 * 4) = v;
            }
        }
    }

    // dump end states at canonical pair slots (pair = n>>1 = g*4+p)
    size_t sb = ((size_t)(b * CHK + c) * DM + d) * 32 + g * 4;
    #pragma unroll
    for (int p = 0; p < 4; p++) {
        g_str[sb + p] = s_r[p];
        g_sti[sb + p] = s_i[p];
    }
}

// ---------------------------------------------------------------------------
// Kernel 3b: fixup for chunks c=1..7 (16 lanes per d, canonical pair slots).
// ---------------------------------------------------------------------------
__global__ void scan_fixup(const float* __restrict__ A_real,
                           const float* __restrict__ A_imag,
                           const float* __restrict__ Cp,
                           const float* __restrict__ log_dt,
                           const float* __restrict__ B_ssm) {
    const int t = threadIdx.x;
    const int grp = t >> 4;
    const int g = t & 15;
    const int blk = blockIdx.x;
    const int c = 1 + blk % 7;
    const int rest = blk / 7;
    const int gid = rest * 8 + grp;
    const int b = gid >> 9;
    const int d = gid & 511;
    const int d0 = (rest * 8) & 511;

    const float dt = expf(log_dt[d]);
    const float k = dt * (1.0f + g_film[b * 2 * DM + d]);

    ull Lr[2], Li[2], nLi[2], LTr[2], LTi[2], nLTi[2], Ccr[2], Cci[2], nCci[2];
    #pragma unroll
    for (int p = 0; p < 2; p++) {
        float lr[2], li[2], ltr[2], lti[2], ccr[2], cci[2];
        #pragma unroll
        for (int j = 0; j < 2; j++) {
            int n = g * 4 + p * 2 + j;
            float ar = dt * A_real[d * NS + n];
            float ai = dt * A_imag[d * NS + n];
            float er = expf(ar), sb, cb;
            sincosf(ai, &sb, &cb);
            lr[j] = er * cb;
            li[j] = er * sb;
            float pr = lr[j], pi = li[j];
            #pragma unroll
            for (int q = 0; q < 8; q++) {
                float nr2 = pr * pr - pi * pi;
                pi = 2.0f * pr * pi;
                pr = nr2;
            }
            ltr[j] = pr; lti[j] = pi;
            float bs = B_ssm[d * NS + n];
            ccr[j] = Cp[(d * NS + n) * 2 + 0] * bs * k;
            cci[j] = Cp[(d * NS + n) * 2 + 1] * bs * k;
        }
        Lr[p]   = pk2(lr[0], lr[1]);
        Li[p]   = pk2(li[0], li[1]);
        nLi[p]  = pk2(-li[0], -li[1]);
        LTr[p]  = pk2(ltr[0], ltr[1]);
        LTi[p]  = pk2(lti[0], lti[1]);
        nLTi[p] = pk2(-lti[0], -lti[1]);
        Ccr[p]  = pk2(ccr[0], ccr[1]);
        Cci[p]  = pk2(cci[0], cci[1]);
        nCci[p] = pk2(-cci[0], -cci[1]);
    }

    // combine local end-states (ascending Horner); pair slot = g*2 + p
    ull ar_[2] = {0ull, 0ull}, ai_[2] = {0ull, 0ull};
    size_t sb0 = ((size_t)(b * CHK) * DM + d) * 32 + g * 2;
    for (int cp = 0; cp < c; cp++) {
        size_t sb = sb0 + (size_t)cp * DM * 32;
        #pragma unroll
        for (int p = 0; p < 2; p++) {
            ull sr = g_str[sb + p];
            ull si = g_sti[sb + p];
            ull t1 = fma2(nLTi[p], ai_[p], sr);
            ull nr = fma2(LTr[p], ar_[p], t1);
            ull t2 = fma2(LTi[p], ar_[p], si);
            ull ni = fma2(LTr[p], ai_[p], t2);
            ar_[p] = nr; ai_[p] = ni;
        }
    }

    ull Wr[2], Wi[2];
    #pragma unroll
    for (int p = 0; p < 2; p++) {
        Wr[p] = fma2(Ccr[p], ar_[p], mul2(nCci[p], ai_[p]));
        Wi[p] = fma2(Ccr[p], ai_[p], mul2(Cci[p], ar_[p]));
    }

    __shared__ float syc[64][8];
    const size_t cbase = (size_t)b * LSEQ * DM + (size_t)c * TCH * DM;
    const float* ypb = g_yp + cbase + d0;

    for (int tile = 0; tile < TCH / 64; tile++) {
        #pragma unroll 4
        for (int i = 0; i < 64; i++) {
            #pragma unroll
            for (int p = 0; p < 2; p++) {
                ull t1 = mul2(nLi[p], Wi[p]);
                ull nr = fma2(Lr[p], Wr[p], t1);
                ull t2 = mul2(Li[p], Wr[p]);
                ull ni = fma2(Lr[p], Wi[p], t2);
                Wr[p] = nr; Wi[p] = ni;
            }
            ull acc = add2(Wr[0], Wr[1]);
            float2 a2 = upk2(acc);
            float tsum = a2.x + a2.y;
            #pragma unroll
            for (int o = 8; o; o >>= 1)
                tsum += __shfl_xor_sync(0xffffffffu, tsum, o);
            if (g == 0) syc[i][grp] = tsum;
        }
        __syncthreads();
        {
            const int r = t >> 1, hh = t & 1;
            size_t lrow = (size_t)(tile * 64 + r) * DM + hh * 4;
            float4 v = *(const float4*)(ypb + lrow);
            v.x += syc[r][hh * 4 + 0];
            v.y += syc[r][hh * 4 + 1];
            v.z += syc[r][hh * 4 + 2];
            v.w += syc[r][hh * 4 + 3];
            int m = b * LSEQ + c * TCH + tile * 64 + r;
            size_t off = a_tiled_off(m, d0 + hh * 4);
            uint2 H, L;
            pack_hl(v, H, L);
            *(uint2*)(g_y2h + off) = H;
            *(uint2*)(g_y2l + off) = L;
        }
        __syncthreads();
    }
}

// ---------------------------------------------------------------------------
// Kernel 4: out_proj GEMM, mma.sync f16 2-pass (exact A split, W fp16),
// block tile 64m x 128n (64 a-cols || 64 g-cols), BK=64, bulk-copy 2-stage.
// Stage (32KB): AH 0, AL 8K, BH 16K (64 a-rows + 64 g-rows).
// ---------------------------------------------------------------------------
#define GSTG 32768
#define NSTG 2
#define GSM_BYTES (NSTG * GSTG)

__device__ __forceinline__ void mma_f16(float d[4], const uint32_t a[4],
                                        const uint32_t b0, const uint32_t b1) {
    asm volatile(
        "mma.sync.aligned.m16n8k16.row.col.f32.f16.f16.f32 "
        "{%0,%1,%2,%3}, {%4,%5,%6,%7}, {%8,%9}, {%0,%1,%2,%3};\n"
        : "+f"(d[0]), "+f"(d[1]), "+f"(d[2]), "+f"(d[3])
        : "r"(a[0]), "r"(a[1]), "r"(a[2]), "r"(a[3]), "r"(b0), "r"(b1));
}
__device__ __forceinline__ void ldsm4(uint32_t* r, uint32_t byteaddr) {
    asm volatile("ldmatrix.sync.aligned.m8n8.x4.shared.b16 {%0,%1,%2,%3}, [%4];"
        : "=r"(r[0]), "=r"(r[1]), "=r"(r[2]), "=r"(r[3]) : "r"(byteaddr));
}

__global__ void __launch_bounds__(256, 2)
gemm_glu_tc(const float* __restrict__ bo,
            const float* __restrict__ resid,
            float* __restrict__ out) {
    extern __shared__ __align__(1024) char smb[];
    __shared__ uint64_t mbar_store[2 * NSTG];
    const uint32_t sbs = (uint32_t)__cvta_generic_to_shared(smb);
    const uint32_t mb = (uint32_t)__cvta_generic_to_shared(mbar_store);

    const int tid = threadIdx.x;
    const int mblk = blockIdx.x;          // m0 = mblk*64
    const int cblk = blockIdx.y;          // c0 = cblk*64
    const int m0 = mblk * 64;
    const int c0 = cblk * 64;
    const int warp = tid >> 5, lane = tid & 31;
    const int wm = warp >> 2;             // 0..1 (m)
    const int wn = warp & 3;              // 0..3 (n over 128 cols)
    const int grp = lane >> 2, tig = lane & 3;

    if (tid == 0) {
        #pragma unroll
        for (int s = 0; s < NSTG; s++) {
            mbar_init(mb + s * 8, 1);             // full (tx-based)
            mbar_init(mb + (NSTG + s) * 8, 256);  // empty (all threads)
        }
    }
    __syncthreads();

    const size_t mtile = mblk >> 1;
    const size_t ahalf = (size_t)(mblk & 1) * 8192;   // byte slice within A tile

    auto issue_stage = [&](int it) {
        int s = it & 1;
        uint32_t full = mb + s * 8;
        mbar_expect_tx(full, GSTG);
        uint32_t st = sbs + s * GSTG;
        bulk_cp(st,         (const char*)g_y2h + ((mtile * 8 + it) << 14) + ahalf, 8192, full);
        bulk_cp(st + 8192,  (const char*)g_y2l + ((mtile * 8 + it) << 14) + ahalf, 8192, full);
        bulk_cp(st + 16384, (const char*)g_Wh + (((size_t)cblk * 8 + it) << 13), 8192, full);
        bulk_cp(st + 24576, (const char*)g_Wh + (((size_t)(8 + cblk) * 8 + it) << 13), 8192, full);
    };

    if (tid == 0) {
        issue_stage(0);
        issue_stage(1);
    }

    float dacc[2][4][4];
    #pragma unroll
    for (int mt = 0; mt < 2; mt++)
        #pragma unroll
        for (int nt = 0; nt < 4; nt++)
            #pragma unroll
            for (int r = 0; r < 4; r++) dacc[mt][nt][r] = 0.0f;

    const int rowA0 = wm * 32 + (lane & 15);
    const int chA0 = lane >> 4;
    const int rowB0 = wn * 32 + ((lane & 16) >> 1) + (lane & 7);
    const int chB0 = (lane >> 3) & 1;

    const int NKT = 8;   // 512 / 64
    for (int it = 0; it < NKT; it++) {
        const int s = it & 1;
        const int q = it >> 1;
        mbar_wait(mb + s * 8, q & 1);
        const uint32_t st = sbs + s * GSTG;

        #pragma unroll
        for (int kk = 0; kk < 4; kk++) {
            uint32_t ah[2][4], al[2][4];
            #pragma unroll
            for (int mt = 0; mt < 2; mt++) {
                int rowA = rowA0 + mt * 16;
                int ch = (2 * kk + chA0) ^ (rowA & 7);
                uint32_t ad = st + (uint32_t)(rowA * 128 + ch * 16);
                ldsm4(ah[mt], ad);
                ldsm4(al[mt], ad + 8192);
            }
            uint32_t bh[8];
            #pragma unroll
            for (int go = 0; go < 2; go++) {
                int rr = rowB0 + go * 16;
                int cs = (2 * kk + chB0) ^ (rr & 7);
                uint32_t bd = st + 16384 + (uint32_t)(rr * 128 + cs * 16);
                ldsm4(&bh[go * 4], bd);
            }
            #pragma unroll
            for (int mt = 0; mt < 2; mt++)
                #pragma unroll
                for (int nt = 0; nt < 4; nt++) {
                    mma_f16(dacc[mt][nt], ah[mt], bh[nt * 2], bh[nt * 2 + 1]);
                    mma_f16(dacc[mt][nt], al[mt], bh[nt * 2], bh[nt * 2 + 1]);
                }
        }

        mbar_arrive(mb + (NSTG + s) * 8);
        if (tid == 0 && it + NSTG < NKT) {
            mbar_wait(mb + (NSTG + s) * 8, q & 1);
            issue_stage(it + NSTG);
        }
    }

    // ---- epilogue: GLU + residual ----
    __syncthreads();                 // pipeline smem free for reuse
    float* sig = (float*)smb;        // [64][68] padded

    if (wn >= 2) {                   // g-gate warps (cols 64..127)
        #pragma unroll
        for (int mt = 0; mt < 2; mt++) {
            #pragma unroll
            for (int nt = 0; nt < 4; nt++) {
                int gcol = (wn - 2) * 32 + nt * 8 + tig * 2;
                float bg0 = bo[DM + c0 + gcol];
                float bg1 = bo[DM + c0 + gcol + 1];
                #pragma unroll
                for (int half = 0; half < 2; half++) {
                    int ml = wm * 32 + mt * 16 + grp + half * 8;
                    float g0 = dacc[mt][nt][half * 2 + 0] + bg0;
                    float g1 = dacc[mt][nt][half * 2 + 1] + bg1;
                    sig[ml * 68 + gcol]     = 1.0f / (1.0f + expf(-g0));
                    sig[ml * 68 + gcol + 1] = 1.0f / (1.0f + expf(-g1));
                }
            }
        }
    }
    __syncthreads();
    if (wn < 2) {                    // a-gate warps (cols 0..63)
        #pragma unroll
        for (int mt = 0; mt < 2; mt++) {
            #pragma unroll
            for (int nt = 0; nt < 4; nt++) {
                int col = wn * 32 + nt * 8 + tig * 2;
                float ba0 = bo[c0 + col];
                float ba1 = bo[c0 + col + 1];
                #pragma unroll
                for (int half = 0; half < 2; half++) {
                    int ml = wm * 32 + mt * 16 + grp + half * 8;
                    int r = m0 + ml;
                    float a0 = dacc[mt][nt][half * 2 + 0] + ba0;
                    float a1 = dacc[mt][nt][half * 2 + 1] + ba1;
                    float s0 = sig[ml * 68 + col];
                    float s1 = sig[ml * 68 + col + 1];
                    float2 res = *(const float2*)(resid + (size_t)r * DM + c0 + col);
                    float2 o;
                    o.x = res.x + a0 * s0;
                    o.y = res.y + a1 * s1;
                    *(float2*)(out + (size_t)r * DM + c0 + col) = o;
                }
            }
        }
    }
}

// ---------------------------------------------------------------------------
extern "C" void kernel_launch(void* const* d_in, const int* in_sizes, int n_in,
                              void* d_out, int out_size) {
    const float* x      = (const float*)d_in[0];
    const float* emb    = (const float*)d_in[1];
    const float* A_real = (const float*)d_in[2];
    const float* A_imag = (const float*)d_in[3];
    const float* C      = (const float*)d_in[4];
    const float* log_dt = (const float*)d_in[5];
    const float* B_ssm  = (const float*)d_in[6];
    const float* D_skip = (const float*)d_in[7];
    const float* ln_g   = (const float*)d_in[8];
    const float* ln_b   = (const float*)d_in[9];
    const float* W_out  = (const float*)d_in[10];
    const float* b_out  = (const float*)d_in[11];
    const float* W_film = (const float*)d_in[12];
    const float* b_film = (const float*)d_in[13];
    float* out = (float*)d_out;

    static bool configured = false;
    if (!configured) {
        cudaFuncSetAttribute(gemm_glu_tc,
                             cudaFuncAttributeMaxDynamicSharedMemorySize,
                             GSM_BYTES);
        configured = true;
    }

    ln_kernel<<<BSZ * LSEQ, 128>>>(x, ln_g, ln_b);
    film_kernel<<<BSZ, 256>>>(emb, W_film, b_film);
    prep_w<<<256, 256>>>(W_out);
    scan_local<<<BSZ * (DM / 16) * CHK, 128>>>(A_real, A_imag, C, log_dt, B_ssm, D_skip);
    scan_fixup<<<BSZ * (DM / 8) * (CHK - 1), 128>>>(A_real, A_imag, C, log_dt, B_ssm);
    gemm_glu_tc<<<dim3((BSZ * LSEQ) / 64, DM / 64), 256, GSM_BYTES>>>(b_out, x, out);
}

// round 10
// speedup vs baseline: 1.5459x; 1.0167x over previous
#include <cuda_runtime.h>
#include <cuda_fp16.h>
#include <math.h>
#include <stdint.h>

#define BSZ 8
#define LSEQ 2048
#define DM 512
#define NS 64
#define EMB 512
#define CHK 16
#define TCH 128   // LSEQ / CHK

typedef unsigned long long ull;

// Scratch (allocation-free rule: __device__ globals)
// g_y2h and g_Wh stored PRE-TILED + PRE-SWIZZLED (SW128-equivalent), fp16:
//   A tiles: [m/128][k/64] tiles of 128x64, rows 128B, chunk ^= row&7
//   W tiles: [r/64][k/64]  tiles of  64x64, same swizzle
__device__ __align__(1024) float g_xn[BSZ * LSEQ * DM];
__device__ __align__(1024) float g_yp[BSZ * LSEQ * DM];
__device__ __align__(1024) unsigned short g_y2h[BSZ * LSEQ * DM];
__device__ __align__(1024) unsigned short g_Wh[2 * DM * DM];
__device__ float g_film[BSZ * 2 * DM];
__device__ ull g_str[BSZ * CHK * DM * 32];
__device__ ull g_sti[BSZ * CHK * DM * 32];

// tiled+swizzled element offset into A-layout arrays (y2 h)
__device__ __forceinline__ size_t a_tiled_off(int m, int d) {
    int row = m & 127;
    int chunk = ((d & 63) >> 3) ^ (row & 7);
    return ((size_t)((m >> 7) * 8 + (d >> 6)) << 13)
         + (size_t)row * 64 + (chunk << 3) + (d & 7);
}

// ---------------------------------------------------------------------------
// f32x2 packed-math helpers
// ---------------------------------------------------------------------------
__device__ __forceinline__ ull pk2(float a, float b) {
    ull r; asm("mov.b64 %0, {%1, %2};" : "=l"(r) : "f"(a), "f"(b)); return r;
}
__device__ __forceinline__ float2 upk2(ull v) {
    float2 f; asm("mov.b64 {%0, %1}, %2;" : "=f"(f.x), "=f"(f.y) : "l"(v)); return f;
}
__device__ __forceinline__ ull fma2(ull a, ull b, ull c) {
    ull d; asm("fma.rn.f32x2 %0, %1, %2, %3;" : "=l"(d) : "l"(a), "l"(b), "l"(c)); return d;
}
__device__ __forceinline__ ull mul2(ull a, ull b) {
    ull d; asm("mul.rn.f32x2 %0, %1, %2;" : "=l"(d) : "l"(a), "l"(b)); return d;
}
__device__ __forceinline__ ull add2(ull a, ull b) {
    ull d; asm("add.rn.f32x2 %0, %1, %2;" : "=l"(d) : "l"(a), "l"(b)); return d;
}

// pack 4 floats into fp16 (uint2)
__device__ __forceinline__ void pack_h(float4 v, uint2& H) {
    unsigned short h[4];
    float e[4] = {v.x, v.y, v.z, v.w};
    #pragma unroll
    for (int j = 0; j < 4; j++)
        h[j] = __half_as_ushort(__float2half_rn(e[j]));
    H.x = (uint32_t)h[0] | ((uint32_t)h[1] << 16);
    H.y = (uint32_t)h[2] | ((uint32_t)h[3] << 16);
}

// mbarrier helpers
__device__ __forceinline__ void mbar_init(uint32_t a, uint32_t cnt) {
    asm volatile("mbarrier.init.shared.b64 [%0], %1;" :: "r"(a), "r"(cnt) : "memory");
}
__device__ __forceinline__ void mbar_expect_tx(uint32_t a, uint32_t tx) {
    asm volatile("mbarrier.arrive.expect_tx.shared.b64 _, [%0], %1;" :: "r"(a), "r"(tx) : "memory");
}
__device__ __forceinline__ void mbar_arrive(uint32_t a) {
    asm volatile("mbarrier.arrive.shared.b64 _, [%0];" :: "r"(a) : "memory");
}
__device__ __forceinline__ void mbar_wait(uint32_t a, int parity) {
    asm volatile(
        "{\n\t.reg .pred P;\n"
        "LW_%=:\n\t"
        "mbarrier.try_wait.parity.acquire.cta.shared::cta.b64 P, [%0], %1, 0x989680;\n\t"
        "@P bra.uni LD_%=;\n\t"
        "bra.uni LW_%=;\n"
        "LD_%=:\n\t}"
        :: "r"(a), "r"(parity) : "memory");
}
__device__ __forceinline__ void bulk_cp(uint32_t dst, const void* src,
                                        uint32_t bytes, uint32_t mbar) {
    asm volatile(
        "cp.async.bulk.shared::cta.global.mbarrier::complete_tx::bytes [%0], [%1], %2, [%3];"
        :: "r"(dst), "l"(src), "r"(bytes), "r"(mbar) : "memory");
}

// ---------------------------------------------------------------------------
// Kernel 1: LayerNorm
// ---------------------------------------------------------------------------
__global__ void ln_kernel(const float* __restrict__ x,
                          const float* __restrict__ gamma,
                          const float* __restrict__ beta) {
    const int row = blockIdx.x;
    const int t = threadIdx.x;
    const float4* xr = (const float4*)(x + (size_t)row * DM);
    float4 v = xr[t];
    float s  = v.x + v.y + v.z + v.w;
    float ss = v.x * v.x + v.y * v.y + v.z * v.z + v.w * v.w;

    __shared__ float sh[8];
    #pragma unroll
    for (int o = 16; o; o >>= 1) {
        s  += __shfl_xor_sync(0xffffffffu, s, o);
        ss += __shfl_xor_sync(0xffffffffu, ss, o);
    }
    int w = t >> 5;
    if ((t & 31) == 0) { sh[w] = s; sh[4 + w] = ss; }
    __syncthreads();
    float S  = sh[0] + sh[1] + sh[2] + sh[3];
    float SS = sh[4] + sh[5] + sh[6] + sh[7];

    const float inv = 1.0f / (float)DM;
    float mu = S * inv;
    float var = SS * inv - mu * mu;
    float rs = rsqrtf(var + 1e-5f);

    float4 g4 = ((const float4*)gamma)[t];
    float4 b4 = ((const float4*)beta)[t];
    float4 o4;
    o4.x = (v.x - mu) * rs * g4.x + b4.x;
    o4.y = (v.y - mu) * rs * g4.y + b4.y;
    o4.z = (v.z - mu) * rs * g4.z + b4.z;
    o4.w = (v.w - mu) * rs * g4.w + b4.w;
    ((float4*)(g_xn + (size_t)row * DM))[t] = o4;
}

// ---------------------------------------------------------------------------
// Kernel 2: FiLM params
// ---------------------------------------------------------------------------
__global__ void film_kernel(const float* __restrict__ emb,
                            const float* __restrict__ Wf,
                            const float* __restrict__ bf) {
    __shared__ float se[EMB];
    const int b = blockIdx.x;
    for (int i = threadIdx.x; i < EMB; i += blockDim.x) {
        float e = emb[b * EMB + i];
        se[i] = e / (1.0f + expf(-e));
    }
    __syncthreads();
    for (int j = threadIdx.x; j < 2 * DM; j += blockDim.x) {
        const float4* wr = (const float4*)(Wf + (size_t)j * EMB);
        const float4* sr = (const float4*)se;
        float acc = bf[j];
        #pragma unroll 4
        for (int q = 0; q < EMB / 4; q++) {
            float4 w = wr[q], sv = sr[q];
            acc += w.x * sv.x + w.y * sv.y + w.z * sv.z + w.w * sv.w;
        }
        g_film[b * 2 * DM + j] = acc;
    }
}

// ---------------------------------------------------------------------------
// Kernel 2b: W -> fp16, TILED (64x64 tiles, swizzled 128B rows)
// ---------------------------------------------------------------------------
__global__ void prep_w(const float* __restrict__ W) {
    int i = blockIdx.x * blockDim.x + threadIdx.x;   // 0 .. 65535
    int r = i >> 6;
    int kc = i & 63;
    const float* src = W + (size_t)r * DM + kc * 8;
    float4 v0 = *(const float4*)src;
    float4 v1 = *(const float4*)(src + 4);
    float e[8] = {v0.x, v0.y, v0.z, v0.w, v1.x, v1.y, v1.z, v1.w};
    uint32_t hw[4];
    #pragma unroll
    for (int j = 0; j < 4; j++) {
        unsigned short h0 = __half_as_ushort(__float2half_rn(e[j * 2]));
        unsigned short h1 = __half_as_ushort(__float2half_rn(e[j * 2 + 1]));
        hw[j] = (uint32_t)h0 | ((uint32_t)h1 << 16);
    }
    int row = r & 63;
    int chunk = (kc & 7) ^ (row & 7);
    size_t off = ((size_t)((r >> 6) * 8 + (kc >> 3)) << 12)
               + (size_t)row * 64 + (chunk << 3);
    *(uint4*)(g_Wh + off) = make_uint4(hw[0], hw[1], hw[2], hw[3]);
}

// ---------------------------------------------------------------------------
// Kernel 3a: local S4D scan over one chunk of TCH=128 (zero initial state).
// 8 lanes per d, 4 f32x2 complex pairs per lane. Block = 16 d of one (b,c).
// ---------------------------------------------------------------------------
__global__ void __launch_bounds__(128)
scan_local(const float* __restrict__ A_real,
           const float* __restrict__ A_imag,
           const float* __restrict__ Cp,
           const float* __restrict__ log_dt,
           const float* __restrict__ B_ssm,
           const float* __restrict__ D_skip) {
    const int t = threadIdx.x;
    const int myd = t >> 3;           // 0..15
    const int g = t & 7;
    const int blk = blockIdx.x;
    const int c = blk & (CHK - 1);
    const int rest = blk >> 4;        // 0..255
    const int gid = rest * 16 + myd;
    const int b = gid >> 9;
    const int d = gid & 511;
    const int d0 = (rest * 16) & 511;

    const float dt = expf(log_dt[d]);
    ull Abr[4], Abi[4], nAbi[4], Ccr[4], nCci[4], s_r[4], s_i[4];
    #pragma unroll
    for (int p = 0; p < 4; p++) {
        float abr[2], abi[2], ccr[2], cci[2];
        #pragma unroll
        for (int j = 0; j < 2; j++) {
            int n = g * 8 + p * 2 + j;
            float ar = dt * A_real[d * NS + n];
            float ai = dt * A_imag[d * NS + n];
            float er = expf(ar), sb, cb;
            sincosf(ai, &sb, &cb);
            abr[j] = er * cb;
            abi[j] = er * sb;
            float bs = B_ssm[d * NS + n];
            ccr[j] = Cp[(d * NS + n) * 2 + 0] * bs;
            cci[j] = Cp[(d * NS + n) * 2 + 1] * bs;
        }
        Abr[p]  = pk2(abr[0], abr[1]);
        Abi[p]  = pk2(abi[0], abi[1]);
        nAbi[p] = pk2(-abi[0], -abi[1]);
        Ccr[p]  = pk2(ccr[0], ccr[1]);
        nCci[p] = pk2(-cci[0], -cci[1]);
        s_r[p] = 0ull; s_i[p] = 0ull;
    }
    const float dsk = D_skip[d];
    const float mult  = 1.0f + g_film[b * 2 * DM + d];
    const float shift = g_film[b * 2 * DM + DM + d];

    __shared__ float sx[2][64][16];
    __shared__ float syb[2][64][16];
    const size_t cbase = (size_t)b * LSEQ * DM + (size_t)c * TCH * DM;
    const float* xbase = g_xn + cbase + d0;
    float* ypb = g_yp + cbase + d0;

    // load mapping: 64 rows x 4 float4 = 256 float4, 2 per thread
    const int l0 = t >> 2, q0 = t & 3;
    const int l1 = (t + 128) >> 2;

    *(float4*)&sx[0][l0][q0 * 4] = *(const float4*)(xbase + (size_t)l0 * DM + q0 * 4);
    *(float4*)&sx[0][l1][q0 * 4] = *(const float4*)(xbase + (size_t)l1 * DM + q0 * 4);
    __syncthreads();

    for (int ch = 0; ch < TCH / 64; ch++) {
        const int cur = ch & 1;
        float4 nld0, nld1;
        const bool more = (ch + 1 < TCH / 64);
        if (more) {
            const float* nb = xbase + (size_t)(ch + 1) * 64 * DM;
            nld0 = *(const float4*)(nb + (size_t)l0 * DM + q0 * 4);
            nld1 = *(const float4*)(nb + (size_t)l1 * DM + q0 * 4);
        }
        #pragma unroll 4
        for (int i = 0; i < 64; i++) {
            float xv = sx[cur][i][myd];
            ull x2 = pk2(xv, xv);
            ull acc = 0ull;
            #pragma unroll
            for (int p = 0; p < 4; p++) {
                ull t1 = fma2(nAbi[p], s_i[p], x2);
                ull nr = fma2(Abr[p], s_r[p], t1);
                ull u  = mul2(Abi[p], s_r[p]);
                ull ni = fma2(Abr[p], s_i[p], u);
                s_r[p] = nr; s_i[p] = ni;
                acc = fma2(Ccr[p], nr, acc);
                acc = fma2(nCci[p], ni, acc);
            }
            float2 ac = upk2(acc);
            float tsum = ac.x + ac.y;
            tsum += __shfl_xor_sync(0xffffffffu, tsum, 4);
            tsum += __shfl_xor_sync(0xffffffffu, tsum, 2);
            tsum += __shfl_xor_sync(0xffffffffu, tsum, 1);
            if (g == 0) {
                float o = dt * tsum + dsk * xv;
                syb[cur][i][myd] = o * mult + shift;
            }
        }
        if (more) {
            *(float4*)&sx[cur ^ 1][l0][q0 * 4] = nld0;
            *(float4*)&sx[cur ^ 1][l1][q0 * 4] = nld1;
        }
        __syncthreads();
        // vectorized store stage: 2 float4 per thread
        #pragma unroll
        for (int pass = 0; pass < 2; pass++) {
            int r = pass ? l1 : l0;
            float4 v = *(float4*)&syb[cur][r][q0 * 4];
            if (c == 0) {
                int m = b * LSEQ + ch * 64 + r;
                size_t off = a_tiled_off(m, d0 + q0 * 4);
                uint2 H;
                pack_h(v, H);
                *(uint2*)(g_y2h + off) = H;
            } else {
                *(float4*)(ypb + (size_t)(ch * 64 + r) * DM + q0 * 4) = v;
            }
        }
    }

    // dump end states at canonical pair slots (pair = n>>1 = g*4+p)
    size_t sb = ((size_t)(b * CHK + c) * DM + d) * 32 + g * 4;
    #pragma unroll
    for (int p = 0; p < 4; p++) {
        g_str[sb + p] = s_r[p];
        g_sti[sb + p] = s_i[p];
    }
}

// ---------------------------------------------------------------------------
// Kernel 3b: fixup for chunks c=1..CHK-1 (16 lanes per d).
// ---------------------------------------------------------------------------
__global__ void scan_fixup(const float* __restrict__ A_real,
                           const float* __restrict__ A_imag,
                           const float* __restrict__ Cp,
                           const float* __restrict__ log_dt,
                           const float* __restrict__ B_ssm) {
    const int t = threadIdx.x;
    const int grp = t >> 4;
    const int g = t & 15;
    const int blk = blockIdx.x;
    const int c = 1 + blk % (CHK - 1);
    const int rest = blk / (CHK - 1);
    const int gid = rest * 8 + grp;
    const int b = gid >> 9;
    const int d = gid & 511;
    const int d0 = (rest * 8) & 511;

    const float dt = expf(log_dt[d]);
    const float k = dt * (1.0f + g_film[b * 2 * DM + d]);

    ull Lr[2], Li[2], nLi[2], LTr[2], LTi[2], nLTi[2], Ccr[2], Cci[2], nCci[2];
    #pragma unroll
    for (int p = 0; p < 2; p++) {
        float lr[2], li[2], ltr[2], lti[2], ccr[2], cci[2];
        #pragma unroll
        for (int j = 0; j < 2; j++) {
            int n = g * 4 + p * 2 + j;
            float ar = dt * A_real[d * NS + n];
            float ai = dt * A_imag[d * NS + n];
            float er = expf(ar), sb, cb;
            sincosf(ai, &sb, &cb);
            lr[j] = er * cb;
            li[j] = er * sb;
            float pr = lr[j], pi = li[j];
            #pragma unroll
            for (int q = 0; q < 7; q++) {    // lam^128 (TCH = 2^7)
                float nr2 = pr * pr - pi * pi;
                pi = 2.0f * pr * pi;
                pr = nr2;
            }
            ltr[j] = pr; lti[j] = pi;
            float bs = B_ssm[d * NS + n];
            ccr[j] = Cp[(d * NS + n) * 2 + 0] * bs * k;
            cci[j] = Cp[(d * NS + n) * 2 + 1] * bs * k;
        }
        Lr[p]   = pk2(lr[0], lr[1]);
        Li[p]   = pk2(li[0], li[1]);
        nLi[p]  = pk2(-li[0], -li[1]);
        LTr[p]  = pk2(ltr[0], ltr[1]);
        LTi[p]  = pk2(lti[0], lti[1]);
        nLTi[p] = pk2(-lti[0], -lti[1]);
        Ccr[p]  = pk2(ccr[0], ccr[1]);
        Cci[p]  = pk2(cci[0], cci[1]);
        nCci[p] = pk2(-cci[0], -cci[1]);
    }

    // combine local end-states (ascending Horner); pair slot = g*2 + p
    ull ar_[2] = {0ull, 0ull}, ai_[2] = {0ull, 0ull};
    size_t sb0 = ((size_t)(b * CHK) * DM + d) * 32 + g * 2;
    for (int cp = 0; cp < c; cp++) {
        size_t sb = sb0 + (size_t)cp * DM * 32;
        #pragma unroll
        for (int p = 0; p < 2; p++) {
            ull sr = g_str[sb + p];
            ull si = g_sti[sb + p];
            ull t1 = fma2(nLTi[p], ai_[p], sr);
            ull nr = fma2(LTr[p], ar_[p], t1);
            ull t2 = fma2(LTi[p], ar_[p], si);
            ull ni = fma2(LTr[p], ai_[p], t2);
            ar_[p] = nr; ai_[p] = ni;
        }
    }

    ull Wr[2], Wi[2];
    #pragma unroll
    for (int p = 0; p < 2; p++) {
        Wr[p] = fma2(Ccr[p], ar_[p], mul2(nCci[p], ai_[p]));
        Wi[p] = fma2(Ccr[p], ai_[p], mul2(Cci[p], ar_[p]));
    }

    __shared__ float syc[64][8];
    const size_t cbase = (size_t)b * LSEQ * DM + (size_t)c * TCH * DM;
    const float* ypb = g_yp + cbase + d0;

    for (int tile = 0; tile < TCH / 64; tile++) {
        #pragma unroll 4
        for (int i = 0; i < 64; i++) {
            #pragma unroll
            for (int p = 0; p < 2; p++) {
                ull t1 = mul2(nLi[p], Wi[p]);
                ull nr = fma2(Lr[p], Wr[p], t1);
                ull t2 = mul2(Li[p], Wr[p]);
                ull ni = fma2(Lr[p], Wi[p], t2);
                Wr[p] = nr; Wi[p] = ni;
            }
            ull acc = add2(Wr[0], Wr[1]);
            float2 a2 = upk2(acc);
            float tsum = a2.x + a2.y;
            #pragma unroll
            for (int o = 8; o; o >>= 1)
                tsum += __shfl_xor_sync(0xffffffffu, tsum, o);
            if (g == 0) syc[i][grp] = tsum;
        }
        __syncthreads();
        {
            const int r = t >> 1, hh = t & 1;
            size_t lrow = (size_t)(tile * 64 + r) * DM + hh * 4;
            float4 v = *(const float4*)(ypb + lrow);
            v.x += syc[r][hh * 4 + 0];
            v.y += syc[r][hh * 4 + 1];
            v.z += syc[r][hh * 4 + 2];
            v.w += syc[r][hh * 4 + 3];
            int m = b * LSEQ + c * TCH + tile * 64 + r;
            size_t off = a_tiled_off(m, d0 + hh * 4);
            uint2 H;
            pack_h(v, H);
            *(uint2*)(g_y2h + off) = H;
        }
        __syncthreads();
    }
}

// ---------------------------------------------------------------------------
// Kernel 4: out_proj GEMM, mma.sync f16 single-pass,
// block tile 64m x 128n (64 a-cols || 64 g-cols), BK=64, bulk-copy 2-stage.
// Stage (24KB): AH 0 (8K), BH 8K (64 a-rows + 64 g-rows = 16K).
// ---------------------------------------------------------------------------
#define GSTG 24576
#define NSTG 2
#define GSM_BYTES (NSTG * GSTG)

__device__ __forceinline__ void mma_f16(float d[4], const uint32_t a[4],
                                        const uint32_t b0, const uint32_t b1) {
    asm volatile(
        "mma.sync.aligned.m16n8k16.row.col.f32.f16.f16.f32 "
        "{%0,%1,%2,%3}, {%4,%5,%6,%7}, {%8,%9}, {%0,%1,%2,%3};\n"
        : "+f"(d[0]), "+f"(d[1]), "+f"(d[2]), "+f"(d[3])
        : "r"(a[0]), "r"(a[1]), "r"(a[2]), "r"(a[3]), "r"(b0), "r"(b1));
}
__device__ __forceinline__ void ldsm4(uint32_t* r, uint32_t byteaddr) {
    asm volatile("ldmatrix.sync.aligned.m8n8.x4.shared.b16 {%0,%1,%2,%3}, [%4];"
        : "=r"(r[0]), "=r"(r[1]), "=r"(r[2]), "=r"(r[3]) : "r"(byteaddr));
}

__global__ void __launch_bounds__(256, 2)
gemm_glu_tc(const float* __restrict__ bo,
            const float* __restrict__ resid,
            float* __restrict__ out) {
    extern __shared__ __align__(1024) char smb[];
    __shared__ uint64_t mbar_store[2 * NSTG];
    const uint32_t sbs = (uint32_t)__cvta_generic_to_shared(smb);
    const uint32_t mb = (uint32_t)__cvta_generic_to_shared(mbar_store);

    const int tid = threadIdx.x;
    const int mblk = blockIdx.x;          // m0 = mblk*64
    const int cblk = blockIdx.y;          // c0 = cblk*64
    const int m0 = mblk * 64;
    const int c0 = cblk * 64;
    const int warp = tid >> 5, lane = tid & 31;
    const int wm = warp >> 2;             // 0..1 (m)
    const int wn = warp & 3;              // 0..3 (n over 128 cols)
    const int grp = lane >> 2, tig = lane & 3;

    if (tid == 0) {
        #pragma unroll
        for (int s = 0; s < NSTG; s++) {
            mbar_init(mb + s * 8, 1);             // full (tx-based)
            mbar_init(mb + (NSTG + s) * 8, 256);  // empty (all threads)
        }
    }
    __syncthreads();

    const size_t mtile = mblk >> 1;
    const size_t ahalf = (size_t)(mblk & 1) * 8192;   // byte slice within A tile

    auto issue_stage = [&](int it) {
        int s = it & 1;
        uint32_t full = mb + s * 8;
        mbar_expect_tx(full, GSTG);
        uint32_t st = sbs + s * GSTG;
        bulk_cp(st,         (const char*)g_y2h + ((mtile * 8 + it) << 14) + ahalf, 8192, full);
        bulk_cp(st + 8192,  (const char*)g_Wh + (((size_t)cblk * 8 + it) << 13), 8192, full);
        bulk_cp(st + 16384, (const char*)g_Wh + (((size_t)(8 + cblk) * 8 + it) << 13), 8192, full);
    };

    if (tid == 0) {
        issue_stage(0);
        issue_stage(1);
    }

    float dacc[2][4][4];
    #pragma unroll
    for (int mt = 0; mt < 2; mt++)
        #pragma unroll
        for (int nt = 0; nt < 4; nt++)
            #pragma unroll
            for (int r = 0; r < 4; r++) dacc[mt][nt][r] = 0.0f;

    const int rowA0 = wm * 32 + (lane & 15);
    const int chA0 = lane >> 4;
    const int rowB0 = wn * 32 + ((lane & 16) >> 1) + (lane & 7);
    const int chB0 = (lane >> 3) & 1;

    const int NKT = 8;   // 512 / 64
    for (int it = 0; it < NKT; it++) {
        const int s = it & 1;
        const int q = it >> 1;
        mbar_wait(mb + s * 8, q & 1);
        const uint32_t st = sbs + s * GSTG;

        #pragma unroll
        for (int kk = 0; kk < 4; kk++) {
            uint32_t ah[2][4];
            #pragma unroll
            for (int mt = 0; mt < 2; mt++) {
                int rowA = rowA0 + mt * 16;
                int ch = (2 * kk + chA0) ^ (rowA & 7);
                ldsm4(ah[mt], st + (uint32_t)(rowA * 128 + ch * 16));
            }
            uint32_t bh[8];
            #pragma unroll
            for (int go = 0; go < 2; go++) {
                int rr = rowB0 + go * 16;
                int cs = (2 * kk + chB0) ^ (rr & 7);
                ldsm4(&bh[go * 4], st + 8192 + (uint32_t)(rr * 128 + cs * 16));
            }
            #pragma unroll
            for (int mt = 0; mt < 2; mt++)
                #pragma unroll
                for (int nt = 0; nt < 4; nt++)
                    mma_f16(dacc[mt][nt], ah[mt], bh[nt * 2], bh[nt * 2 + 1]);
        }

        mbar_arrive(mb + (NSTG + s) * 8);
        if (tid == 0 && it + NSTG < NKT) {
            mbar_wait(mb + (NSTG + s) * 8, q & 1);
            issue_stage(it + NSTG);
        }
    }

    // ---- epilogue: GLU + residual ----
    __syncthreads();                 // pipeline smem free for reuse
    float* sig = (float*)smb;        // [64][68] padded

    if (wn >= 2) {                   // g-gate warps (cols 64..127)
        #pragma unroll
        for (int mt = 0; mt < 2; mt++) {
            #pragma unroll
            for (int nt = 0; nt < 4; nt++) {
                int gcol = (wn - 2) * 32 + nt * 8 + tig * 2;
                float bg0 = bo[DM + c0 + gcol];
                float bg1 = bo[DM + c0 + gcol + 1];
                #pragma unroll
                for (int half = 0; half < 2; half++) {
                    int ml = wm * 32 + mt * 16 + grp + half * 8;
                    float g0 = dacc[mt][nt][half * 2 + 0] + bg0;
                    float g1 = dacc[mt][nt][half * 2 + 1] + bg1;
                    sig[ml * 68 + gcol]     = 1.0f / (1.0f + expf(-g0));
                    sig[ml * 68 + gcol + 1] = 1.0f / (1.0f + expf(-g1));
                }
            }
        }
    }
    __syncthreads();
    if (wn < 2) {                    // a-gate warps (cols 0..63)
        #pragma unroll
        for (int mt = 0; mt < 2; mt++) {
            #pragma unroll
            for (int nt = 0; nt < 4; nt++) {
                int col = wn * 32 + nt * 8 + tig * 2;
                float ba0 = bo[c0 + col];
                float ba1 = bo[c0 + col + 1];
                #pragma unroll
                for (int half = 0; half < 2; half++) {
                    int ml = wm * 32 + mt * 16 + grp + half * 8;
                    int r = m0 + ml;
                    float a0 = dacc[mt][nt][half * 2 + 0] + ba0;
                    float a1 = dacc[mt][nt][half * 2 + 1] + ba1;
                    float s0 = sig[ml * 68 + col];
                    float s1 = sig[ml * 68 + col + 1];
                    float2 res = *(const float2*)(resid + (size_t)r * DM + c0 + col);
                    float2 o;
                    o.x = res.x + a0 * s0;
                    o.y = res.y + a1 * s1;
                    *(float2*)(out + (size_t)r * DM + c0 + col) = o;
                }
            }
        }
    }
}

// ---------------------------------------------------------------------------
extern "C" void kernel_launch(void* const* d_in, const int* in_sizes, int n_in,
                              void* d_out, int out_size) {
    const float* x      = (const float*)d_in[0];
    const float* emb    = (const float*)d_in[1];
    const float* A_real = (const float*)d_in[2];
    const float* A_imag = (const float*)d_in[3];
    const float* C      = (const float*)d_in[4];
    const float* log_dt = (const float*)d_in[5];
    const float* B_ssm  = (const float*)d_in[6];
    const float* D_skip = (const float*)d_in[7];
    const float* ln_g   = (const float*)d_in[8];
    const float* ln_b   = (const float*)d_in[9];
    const float* W_out  = (const float*)d_in[10];
    const float* b_out  = (const float*)d_in[11];
    const float* W_film = (const float*)d_in[12];
    const float* b_film = (const float*)d_in[13];
    float* out = (float*)d_out;

    static bool configured = false;
    if (!configured) {
        cudaFuncSetAttribute(gemm_glu_tc,
                             cudaFuncAttributeMaxDynamicSharedMemorySize,
                             GSM_BYTES);
        configured = true;
    }

    ln_kernel<<<BSZ * LSEQ, 128>>>(x, ln_g, ln_b);
    film_kernel<<<BSZ, 256>>>(emb, W_film, b_film);
    prep_w<<<256, 256>>>(W_out);
    scan_local<<<BSZ * (DM / 16) * CHK, 128>>>(A_real, A_imag, C, log_dt, B_ssm, D_skip);
    scan_fixup<<<BSZ * (DM / 8) * (CHK - 1), 128>>>(A_real, A_imag, C, log_dt, B_ssm);
    gemm_glu_tc<<<dim3((BSZ * LSEQ) / 64, DM / 64), 256, GSM_BYTES>>>(b_out, x, out);
}

// round 11
// speedup vs baseline: 1.5637x; 1.0115x over previous
#include <cuda_runtime.h>
#include <cuda_fp16.h>
#include <math.h>
#include <stdint.h>

#define BSZ 8
#define LSEQ 2048
#define DM 512
#define NS 64
#define EMB 512
#define CHK 16
#define TCH 128   // LSEQ / CHK

typedef unsigned long long ull;

// Scratch (allocation-free rule: __device__ globals)
// g_y2h and g_Wh stored PRE-TILED + PRE-SWIZZLED (SW128-equivalent), fp16:
//   A tiles: [m/128][k/64] tiles of 128x64, rows 128B, chunk ^= row&7
//   W tiles: [r/64][k/64]  tiles of  64x64, same swizzle
__device__ __align__(1024) float g_xn[BSZ * LSEQ * DM];
__device__ __align__(1024) float g_yp[BSZ * LSEQ * DM];
__device__ __align__(1024) unsigned short g_y2h[BSZ * LSEQ * DM];
__device__ __align__(1024) unsigned short g_Wh[2 * DM * DM];
__device__ float g_film[BSZ * 2 * DM];
__device__ ull g_str[BSZ * CHK * DM * 32];
__device__ ull g_sti[BSZ * CHK * DM * 32];

// tiled+swizzled element offset into A-layout arrays (y2 h)
__device__ __forceinline__ size_t a_tiled_off(int m, int d) {
    int row = m & 127;
    int chunk = ((d & 63) >> 3) ^ (row & 7);
    return ((size_t)((m >> 7) * 8 + (d >> 6)) << 13)
         + (size_t)row * 64 + (chunk << 3) + (d & 7);
}

// ---------------------------------------------------------------------------
// f32x2 packed-math helpers
// ---------------------------------------------------------------------------
__device__ __forceinline__ ull pk2(float a, float b) {
    ull r; asm("mov.b64 %0, {%1, %2};" : "=l"(r) : "f"(a), "f"(b)); return r;
}
__device__ __forceinline__ float2 upk2(ull v) {
    float2 f; asm("mov.b64 {%0, %1}, %2;" : "=f"(f.x), "=f"(f.y) : "l"(v)); return f;
}
__device__ __forceinline__ ull fma2(ull a, ull b, ull c) {
    ull d; asm("fma.rn.f32x2 %0, %1, %2, %3;" : "=l"(d) : "l"(a), "l"(b), "l"(c)); return d;
}
__device__ __forceinline__ ull mul2(ull a, ull b) {
    ull d; asm("mul.rn.f32x2 %0, %1, %2;" : "=l"(d) : "l"(a), "l"(b)); return d;
}
__device__ __forceinline__ ull add2(ull a, ull b) {
    ull d; asm("add.rn.f32x2 %0, %1, %2;" : "=l"(d) : "l"(a), "l"(b)); return d;
}

// pack 4 floats into fp16 (uint2)
__device__ __forceinline__ void pack_h(float4 v, uint2& H) {
    unsigned short h[4];
    float e[4] = {v.x, v.y, v.z, v.w};
    #pragma unroll
    for (int j = 0; j < 4; j++)
        h[j] = __half_as_ushort(__float2half_rn(e[j]));
    H.x = (uint32_t)h[0] | ((uint32_t)h[1] << 16);
    H.y = (uint32_t)h[2] | ((uint32_t)h[3] << 16);
}

// mbarrier helpers
__device__ __forceinline__ void mbar_init(uint32_t a, uint32_t cnt) {
    asm volatile("mbarrier.init.shared.b64 [%0], %1;" :: "r"(a), "r"(cnt) : "memory");
}
__device__ __forceinline__ void mbar_expect_tx(uint32_t a, uint32_t tx) {
    asm volatile("mbarrier.arrive.expect_tx.shared.b64 _, [%0], %1;" :: "r"(a), "r"(tx) : "memory");
}
__device__ __forceinline__ void mbar_arrive(uint32_t a) {
    asm volatile("mbarrier.arrive.shared.b64 _, [%0];" :: "r"(a) : "memory");
}
__device__ __forceinline__ void mbar_wait(uint32_t a, int parity) {
    asm volatile(
        "{\n\t.reg .pred P;\n"
        "LW_%=:\n\t"
        "mbarrier.try_wait.parity.acquire.cta.shared::cta.b64 P, [%0], %1, 0x989680;\n\t"
        "@P bra.uni LD_%=;\n\t"
        "bra.uni LW_%=;\n"
        "LD_%=:\n\t}"
        :: "r"(a), "r"(parity) : "memory");
}
__device__ __forceinline__ void bulk_cp(uint32_t dst, const void* src,
                                        uint32_t bytes, uint32_t mbar) {
    asm volatile(
        "cp.async.bulk.shared::cta.global.mbarrier::complete_tx::bytes [%0], [%1], %2, [%3];"
        :: "r"(dst), "l"(src), "r"(bytes), "r"(mbar) : "memory");
}

// ---------------------------------------------------------------------------
// Kernel 1: LayerNorm
// ---------------------------------------------------------------------------
__global__ void ln_kernel(const float* __restrict__ x,
                          const float* __restrict__ gamma,
                          const float* __restrict__ beta) {
    const int row = blockIdx.x;
    const int t = threadIdx.x;
    const float4* xr = (const float4*)(x + (size_t)row * DM);
    float4 v = xr[t];
    float s  = v.x + v.y + v.z + v.w;
    float ss = v.x * v.x + v.y * v.y + v.z * v.z + v.w * v.w;

    __shared__ float sh[8];
    #pragma unroll
    for (int o = 16; o; o >>= 1) {
        s  += __shfl_xor_sync(0xffffffffu, s, o);
        ss += __shfl_xor_sync(0xffffffffu, ss, o);
    }
    int w = t >> 5;
    if ((t & 31) == 0) { sh[w] = s; sh[4 + w] = ss; }
    __syncthreads();
    float S  = sh[0] + sh[1] + sh[2] + sh[3];
    float SS = sh[4] + sh[5] + sh[6] + sh[7];

    const float inv = 1.0f / (float)DM;
    float mu = S * inv;
    float var = SS * inv - mu * mu;
    float rs = rsqrtf(var + 1e-5f);

    float4 g4 = ((const float4*)gamma)[t];
    float4 b4 = ((const float4*)beta)[t];
    float4 o4;
    o4.x = (v.x - mu) * rs * g4.x + b4.x;
    o4.y = (v.y - mu) * rs * g4.y + b4.y;
    o4.z = (v.z - mu) * rs * g4.z + b4.z;
    o4.w = (v.w - mu) * rs * g4.w + b4.w;
    ((float4*)(g_xn + (size_t)row * DM))[t] = o4;
}

// ---------------------------------------------------------------------------
// Kernel 2: FiLM params
// ---------------------------------------------------------------------------
__global__ void film_kernel(const float* __restrict__ emb,
                            const float* __restrict__ Wf,
                            const float* __restrict__ bf) {
    __shared__ float se[EMB];
    const int b = blockIdx.x;
    for (int i = threadIdx.x; i < EMB; i += blockDim.x) {
        float e = emb[b * EMB + i];
        se[i] = e / (1.0f + expf(-e));
    }
    __syncthreads();
    for (int j = threadIdx.x; j < 2 * DM; j += blockDim.x) {
        const float4* wr = (const float4*)(Wf + (size_t)j * EMB);
        const float4* sr = (const float4*)se;
        float acc = bf[j];
        #pragma unroll 4
        for (int q = 0; q < EMB / 4; q++) {
            float4 w = wr[q], sv = sr[q];
            acc += w.x * sv.x + w.y * sv.y + w.z * sv.z + w.w * sv.w;
        }
        g_film[b * 2 * DM + j] = acc;
    }
}

// ---------------------------------------------------------------------------
// Kernel 2b: W -> fp16, TILED (64x64 tiles, swizzled 128B rows)
// ---------------------------------------------------------------------------
__global__ void prep_w(const float* __restrict__ W) {
    int i = blockIdx.x * blockDim.x + threadIdx.x;   // 0 .. 65535
    int r = i >> 6;
    int kc = i & 63;
    const float* src = W + (size_t)r * DM + kc * 8;
    float4 v0 = *(const float4*)src;
    float4 v1 = *(const float4*)(src + 4);
    float e[8] = {v0.x, v0.y, v0.z, v0.w, v1.x, v1.y, v1.z, v1.w};
    uint32_t hw[4];
    #pragma unroll
    for (int j = 0; j < 4; j++) {
        unsigned short h0 = __half_as_ushort(__float2half_rn(e[j * 2]));
        unsigned short h1 = __half_as_ushort(__float2half_rn(e[j * 2 + 1]));
        hw[j] = (uint32_t)h0 | ((uint32_t)h1 << 16);
    }
    int row = r & 63;
    int chunk = (kc & 7) ^ (row & 7);
    size_t off = ((size_t)((r >> 6) * 8 + (kc >> 3)) << 12)
               + (size_t)row * 64 + (chunk << 3);
    *(uint4*)(g_Wh + off) = make_uint4(hw[0], hw[1], hw[2], hw[3]);
}

// ---------------------------------------------------------------------------
// Kernel 3a: local S4D scan over one chunk of TCH=128 (zero initial state).
// 8 lanes per d, 4 f32x2 complex pairs per lane. Block = 16 d of one (b,c).
// accP/accN split drops the nCci constants (register diet, occ >= 6 CTAs/SM).
// ---------------------------------------------------------------------------
__global__ void __launch_bounds__(128, 6)
scan_local(const float* __restrict__ A_real,
           const float* __restrict__ A_imag,
           const float* __restrict__ Cp,
           const float* __restrict__ log_dt,
           const float* __restrict__ B_ssm,
           const float* __restrict__ D_skip) {
    const int t = threadIdx.x;
    const int myd = t >> 3;           // 0..15
    const int g = t & 7;
    const int blk = blockIdx.x;
    const int c = blk & (CHK - 1);
    const int rest = blk >> 4;        // 0..255
    const int gid = rest * 16 + myd;
    const int b = gid >> 9;
    const int d = gid & 511;
    const int d0 = (rest * 16) & 511;

    const float dt = expf(log_dt[d]);
    ull Abr[4], Abi[4], nAbi[4], Ccr[4], Cci[4], s_r[4], s_i[4];
    #pragma unroll
    for (int p = 0; p < 4; p++) {
        float abr[2], abi[2], ccr[2], cci[2];
        #pragma unroll
        for (int j = 0; j < 2; j++) {
            int n = g * 8 + p * 2 + j;
            float ar = dt * A_real[d * NS + n];
            float ai = dt * A_imag[d * NS + n];
            float er = expf(ar), sb, cb;
            sincosf(ai, &sb, &cb);
            abr[j] = er * cb;
            abi[j] = er * sb;
            float bs = B_ssm[d * NS + n];
            ccr[j] = Cp[(d * NS + n) * 2 + 0] * bs;
            cci[j] = Cp[(d * NS + n) * 2 + 1] * bs;
        }
        Abr[p]  = pk2(abr[0], abr[1]);
        Abi[p]  = pk2(abi[0], abi[1]);
        nAbi[p] = pk2(-abi[0], -abi[1]);
        Ccr[p]  = pk2(ccr[0], ccr[1]);
        Cci[p]  = pk2(cci[0], cci[1]);
        s_r[p] = 0ull; s_i[p] = 0ull;
    }
    const float dsk = D_skip[d];
    const float mult  = 1.0f + g_film[b * 2 * DM + d];
    const float shift = g_film[b * 2 * DM + DM + d];

    __shared__ float sx[2][64][16];
    __shared__ float syb[2][64][16];
    const size_t cbase = (size_t)b * LSEQ * DM + (size_t)c * TCH * DM;
    const float* xbase = g_xn + cbase + d0;
    float* ypb = g_yp + cbase + d0;

    // load mapping: 64 rows x 4 float4 = 256 float4, 2 per thread
    const int l0 = t >> 2, q0 = t & 3;
    const int l1 = (t + 128) >> 2;

    *(float4*)&sx[0][l0][q0 * 4] = *(const float4*)(xbase + (size_t)l0 * DM + q0 * 4);
    *(float4*)&sx[0][l1][q0 * 4] = *(const float4*)(xbase + (size_t)l1 * DM + q0 * 4);
    __syncthreads();

    for (int ch = 0; ch < TCH / 64; ch++) {
        const int cur = ch & 1;
        float4 nld0, nld1;
        const bool more = (ch + 1 < TCH / 64);
        if (more) {
            const float* nb = xbase + (size_t)(ch + 1) * 64 * DM;
            nld0 = *(const float4*)(nb + (size_t)l0 * DM + q0 * 4);
            nld1 = *(const float4*)(nb + (size_t)l1 * DM + q0 * 4);
        }
        #pragma unroll 4
        for (int i = 0; i < 64; i++) {
            float xv = sx[cur][i][myd];
            ull x2 = pk2(xv, xv);
            ull accP = 0ull, accN = 0ull;
            #pragma unroll
            for (int p = 0; p < 4; p++) {
                ull t1 = fma2(nAbi[p], s_i[p], x2);
                ull nr = fma2(Abr[p], s_r[p], t1);
                ull u  = mul2(Abi[p], s_r[p]);
                ull ni = fma2(Abr[p], s_i[p], u);
                s_r[p] = nr; s_i[p] = ni;
                accP = fma2(Ccr[p], nr, accP);
                accN = fma2(Cci[p], ni, accN);
            }
            float2 aP = upk2(accP);
            float2 aN = upk2(accN);
            float tsum = (aP.x - aN.x) + (aP.y - aN.y);
            tsum += __shfl_xor_sync(0xffffffffu, tsum, 4);
            tsum += __shfl_xor_sync(0xffffffffu, tsum, 2);
            tsum += __shfl_xor_sync(0xffffffffu, tsum, 1);
            if (g == 0) {
                float o = dt * tsum + dsk * xv;
                syb[cur][i][myd] = o * mult + shift;
            }
        }
        if (more) {
            *(float4*)&sx[cur ^ 1][l0][q0 * 4] = nld0;
            *(float4*)&sx[cur ^ 1][l1][q0 * 4] = nld1;
        }
        __syncthreads();
        // vectorized store stage: 2 float4 per thread
        #pragma unroll
        for (int pass = 0; pass < 2; pass++) {
            int r = pass ? l1 : l0;
            float4 v = *(float4*)&syb[cur][r][q0 * 4];
            if (c == 0) {
                int m = b * LSEQ + ch * 64 + r;
                size_t off = a_tiled_off(m, d0 + q0 * 4);
                uint2 H;
                pack_h(v, H);
                *(uint2*)(g_y2h + off) = H;
            } else {
                *(float4*)(ypb + (size_t)(ch * 64 + r) * DM + q0 * 4) = v;
            }
        }
    }

    // dump end states at canonical pair slots (pair index = g*4+p)
    size_t sb = ((size_t)(b * CHK + c) * DM + d) * 32 + g * 4;
    #pragma unroll
    for (int p = 0; p < 4; p++) {
        g_str[sb + p] = s_r[p];
        g_sti[sb + p] = s_i[p];
    }
}

// ---------------------------------------------------------------------------
// Kernel 3b: fixup for chunks c=1..CHK-1. 8 lanes per d, 4 pairs per lane,
// 16 d per block. Cc*k folded into W at init; mainloop = lambda rotation only.
// ---------------------------------------------------------------------------
__global__ void __launch_bounds__(128)
scan_fixup(const float* __restrict__ A_real,
           const float* __restrict__ A_imag,
           const float* __restrict__ Cp,
           const float* __restrict__ log_dt,
           const float* __restrict__ B_ssm) {
    const int t = threadIdx.x;
    const int myd = t >> 3;           // 0..15
    const int g = t & 7;
    const int blk = blockIdx.x;
    const int c = 1 + blk % (CHK - 1);
    const int rest = blk / (CHK - 1); // 0..255
    const int gid = rest * 16 + myd;
    const int b = gid >> 9;
    const int d = gid & 511;
    const int d0 = (rest * 16) & 511;

    const float dt = expf(log_dt[d]);
    const float k = dt * (1.0f + g_film[b * 2 * DM + d]);

    ull Lr[4], Li[4], nLi[4], Wr[4], Wi[4];
    {
        ull LTr[4], LTi[4], nLTi[4], Ccr[4], Cci[4];
        #pragma unroll
        for (int p = 0; p < 4; p++) {
            float lr[2], li[2], ltr[2], lti[2], ccr[2], cci[2];
            #pragma unroll
            for (int j = 0; j < 2; j++) {
                int n = g * 8 + p * 2 + j;
                float ar = dt * A_real[d * NS + n];
                float ai = dt * A_imag[d * NS + n];
                float er = expf(ar), sb, cb;
                sincosf(ai, &sb, &cb);
                lr[j] = er * cb;
                li[j] = er * sb;
                float pr = lr[j], pi = li[j];
                #pragma unroll
                for (int q = 0; q < 7; q++) {    // lam^128 (TCH = 2^7)
                    float nr2 = pr * pr - pi * pi;
                    pi = 2.0f * pr * pi;
                    pr = nr2;
                }
                ltr[j] = pr; lti[j] = pi;
                float bs = B_ssm[d * NS + n];
                ccr[j] = Cp[(d * NS + n) * 2 + 0] * bs * k;
                cci[j] = Cp[(d * NS + n) * 2 + 1] * bs * k;
            }
            Lr[p]   = pk2(lr[0], lr[1]);
            Li[p]   = pk2(li[0], li[1]);
            nLi[p]  = pk2(-li[0], -li[1]);
            LTr[p]  = pk2(ltr[0], ltr[1]);
            LTi[p]  = pk2(lti[0], lti[1]);
            nLTi[p] = pk2(-lti[0], -lti[1]);
            Ccr[p]  = pk2(ccr[0], ccr[1]);
            Cci[p]  = pk2(cci[0], cci[1]);
        }

        // combine local end-states (ascending Horner); pair slot = g*4 + p
        ull ar_[4] = {0ull, 0ull, 0ull, 0ull}, ai_[4] = {0ull, 0ull, 0ull, 0ull};
        size_t sb0 = ((size_t)(b * CHK) * DM + d) * 32 + g * 4;
        for (int cp = 0; cp < c; cp++) {
            size_t sb = sb0 + (size_t)cp * DM * 32;
            #pragma unroll
            for (int p = 0; p < 4; p++) {
                ull sr = g_str[sb + p];
                ull si = g_sti[sb + p];
                ull t1 = fma2(nLTi[p], ai_[p], sr);
                ull nr = fma2(LTr[p], ar_[p], t1);
                ull t2 = fma2(LTi[p], ar_[p], si);
                ull ni = fma2(LTr[p], ai_[p], t2);
                ar_[p] = nr; ai_[p] = ni;
            }
        }

        // W = (Cc * k) * s_in   (complex)
        #pragma unroll
        for (int p = 0; p < 4; p++) {
            ull u1 = mul2(Cci[p], ai_[p]);
            ull pos = fma2(Ccr[p], ar_[p], 0ull);
            // Wr = Ccr*ar - Cci*ai : compute via negated product
            float2 u1f = upk2(u1);
            ull nu1 = pk2(-u1f.x, -u1f.y);
            Wr[p] = add2(pos, nu1);
            Wi[p] = fma2(Ccr[p], ai_[p], mul2(Cci[p], ar_[p]));
        }
    }

    __shared__ float syc[64][16];
    const size_t cbase = (size_t)b * LSEQ * DM + (size_t)c * TCH * DM;
    const float* ypb = g_yp + cbase + d0;

    const int l0 = t >> 2, q0 = t & 3;
    const int l1 = (t + 128) >> 2;

    for (int tile = 0; tile < TCH / 64; tile++) {
        #pragma unroll 4
        for (int i = 0; i < 64; i++) {
            #pragma unroll
            for (int p = 0; p < 4; p++) {
                ull t1 = mul2(nLi[p], Wi[p]);
                ull nr = fma2(Lr[p], Wr[p], t1);
                ull t2 = mul2(Li[p], Wr[p]);
                ull ni = fma2(Lr[p], Wi[p], t2);
                Wr[p] = nr; Wi[p] = ni;
            }
            ull acc = add2(add2(Wr[0], Wr[1]), add2(Wr[2], Wr[3]));
            float2 a2 = upk2(acc);
            float tsum = a2.x + a2.y;
            tsum += __shfl_xor_sync(0xffffffffu, tsum, 4);
            tsum += __shfl_xor_sync(0xffffffffu, tsum, 2);
            tsum += __shfl_xor_sync(0xffffffffu, tsum, 1);
            if (g == 0) syc[i][myd] = tsum;
        }
        __syncthreads();
        // vectorized read/modify/store: 2 float4 per thread
        #pragma unroll
        for (int pass = 0; pass < 2; pass++) {
            int r = pass ? l1 : l0;
            size_t lrow = (size_t)(tile * 64 + r) * DM + q0 * 4;
            float4 v = *(const float4*)(ypb + lrow);
            v.x += syc[r][q0 * 4 + 0];
            v.y += syc[r][q0 * 4 + 1];
            v.z += syc[r][q0 * 4 + 2];
            v.w += syc[r][q0 * 4 + 3];
            int m = b * LSEQ + c * TCH + tile * 64 + r;
            size_t off = a_tiled_off(m, d0 + q0 * 4);
            uint2 H;
            pack_h(v, H);
            *(uint2*)(g_y2h + off) = H;
        }
        __syncthreads();
    }
}

// ---------------------------------------------------------------------------
// Kernel 4: out_proj GEMM, mma.sync f16 single-pass,
// block tile 64m x 128n (64 a-cols || 64 g-cols), BK=64, bulk-copy 2-stage.
// Stage (24KB): AH 0 (8K), BH 8K (64 a-rows + 64 g-rows = 16K).
// ---------------------------------------------------------------------------
#define GSTG 24576
#define NSTG 2
#define GSM_BYTES (NSTG * GSTG)

__device__ __forceinline__ void mma_f16(float d[4], const uint32_t a[4],
                                        const uint32_t b0, const uint32_t b1) {
    asm volatile(
        "mma.sync.aligned.m16n8k16.row.col.f32.f16.f16.f32 "
        "{%0,%1,%2,%3}, {%4,%5,%6,%7}, {%8,%9}, {%0,%1,%2,%3};\n"
        : "+f"(d[0]), "+f"(d[1]), "+f"(d[2]), "+f"(d[3])
        : "r"(a[0]), "r"(a[1]), "r"(a[2]), "r"(a[3]), "r"(b0), "r"(b1));
}
__device__ __forceinline__ void ldsm4(uint32_t* r, uint32_t byteaddr) {
    asm volatile("ldmatrix.sync.aligned.m8n8.x4.shared.b16 {%0,%1,%2,%3}, [%4];"
        : "=r"(r[0]), "=r"(r[1]), "=r"(r[2]), "=r"(r[3]) : "r"(byteaddr));
}

__global__ void __launch_bounds__(256, 2)
gemm_glu_tc(const float* __restrict__ bo,
            const float* __restrict__ resid,
            float* __restrict__ out) {
    extern __shared__ __align__(1024) char smb[];
    __shared__ uint64_t mbar_store[2 * NSTG];
    const uint32_t sbs = (uint32_t)__cvta_generic_to_shared(smb);
    const uint32_t mb = (uint32_t)__cvta_generic_to_shared(mbar_store);

    const int tid = threadIdx.x;
    const int mblk = blockIdx.x;          // m0 = mblk*64
    const int cblk = blockIdx.y;          // c0 = cblk*64
    const int m0 = mblk * 64;
    const int c0 = cblk * 64;
    const int warp = tid >> 5, lane = tid & 31;
    const int wm = warp >> 2;             // 0..1 (m)
    const int wn = warp & 3;              // 0..3 (n over 128 cols)
    const int grp = lane >> 2, tig = lane & 3;

    if (tid == 0) {
        #pragma unroll
        for (int s = 0; s < NSTG; s++) {
            mbar_init(mb + s * 8, 1);             // full (tx-based)
            mbar_init(mb + (NSTG + s) * 8, 256);  // empty (all threads)
        }
    }
    __syncthreads();

    const size_t mtile = mblk >> 1;
    const size_t ahalf = (size_t)(mblk & 1) * 8192;   // byte slice within A tile

    auto issue_stage = [&](int it) {
        int s = it & 1;
        uint32_t full = mb + s * 8;
        mbar_expect_tx(full, GSTG);
        uint32_t st = sbs + s * GSTG;
        bulk_cp(st,         (const char*)g_y2h + ((mtile * 8 + it) << 14) + ahalf, 8192, full);
        bulk_cp(st + 8192,  (const char*)g_Wh + (((size_t)cblk * 8 + it) << 13), 8192, full);
        bulk_cp(st + 16384, (const char*)g_Wh + (((size_t)(8 + cblk) * 8 + it) << 13), 8192, full);
    };

    if (tid == 0) {
        issue_stage(0);
        issue_stage(1);
    }

    float dacc[2][4][4];
    #pragma unroll
    for (int mt = 0; mt < 2; mt++)
        #pragma unroll
        for (int nt = 0; nt < 4; nt++)
            #pragma unroll
            for (int r = 0; r < 4; r++) dacc[mt][nt][r] = 0.0f;

    const int rowA0 = wm * 32 + (lane & 15);
    const int chA0 = lane >> 4;
    const int rowB0 = wn * 32 + ((lane & 16) >> 1) + (lane & 7);
    const int chB0 = (lane >> 3) & 1;

    const int NKT = 8;   // 512 / 64
    for (int it = 0; it < NKT; it++) {
        const int s = it & 1;
        const int q = it >> 1;
        mbar_wait(mb + s * 8, q & 1);
        const uint32_t st = sbs + s * GSTG;

        #pragma unroll
        for (int kk = 0; kk < 4; kk++) {
            uint32_t ah[2][4];
            #pragma unroll
            for (int mt = 0; mt < 2; mt++) {
                int rowA = rowA0 + mt * 16;
                int ch = (2 * kk + chA0) ^ (rowA & 7);
                ldsm4(ah[mt], st + (uint32_t)(rowA * 128 + ch * 16));
            }
            uint32_t bh[8];
            #pragma unroll
            for (int go = 0; go < 2; go++) {
                int rr = rowB0 + go * 16;
                int cs = (2 * kk + chB0) ^ (rr & 7);
                ldsm4(&bh[go * 4], st + 8192 + (uint32_t)(rr * 128 + cs * 16));
            }
            #pragma unroll
            for (int mt = 0; mt < 2; mt++)
                #pragma unroll
                for (int nt = 0; nt < 4; nt++)
                    mma_f16(dacc[mt][nt], ah[mt], bh[nt * 2], bh[nt * 2 + 1]);
        }

        mbar_arrive(mb + (NSTG + s) * 8);
        if (tid == 0 && it + NSTG < NKT) {
            mbar_wait(mb + (NSTG + s) * 8, q & 1);
            issue_stage(it + NSTG);
        }
    }

    // ---- epilogue: GLU + residual ----
    __syncthreads();                 // pipeline smem free for reuse
    float* sig = (float*)smb;        // [64][68] padded

    if (wn >= 2) {                   // g-gate warps (cols 64..127)
        #pragma unroll
        for (int mt = 0; mt < 2; mt++) {
            #pragma unroll
            for (int nt = 0; nt < 4; nt++) {
                int gcol = (wn - 2) * 32 + nt * 8 + tig * 2;
                float bg0 = bo[DM + c0 + gcol];
                float bg1 = bo[DM + c0 + gcol + 1];
                #pragma unroll
                for (int half = 0; half < 2; half++) {
                    int ml = wm * 32 + mt * 16 + grp + half * 8;
                    float g0 = dacc[mt][nt][half * 2 + 0] + bg0;
                    float g1 = dacc[mt][nt][half * 2 + 1] + bg1;
                    sig[ml * 68 + gcol]     = 1.0f / (1.0f + expf(-g0));
                    sig[ml * 68 + gcol + 1] = 1.0f / (1.0f + expf(-g1));
                }
            }
        }
    }
    __syncthreads();
    if (wn < 2) {                    // a-gate warps (cols 0..63)
        #pragma unroll
        for (int mt = 0; mt < 2; mt++) {
            #pragma unroll
            for (int nt = 0; nt < 4; nt++) {
                int col = wn * 32 + nt * 8 + tig * 2;
                float ba0 = bo[c0 + col];
                float ba1 = bo[c0 + col + 1];
                #pragma unroll
                for (int half = 0; half < 2; half++) {
                    int ml = wm * 32 + mt * 16 + grp + half * 8;
                    int r = m0 + ml;
                    float a0 = dacc[mt][nt][half * 2 + 0] + ba0;
                    float a1 = dacc[mt][nt][half * 2 + 1] + ba1;
                    float s0 = sig[ml * 68 + col];
                    float s1 = sig[ml * 68 + col + 1];
                    float2 res = *(const float2*)(resid + (size_t)r * DM + c0 + col);
                    float2 o;
                    o.x = res.x + a0 * s0;
                    o.y = res.y + a1 * s1;
                    *(float2*)(out + (size_t)r * DM + c0 + col) = o;
                }
            }
        }
    }
}

// ---------------------------------------------------------------------------
extern "C" void kernel_launch(void* const* d_in, const int* in_sizes, int n_in,
                              void* d_out, int out_size) {
    const float* x      = (const float*)d_in[0];
    const float* emb    = (const float*)d_in[1];
    const float* A_real = (const float*)d_in[2];
    const float* A_imag = (const float*)d_in[3];
    const float* C      = (const float*)d_in[4];
    const float* log_dt = (const float*)d_in[5];
    const float* B_ssm  = (const float*)d_in[6];
    const float* D_skip = (const float*)d_in[7];
    const float* ln_g   = (const float*)d_in[8];
    const float* ln_b   = (const float*)d_in[9];
    const float* W_out  = (const float*)d_in[10];
    const float* b_out  = (const float*)d_in[11];
    const float* W_film = (const float*)d_in[12];
    const float* b_film = (const float*)d_in[13];
    float* out = (float*)d_out;

    static bool configured = false;
    if (!configured) {
        cudaFuncSetAttribute(gemm_glu_tc,
                             cudaFuncAttributeMaxDynamicSharedMemorySize,
                             GSM_BYTES);
        configured = true;
    }

    ln_kernel<<<BSZ * LSEQ, 128>>>(x, ln_g, ln_b);
    film_kernel<<<BSZ, 256>>>(emb, W_film, b_film);
    prep_w<<<256, 256>>>(W_out);
    scan_local<<<BSZ * (DM / 16) * CHK, 128>>>(A_real, A_imag, C, log_dt, B_ssm, D_skip);
    scan_fixup<<<BSZ * (DM / 16) * (CHK - 1), 128>>>(A_real, A_imag, C, log_dt, B_ssm);
    gemm_glu_tc<<<dim3((BSZ * LSEQ) / 64, DM / 64), 256, GSM_BYTES>>>(b_out, x, out);
}

// round 12
// speedup vs baseline: 1.8141x; 1.1602x over previous
#include <cuda_runtime.h>
#include <cuda_fp16.h>
#include <math.h>
#include <stdint.h>

#define BSZ 8
#define LSEQ 2048
#define DM 512
#define NS 64
#define EMB 512
#define TCH 128           // chunk length
#define NCH 16            // chunks (LSEQ/TCH)
#define NCOL 128          // (b, chunk) columns = BSZ*NCH

typedef unsigned long long ull;
typedef unsigned short us;

// ---------------------------------------------------------------------------
// Global scratch (allocation-free rule). fp16 matrices stored per-d as
// [128 rows][128 k] with 256B rows, 16B chunks swizzled: chunk ^= (row & 7).
// ---------------------------------------------------------------------------
__device__ __align__(1024) float g_xn[BSZ * LSEQ * DM];        // LN output f32
__device__ __align__(1024) us g_Xt[DM * 128 * 128];            // x, d-major [col][j]
__device__ __align__(1024) us g_KT[DM * 128 * 128];            // Toeplitz(K) [i][j]
__device__ __align__(1024) us g_V [DM * 128 * 128];            // state mat [n2][j]
__device__ __align__(1024) us g_U [DM * 128 * 128];            // tail mat [i][n2]
__device__ __align__(1024) us g_y2h[BSZ * LSEQ * DM];          // y fp16, GEMM-A tiled
__device__ __align__(1024) us g_Wh[2 * DM * DM];               // W fp16, tiled
__device__ float g_film[BSZ * 2 * DM];

// tiled+swizzled element offset into g_y2h (A-layout for final GEMM)
__device__ __forceinline__ size_t a_tiled_off(int m, int d) {
    int row = m & 127;
    int chunk = ((d & 63) >> 3) ^ (row & 7);
    return ((size_t)((m >> 7) * 8 + (d >> 6)) << 13)
         + (size_t)row * 64 + (chunk << 3) + (d & 7);
}

// swizzled us index inside a per-d [128][128] fp16 matrix
__device__ __forceinline__ int tswz(int r, int e) {
    return r * 128 + (((e >> 3) ^ (r & 7)) << 3) + (e & 7);
}

// mbarrier helpers
__device__ __forceinline__ void mbar_init(uint32_t a, uint32_t cnt) {
    asm volatile("mbarrier.init.shared.b64 [%0], %1;" :: "r"(a), "r"(cnt) : "memory");
}
__device__ __forceinline__ void mbar_expect_tx(uint32_t a, uint32_t tx) {
    asm volatile("mbarrier.arrive.expect_tx.shared.b64 _, [%0], %1;" :: "r"(a), "r"(tx) : "memory");
}
__device__ __forceinline__ void mbar_arrive(uint32_t a) {
    asm volatile("mbarrier.arrive.shared.b64 _, [%0];" :: "r"(a) : "memory");
}
__device__ __forceinline__ void mbar_wait(uint32_t a, int parity) {
    asm volatile(
        "{\n\t.reg .pred P;\n"
        "LW_%=:\n\t"
        "mbarrier.try_wait.parity.acquire.cta.shared::cta.b64 P, [%0], %1, 0x989680;\n\t"
        "@P bra.uni LD_%=;\n\t"
        "bra.uni LW_%=;\n"
        "LD_%=:\n\t}"
        :: "r"(a), "r"(parity) : "memory");
}
__device__ __forceinline__ void bulk_cp(uint32_t dst, const void* src,
                                        uint32_t bytes, uint32_t mbar) {
    asm volatile(
        "cp.async.bulk.shared::cta.global.mbarrier::complete_tx::bytes [%0], [%1], %2, [%3];"
        :: "r"(dst), "l"(src), "r"(bytes), "r"(mbar) : "memory");
}

__device__ __forceinline__ void mma_f16(float d[4], const uint32_t a[4],
                                        const uint32_t b0, const uint32_t b1) {
    asm volatile(
        "mma.sync.aligned.m16n8k16.row.col.f32.f16.f16.f32 "
        "{%0,%1,%2,%3}, {%4,%5,%6,%7}, {%8,%9}, {%0,%1,%2,%3};\n"
        : "+f"(d[0]), "+f"(d[1]), "+f"(d[2]), "+f"(d[3])
        : "r"(a[0]), "r"(a[1]), "r"(a[2]), "r"(a[3]), "r"(b0), "r"(b1));
}
__device__ __forceinline__ void ldsm4(uint32_t* r, uint32_t byteaddr) {
    asm volatile("ldmatrix.sync.aligned.m8n8.x4.shared.b16 {%0,%1,%2,%3}, [%4];"
        : "=r"(r[0]), "=r"(r[1]), "=r"(r[2]), "=r"(r[3]) : "r"(byteaddr));
}

// ---------------------------------------------------------------------------
// Kernel 1: LayerNorm  (writes f32 g_xn)
// ---------------------------------------------------------------------------
__global__ void ln_kernel(const float* __restrict__ x,
                          const float* __restrict__ gamma,
                          const float* __restrict__ beta) {
    const int row = blockIdx.x;
    const int t = threadIdx.x;
    const float4* xr = (const float4*)(x + (size_t)row * DM);
    float4 v = xr[t];
    float s  = v.x + v.y + v.z + v.w;
    float ss = v.x * v.x + v.y * v.y + v.z * v.z + v.w * v.w;

    __shared__ float sh[8];
    #pragma unroll
    for (int o = 16; o; o >>= 1) {
        s  += __shfl_xor_sync(0xffffffffu, s, o);
        ss += __shfl_xor_sync(0xffffffffu, ss, o);
    }
    int w = t >> 5;
    if ((t & 31) == 0) { sh[w] = s; sh[4 + w] = ss; }
    __syncthreads();
    float S  = sh[0] + sh[1] + sh[2] + sh[3];
    float SS = sh[4] + sh[5] + sh[6] + sh[7];

    const float inv = 1.0f / (float)DM;
    float mu = S * inv;
    float var = SS * inv - mu * mu;
    float rs = rsqrtf(var + 1e-5f);

    float4 g4 = ((const float4*)gamma)[t];
    float4 b4 = ((const float4*)beta)[t];
    float4 o4;
    o4.x = (v.x - mu) * rs * g4.x + b4.x;
    o4.y = (v.y - mu) * rs * g4.y + b4.y;
    o4.z = (v.z - mu) * rs * g4.z + b4.z;
    o4.w = (v.w - mu) * rs * g4.w + b4.w;
    ((float4*)(g_xn + (size_t)row * DM))[t] = o4;
}

// ---------------------------------------------------------------------------
// Kernel 2: FiLM params
// ---------------------------------------------------------------------------
__global__ void film_kernel(const float* __restrict__ emb,
                            const float* __restrict__ Wf,
                            const float* __restrict__ bf) {
    __shared__ float se[EMB];
    const int b = blockIdx.x;
    for (int i = threadIdx.x; i < EMB; i += blockDim.x) {
        float e = emb[b * EMB + i];
        se[i] = e / (1.0f + expf(-e));
    }
    __syncthreads();
    for (int j = threadIdx.x; j < 2 * DM; j += blockDim.x) {
        const float4* wr = (const float4*)(Wf + (size_t)j * EMB);
        const float4* sr = (const float4*)se;
        float acc = bf[j];
        #pragma unroll 4
        for (int q = 0; q < EMB / 4; q++) {
            float4 w = wr[q], sv = sr[q];
            acc += w.x * sv.x + w.y * sv.y + w.z * sv.z + w.w * sv.w;
        }
        g_film[b * 2 * DM + j] = acc;
    }
}

// ---------------------------------------------------------------------------
// Kernel 2b: W -> fp16, TILED (64x64 tiles, 128B rows, swizzled)
// ---------------------------------------------------------------------------
__global__ void prep_w(const float* __restrict__ W) {
    int i = blockIdx.x * blockDim.x + threadIdx.x;   // 0 .. 65535
    int r = i >> 6;
    int kc = i & 63;
    const float* src = W + (size_t)r * DM + kc * 8;
    float4 v0 = *(const float4*)src;
    float4 v1 = *(const float4*)(src + 4);
    float e[8] = {v0.x, v0.y, v0.z, v0.w, v1.x, v1.y, v1.z, v1.w};
    uint32_t hw[4];
    #pragma unroll
    for (int j = 0; j < 4; j++) {
        us h0 = __half_as_ushort(__float2half_rn(e[j * 2]));
        us h1 = __half_as_ushort(__float2half_rn(e[j * 2 + 1]));
        hw[j] = (uint32_t)h0 | ((uint32_t)h1 << 16);
    }
    int row = r & 63;
    int chunk = (kc & 7) ^ (row & 7);
    size_t off = ((size_t)((r >> 6) * 8 + (kc >> 3)) << 12)
               + (size_t)row * 64 + (chunk << 3);
    *(uint4*)(g_Wh + off) = make_uint4(hw[0], hw[1], hw[2], hw[3]);
}

// ---------------------------------------------------------------------------
// Kernel 3: transpose x -> g_Xt (per-d [col=(b,c)][j], fp16, swizzled rows)
// grid = 8b x 16c x 16 dgroups of 32
// ---------------------------------------------------------------------------
__global__ void xt_kernel() {
    const int blk = blockIdx.x;
    const int b = blk >> 8;
    const int c = (blk >> 4) & 15;
    const int dg = blk & 15;
    const int d0 = dg * 32;
    const int t = threadIdx.x;   // 256

    __shared__ float tile[128][33];
    #pragma unroll
    for (int it = 0; it < 16; it++) {
        int flat = t + it * 256;      // 4096
        int j = flat >> 5, dd = flat & 31;
        tile[j][dd] = g_xn[((size_t)(b * 2048 + c * 128 + j)) * DM + d0 + dd];
    }
    __syncthreads();

    const int r = b * 16 + c;
    #pragma unroll
    for (int it = 0; it < 2; it++) {
        int flat = t + it * 256;      // 512 = 32dd x 16ch
        int dd = flat >> 4, ch = flat & 15;
        us h8[8];
        #pragma unroll
        for (int e = 0; e < 8; e++)
            h8[e] = __half_as_ushort(__float2half_rn(tile[ch * 8 + e][dd]));
        us* dst = g_Xt + (size_t)(d0 + dd) * 16384 + r * 128 + ((ch ^ (r & 7)) << 3);
        *(uint4*)dst = *(const uint4*)h8;
    }
}

// ---------------------------------------------------------------------------
// Kernel 4: per-d matrix builder: K-Toeplitz, V (states), U (tail).
// 512 blocks (one per d), 128 threads.
// ---------------------------------------------------------------------------
__global__ void mats_kernel(const float* __restrict__ A_real,
                            const float* __restrict__ A_imag,
                            const float* __restrict__ Cp,
                            const float* __restrict__ log_dt,
                            const float* __restrict__ B_ssm,
                            const float* __restrict__ D_skip) {
    const int d = blockIdx.x;
    const int t = threadIdx.x;
    const float dt = expf(log_dt[d]);

    __shared__ float sP[2][128];
    __shared__ float sK[128];
    __shared__ us sM[128 * 128];

    float lr = 0.f, li = 0.f, ccr = 0.f, cci = 0.f;
    if (t < 64) {
        float ar = dt * A_real[d * NS + t];
        float ai = dt * A_imag[d * NS + t];
        float er = expf(ar), sb, cb;
        sincosf(ai, &sb, &cb);
        lr = er * cb; li = er * sb;
        float bs = B_ssm[d * NS + t];
        ccr = Cp[(d * NS + t) * 2 + 0] * bs;
        cci = Cp[(d * NS + t) * 2 + 1] * bs;
    }

    // ---- K[delta] = dt * sum_n Re(Cc * lam^delta) ----
    if (t < 64) {
        float pr = ccr, pi = cci;
        const int w = t >> 5;
        for (int del = 0; del < 128; del++) {
            float v = pr;
            #pragma unroll
            for (int o = 16; o; o >>= 1)
                v += __shfl_xor_sync(0xffffffffu, v, o);
            if ((t & 31) == 0) sP[w][del] = v;
            float nr = pr * lr - pi * li;
            pi = pr * li + pi * lr;
            pr = nr;
        }
    }
    __syncthreads();
    {
        float kv = dt * (sP[0][t] + sP[1][t]);
        if (t == 0) kv += D_skip[d];
        sK[t] = kv;
    }
    __syncthreads();

    // ---- Toeplitz fill + writeout ----
    for (int j = 0; j < 128; j++)
        sM[t * 128 + j] = __half_as_ushort(
            __float2half_rn(j <= t ? sK[t - j] : 0.0f));
    __syncthreads();
    {
        us* g = g_KT + (size_t)d * 16384;
        #pragma unroll
        for (int ch = 0; ch < 16; ch++) {
            uint4 v = *(const uint4*)&sM[t * 128 + ch * 8];
            *(uint4*)(g + t * 128 + ((ch ^ (t & 7)) << 3)) = v;
        }
    }
    __syncthreads();

    // ---- V: rows n (Re), n+64 (Im): V[n][j] = lam^(127-j) ----
    if (t < 64) {
        float pr = 1.0f, pi = 0.0f;
        for (int jj = 0; jj < 128; jj++) {
            int j = 127 - jj;
            sM[t * 128 + j] = __half_as_ushort(__float2half_rn(pr));
            sM[(t + 64) * 128 + j] = __half_as_ushort(__float2half_rn(pi));
            float nr = pr * lr - pi * li;
            pi = pr * li + pi * lr;
            pr = nr;
        }
    }
    __syncthreads();
    {
        us* g = g_V + (size_t)d * 16384;
        #pragma unroll
        for (int ch = 0; ch < 16; ch++) {
            uint4 v = *(const uint4*)&sM[t * 128 + ch * 8];
            *(uint4*)(g + t * 128 + ((ch ^ (t & 7)) << 3)) = v;
        }
    }
    __syncthreads();

    // ---- U: U[i][n] = dt*Re(Cc lam^(i+1)), U[i][n+64] = -dt*Im(...) ----
    if (t < 64) {
        float pr = ccr * lr - cci * li;
        float pi = ccr * li + cci * lr;
        for (int i = 0; i < 128; i++) {
            sM[i * 128 + t] = __half_as_ushort(__float2half_rn(dt * pr));
            sM[i * 128 + t + 64] = __half_as_ushort(__float2half_rn(-dt * pi));
            float nr = pr * lr - pi * li;
            pi = pr * li + pi * lr;
            pr = nr;
        }
    }
    __syncthreads();
    {
        us* g = g_U + (size_t)d * 16384;
        #pragma unroll
        for (int ch = 0; ch < 16; ch++) {
            uint4 v = *(const uint4*)&sM[t * 128 + ch * 8];
            *(uint4*)(g + t * 128 + ((ch ^ (t & 7)) << 3)) = v;
        }
    }
}

// ---------------------------------------------------------------------------
// Kernel 5: per-d fused conv: S = V*X; Horner -> SIn; Y = KT*X + U*SIn;
// FiLM epilogue; scatter to g_y2h (A-tiled). 512 CTAs (d), 256 threads.
// SMEM: X 32K | A0 32K | A1 32K | S/Y 64K f32 | SIn 32K  = 192K dynamic.
// ---------------------------------------------------------------------------
#define CV_X   0
#define CV_A0  32768
#define CV_A1  65536
#define CV_S   98304
#define CV_SIN 163840
#define CV_BYTES 196608

__global__ void __launch_bounds__(256, 1)
conv_kernel(const float* __restrict__ A_real,
            const float* __restrict__ A_imag,
            const float* __restrict__ log_dt) {
    extern __shared__ __align__(1024) char smb[];
    __shared__ uint64_t cmb[2];
    const uint32_t sbs = (uint32_t)__cvta_generic_to_shared(smb);
    const uint32_t mb = (uint32_t)__cvta_generic_to_shared(cmb);

    const int d = blockIdx.x;
    const int tid = threadIdx.x;
    const int warp = tid >> 5, lane = tid & 31;
    const int wm = warp & 3;          // 4 x 32 m-rows
    const int wn = warp >> 2;         // 2 x 64 n-cols
    const int grp = lane >> 2, tig = lane & 3;

    if (tid == 0) {
        mbar_init(mb, 1);
        mbar_init(mb + 8, 1);
    }
    __syncthreads();

    if (tid == 0) {
        mbar_expect_tx(mb, 65536);
        bulk_cp(sbs + CV_X,  (const char*)g_Xt + (size_t)d * 32768, 32768, mb);
        bulk_cp(sbs + CV_A0, (const char*)g_V  + (size_t)d * 32768, 32768, mb);
        mbar_expect_tx(mb + 8, 32768);
        bulk_cp(sbs + CV_A1, (const char*)g_KT + (size_t)d * 32768, 32768, mb + 8);
    }

    float* sYf = (float*)(smb + CV_S);

    // ---- GEMM helper: acc += A[128x128] * B[128(col) x 128(k)] ----
    auto run_gemm = [&](uint32_t abase, uint32_t bbase, float acc[2][8][4]) {
        #pragma unroll 2
        for (int kk = 0; kk < 8; kk++) {
            uint32_t a[2][4];
            #pragma unroll
            for (int mt = 0; mt < 2; mt++) {
                int rowA = wm * 32 + mt * 16 + (lane & 15);
                int kc = kk * 2 + ((lane & 16) >> 4);
                ldsm4(a[mt], abase + (uint32_t)(rowA * 256 + (((kc) ^ (rowA & 7)) << 4)));
            }
            uint32_t bh[4][4];
            #pragma unroll
            for (int bb = 0; bb < 4; bb++) {
                int rowB = wn * 64 + bb * 16 + ((lane & 16) >> 1) + (lane & 7);
                int kcb = kk * 2 + ((lane >> 3) & 1);
                ldsm4(bh[bb], bbase + (uint32_t)(rowB * 256 + (((kcb) ^ (rowB & 7)) << 4)));
            }
            #pragma unroll
            for (int mt = 0; mt < 2; mt++)
                #pragma unroll
                for (int bb = 0; bb < 4; bb++) {
                    mma_f16(acc[mt][bb * 2 + 0], a[mt], bh[bb][0], bh[bb][1]);
                    mma_f16(acc[mt][bb * 2 + 1], a[mt], bh[bb][2], bh[bb][3]);
                }
        }
    };
    auto store_frags = [&](float acc[2][8][4]) {
        #pragma unroll
        for (int mt = 0; mt < 2; mt++)
            #pragma unroll
            for (int nt = 0; nt < 8; nt++) {
                int r0 = wm * 32 + mt * 16 + grp;
                int c0 = wn * 64 + nt * 8 + tig * 2;
                *(float2*)&sYf[r0 * 128 + c0] =
                    make_float2(acc[mt][nt][0], acc[mt][nt][1]);
                *(float2*)&sYf[(r0 + 8) * 128 + c0] =
                    make_float2(acc[mt][nt][2], acc[mt][nt][3]);
            }
    };

    float acc[2][8][4];
    #pragma unroll
    for (int mt = 0; mt < 2; mt++)
        #pragma unroll
        for (int nt = 0; nt < 8; nt++)
            #pragma unroll
            for (int r = 0; r < 4; r++) acc[mt][nt][r] = 0.0f;

    // ---- Phase 1: S = V * X ----
    mbar_wait(mb, 0);
    run_gemm(sbs + CV_A0, sbs + CV_X, acc);
    store_frags(acc);
    __syncthreads();

    if (tid == 0) {
        mbar_expect_tx(mb, 32768);
        bulk_cp(sbs + CV_A0, (const char*)g_U + (size_t)d * 32768, 32768, mb);
    }

    // ---- Glue: Horner over chunks -> SIn fp16 [col][n2] swizzled ----
    {
        const float dt = expf(log_dt[d]);
        us* sIn = (us*)(smb + CV_SIN);
        #pragma unroll
        for (int it = 0; it < 2; it++) {
            int idx = tid + it * 256;       // 512 tasks
            int n = idx & 63, b = idx >> 6;
            float ar = dt * A_real[d * NS + n];
            float ai = dt * A_imag[d * NS + n];
            float er = expf(ar), sb, cb;
            sincosf(ai, &sb, &cb);
            float pr = er * cb, pi = er * sb;
            #pragma unroll
            for (int q = 0; q < 7; q++) {   // lam^128
                float nr = pr * pr - pi * pi;
                pi = 2.0f * pr * pi;
                pr = nr;
            }
            float runr = 0.0f, runi = 0.0f;
            for (int c = 0; c < NCH; c++) {
                int col = b * 16 + c;
                sIn[tswz(col, n)]      = __half_as_ushort(__float2half_rn(runr));
                sIn[tswz(col, n + 64)] = __half_as_ushort(__float2half_rn(runi));
                float s_re = sYf[n * 128 + col];
                float s_im = sYf[(n + 64) * 128 + col];
                float nr = pr * runr - pi * runi + s_re;
                runi = pr * runi + pi * runr + s_im;
                runr = nr;
            }
        }
    }
    __syncthreads();

    // ---- Phase 2+3: Y = KT*X + U*SIn ----
    #pragma unroll
    for (int mt = 0; mt < 2; mt++)
        #pragma unroll
        for (int nt = 0; nt < 8; nt++)
            #pragma unroll
            for (int r = 0; r < 4; r++) acc[mt][nt][r] = 0.0f;

    mbar_wait(mb + 8, 0);
    run_gemm(sbs + CV_A1, sbs + CV_X, acc);
    mbar_wait(mb, 1);
    run_gemm(sbs + CV_A0, sbs + CV_SIN, acc);
    store_frags(acc);
    __syncthreads();

    // ---- Epilogue: FiLM + scatter into g_y2h (A-tiled fp16) ----
    {
        int col = tid & 127;
        int ib = tid >> 7;
        int b = col >> 4;
        float mult  = 1.0f + g_film[b * 2 * DM + d];
        float shift = g_film[b * 2 * DM + DM + d];
        size_t tbase = ((size_t)(col * 8 + (d >> 6)) << 13) + (d & 7);
        int dch = (d & 63) >> 3;
        #pragma unroll 4
        for (int ii = 0; ii < 64; ii++) {
            int i = ib * 64 + ii;
            float v = sYf[i * 128 + col] * mult + shift;
            g_y2h[tbase + i * 64 + ((dch ^ (i & 7)) << 3)] =
                __half_as_ushort(__float2half_rn(v));
        }
    }
}

// ---------------------------------------------------------------------------
// Kernel 6: out_proj GEMM, mma.sync f16 single-pass (unchanged from R10/11).
// ---------------------------------------------------------------------------
#define GSTG 24576
#define NSTG 2
#define GSM_BYTES (NSTG * GSTG)

__global__ void __launch_bounds__(256, 2)
gemm_glu_tc(const float* __restrict__ bo,
            const float* __restrict__ resid,
            float* __restrict__ out) {
    extern __shared__ __align__(1024) char smb[];
    __shared__ uint64_t mbar_store[2 * NSTG];
    const uint32_t sbs = (uint32_t)__cvta_generic_to_shared(smb);
    const uint32_t mb = (uint32_t)__cvta_generic_to_shared(mbar_store);

    const int tid = threadIdx.x;
    const int mblk = blockIdx.x;
    const int cblk = blockIdx.y;
    const int m0 = mblk * 64;
    const int c0 = cblk * 64;
    const int warp = tid >> 5, lane = tid & 31;
    const int wm = warp >> 2;
    const int wn = warp & 3;
    const int grp = lane >> 2, tig = lane & 3;

    if (tid == 0) {
        #pragma unroll
        for (int s = 0; s < NSTG; s++) {
            mbar_init(mb + s * 8, 1);
            mbar_init(mb + (NSTG + s) * 8, 256);
        }
    }
    __syncthreads();

    const size_t mtile = mblk >> 1;
    const size_t ahalf = (size_t)(mblk & 1) * 8192;

    auto issue_stage = [&](int it) {
        int s = it & 1;
        uint32_t full = mb + s * 8;
        mbar_expect_tx(full, GSTG);
        uint32_t st = sbs + s * GSTG;
        bulk_cp(st,         (const char*)g_y2h + ((mtile * 8 + it) << 14) + ahalf, 8192, full);
        bulk_cp(st + 8192,  (const char*)g_Wh + (((size_t)cblk * 8 + it) << 13), 8192, full);
        bulk_cp(st + 16384, (const char*)g_Wh + (((size_t)(8 + cblk) * 8 + it) << 13), 8192, full);
    };

    if (tid == 0) { issue_stage(0); issue_stage(1); }

    float dacc[2][4][4];
    #pragma unroll
    for (int mt = 0; mt < 2; mt++)
        #pragma unroll
        for (int nt = 0; nt < 4; nt++)
            #pragma unroll
            for (int r = 0; r < 4; r++) dacc[mt][nt][r] = 0.0f;

    const int rowA0 = wm * 32 + (lane & 15);
    const int chA0 = lane >> 4;
    const int rowB0 = wn * 32 + ((lane & 16) >> 1) + (lane & 7);
    const int chB0 = (lane >> 3) & 1;

    const int NKT = 8;
    for (int it = 0; it < NKT; it++) {
        const int s = it & 1;
        const int q = it >> 1;
        mbar_wait(mb + s * 8, q & 1);
        const uint32_t st = sbs + s * GSTG;

        #pragma unroll
        for (int kk = 0; kk < 4; kk++) {
            uint32_t ah[2][4];
            #pragma unroll
            for (int mt = 0; mt < 2; mt++) {
                int rowA = rowA0 + mt * 16;
                int ch = (2 * kk + chA0) ^ (rowA & 7);
                ldsm4(ah[mt], st + (uint32_t)(rowA * 128 + ch * 16));
            }
            uint32_t bh[8];
            #pragma unroll
            for (int go = 0; go < 2; go++) {
                int rr = rowB0 + go * 16;
                int cs = (2 * kk + chB0) ^ (rr & 7);
                ldsm4(&bh[go * 4], st + 8192 + (uint32_t)(rr * 128 + cs * 16));
            }
            #pragma unroll
            for (int mt = 0; mt < 2; mt++)
                #pragma unroll
                for (int nt = 0; nt < 4; nt++)
                    mma_f16(dacc[mt][nt], ah[mt], bh[nt * 2], bh[nt * 2 + 1]);
        }

        mbar_arrive(mb + (NSTG + s) * 8);
        if (tid == 0 && it + NSTG < NKT) {
            mbar_wait(mb + (NSTG + s) * 8, q & 1);
            issue_stage(it + NSTG);
        }
    }

    __syncthreads();
    float* sig = (float*)smb;

    if (wn >= 2) {
        #pragma unroll
        for (int mt = 0; mt < 2; mt++) {
            #pragma unroll
            for (int nt = 0; nt < 4; nt++) {
                int gcol = (wn - 2) * 32 + nt * 8 + tig * 2;
                float bg0 = bo[DM + c0 + gcol];
                float bg1 = bo[DM + c0 + gcol + 1];
                #pragma unroll
                for (int half = 0; half < 2; half++) {
                    int ml = wm * 32 + mt * 16 + grp + half * 8;
                    float g0 = dacc[mt][nt][half * 2 + 0] + bg0;
                    float g1 = dacc[mt][nt][half * 2 + 1] + bg1;
                    sig[ml * 68 + gcol]     = 1.0f / (1.0f + expf(-g0));
                    sig[ml * 68 + gcol + 1] = 1.0f / (1.0f + expf(-g1));
                }
            }
        }
    }
    __syncthreads();
    if (wn < 2) {
        #pragma unroll
        for (int mt = 0; mt < 2; mt++) {
            #pragma unroll
            for (int nt = 0; nt < 4; nt++) {
                int col = wn * 32 + nt * 8 + tig * 2;
                float ba0 = bo[c0 + col];
                float ba1 = bo[c0 + col + 1];
                #pragma unroll
                for (int half = 0; half < 2; half++) {
                    int ml = wm * 32 + mt * 16 + grp + half * 8;
                    int r = m0 + ml;
                    float a0 = dacc[mt][nt][half * 2 + 0] + ba0;
                    float a1 = dacc[mt][nt][half * 2 + 1] + ba1;
                    float s0 = sig[ml * 68 + col];
                    float s1 = sig[ml * 68 + col + 1];
                    float2 res = *(const float2*)(resid + (size_t)r * DM + c0 + col);
                    float2 o;
                    o.x = res.x + a0 * s0;
                    o.y = res.y + a1 * s1;
                    *(float2*)(out + (size_t)r * DM + c0 + col) = o;
                }
            }
        }
    }
}

// ---------------------------------------------------------------------------
extern "C" void kernel_launch(void* const* d_in, const int* in_sizes, int n_in,
                              void* d_out, int out_size) {
    const float* x      = (const float*)d_in[0];
    const float* emb    = (const float*)d_in[1];
    const float* A_real = (const float*)d_in[2];
    const float* A_imag = (const float*)d_in[3];
    const float* C      = (const float*)d_in[4];
    const float* log_dt = (const float*)d_in[5];
    const float* B_ssm  = (const float*)d_in[6];
    const float* D_skip = (const float*)d_in[7];
    const float* ln_g   = (const float*)d_in[8];
    const float* ln_b   = (const float*)d_in[9];
    const float* W_out  = (const float*)d_in[10];
    const float* b_out  = (const float*)d_in[11];
    const float* W_film = (const float*)d_in[12];
    const float* b_film = (const float*)d_in[13];
    float* out = (float*)d_out;

    static bool configured = false;
    if (!configured) {
        cudaFuncSetAttribute(gemm_glu_tc,
                             cudaFuncAttributeMaxDynamicSharedMemorySize,
                             GSM_BYTES);
        cudaFuncSetAttribute(conv_kernel,
                             cudaFuncAttributeMaxDynamicSharedMemorySize,
                             CV_BYTES);
        configured = true;
    }

    ln_kernel<<<BSZ * LSEQ, 128>>>(x, ln_g, ln_b);
    film_kernel<<<BSZ, 256>>>(emb, W_film, b_film);
    prep_w<<<256, 256>>>(W_out);
    mats_kernel<<<DM, 128>>>(A_real, A_imag, C, log_dt, B_ssm, D_skip);
    xt_kernel<<<BSZ * NCH * 16, 256>>>();
    conv_kernel<<<DM, 256, CV_BYTES>>>(A_real, A_imag, log_dt);
    gemm_glu_tc<<<dim3((BSZ * LSEQ) / 64, DM / 64), 256, GSM_BYTES>>>(b_out, x, out);
}

// round 13
// speedup vs baseline: 2.0206x; 1.1138x over previous
#include <cuda_runtime.h>
#include <cuda_fp16.h>
#include <math.h>
#include <stdint.h>

#define BSZ 8
#define LSEQ 2048
#define DM 512
#define NS 64
#define EMB 512
#define TCH 128           // chunk length
#define NCH 16            // chunks (LSEQ/TCH)

typedef unsigned long long ull;
typedef unsigned short us;

// ---------------------------------------------------------------------------
// Global scratch. fp16 matrices stored per-d as [128 rows][128 k] with 256B
// rows, 16B chunks swizzled: chunk ^= (row & 7).
// ---------------------------------------------------------------------------
__device__ __align__(1024) float g_xn[BSZ * LSEQ * DM];
__device__ __align__(1024) us g_Xt[DM * 128 * 128];
__device__ __align__(1024) us g_KT[DM * 128 * 128];
__device__ __align__(1024) us g_V [DM * 128 * 128];
__device__ __align__(1024) us g_U [DM * 128 * 128];
__device__ __align__(1024) us g_y2h[BSZ * LSEQ * DM];
__device__ __align__(1024) us g_Wh[2 * DM * DM];
__device__ float g_film[BSZ * 2 * DM];

__device__ __forceinline__ int tswz(int r, int e) {
    return r * 128 + (((e >> 3) ^ (r & 7)) << 3) + (e & 7);
}

// mbarrier helpers
__device__ __forceinline__ void mbar_init(uint32_t a, uint32_t cnt) {
    asm volatile("mbarrier.init.shared.b64 [%0], %1;" :: "r"(a), "r"(cnt) : "memory");
}
__device__ __forceinline__ void mbar_expect_tx(uint32_t a, uint32_t tx) {
    asm volatile("mbarrier.arrive.expect_tx.shared.b64 _, [%0], %1;" :: "r"(a), "r"(tx) : "memory");
}
__device__ __forceinline__ void mbar_arrive(uint32_t a) {
    asm volatile("mbarrier.arrive.shared.b64 _, [%0];" :: "r"(a) : "memory");
}
__device__ __forceinline__ void mbar_wait(uint32_t a, int parity) {
    asm volatile(
        "{\n\t.reg .pred P;\n"
        "LW_%=:\n\t"
        "mbarrier.try_wait.parity.acquire.cta.shared::cta.b64 P, [%0], %1, 0x989680;\n\t"
        "@P bra.uni LD_%=;\n\t"
        "bra.uni LW_%=;\n"
        "LD_%=:\n\t}"
        :: "r"(a), "r"(parity) : "memory");
}
__device__ __forceinline__ void bulk_cp(uint32_t dst, const void* src,
                                        uint32_t bytes, uint32_t mbar) {
    asm volatile(
        "cp.async.bulk.shared::cta.global.mbarrier::complete_tx::bytes [%0], [%1], %2, [%3];"
        :: "r"(dst), "l"(src), "r"(bytes), "r"(mbar) : "memory");
}

__device__ __forceinline__ void mma_f16(float d[4], const uint32_t a[4],
                                        const uint32_t b0, const uint32_t b1) {
    asm volatile(
        "mma.sync.aligned.m16n8k16.row.col.f32.f16.f16.f32 "
        "{%0,%1,%2,%3}, {%4,%5,%6,%7}, {%8,%9}, {%0,%1,%2,%3};\n"
        : "+f"(d[0]), "+f"(d[1]), "+f"(d[2]), "+f"(d[3])
        : "r"(a[0]), "r"(a[1]), "r"(a[2]), "r"(a[3]), "r"(b0), "r"(b1));
}
__device__ __forceinline__ void ldsm4(uint32_t* r, uint32_t byteaddr) {
    asm volatile("ldmatrix.sync.aligned.m8n8.x4.shared.b16 {%0,%1,%2,%3}, [%4];"
        : "=r"(r[0]), "=r"(r[1]), "=r"(r[2]), "=r"(r[3]) : "r"(byteaddr));
}

// ---------------------------------------------------------------------------
// Kernel 1: LayerNorm
// ---------------------------------------------------------------------------
__global__ void ln_kernel(const float* __restrict__ x,
                          const float* __restrict__ gamma,
                          const float* __restrict__ beta) {
    const int row = blockIdx.x;
    const int t = threadIdx.x;
    const float4* xr = (const float4*)(x + (size_t)row * DM);
    float4 v = xr[t];
    float s  = v.x + v.y + v.z + v.w;
    float ss = v.x * v.x + v.y * v.y + v.z * v.z + v.w * v.w;

    __shared__ float sh[8];
    #pragma unroll
    for (int o = 16; o; o >>= 1) {
        s  += __shfl_xor_sync(0xffffffffu, s, o);
        ss += __shfl_xor_sync(0xffffffffu, ss, o);
    }
    int w = t >> 5;
    if ((t & 31) == 0) { sh[w] = s; sh[4 + w] = ss; }
    __syncthreads();
    float S  = sh[0] + sh[1] + sh[2] + sh[3];
    float SS = sh[4] + sh[5] + sh[6] + sh[7];

    const float inv = 1.0f / (float)DM;
    float mu = S * inv;
    float var = SS * inv - mu * mu;
    float rs = rsqrtf(var + 1e-5f);

    float4 g4 = ((const float4*)gamma)[t];
    float4 b4 = ((const float4*)beta)[t];
    float4 o4;
    o4.x = (v.x - mu) * rs * g4.x + b4.x;
    o4.y = (v.y - mu) * rs * g4.y + b4.y;
    o4.z = (v.z - mu) * rs * g4.z + b4.z;
    o4.w = (v.w - mu) * rs * g4.w + b4.w;
    ((float4*)(g_xn + (size_t)row * DM))[t] = o4;
}

// ---------------------------------------------------------------------------
// Kernel 2: FiLM params
// ---------------------------------------------------------------------------
__global__ void film_kernel(const float* __restrict__ emb,
                            const float* __restrict__ Wf,
                            const float* __restrict__ bf) {
    __shared__ float se[EMB];
    const int b = blockIdx.x;
    for (int i = threadIdx.x; i < EMB; i += blockDim.x) {
        float e = emb[b * EMB + i];
        se[i] = e / (1.0f + expf(-e));
    }
    __syncthreads();
    for (int j = threadIdx.x; j < 2 * DM; j += blockDim.x) {
        const float4* wr = (const float4*)(Wf + (size_t)j * EMB);
        const float4* sr = (const float4*)se;
        float acc = bf[j];
        #pragma unroll 4
        for (int q = 0; q < EMB / 4; q++) {
            float4 w = wr[q], sv = sr[q];
            acc += w.x * sv.x + w.y * sv.y + w.z * sv.z + w.w * sv.w;
        }
        g_film[b * 2 * DM + j] = acc;
    }
}

// ---------------------------------------------------------------------------
// Kernel 2b: W -> fp16, TILED (64x64 tiles, 128B rows, swizzled)
// ---------------------------------------------------------------------------
__global__ void prep_w(const float* __restrict__ W) {
    int i = blockIdx.x * blockDim.x + threadIdx.x;
    int r = i >> 6;
    int kc = i & 63;
    const float* src = W + (size_t)r * DM + kc * 8;
    float4 v0 = *(const float4*)src;
    float4 v1 = *(const float4*)(src + 4);
    float e[8] = {v0.x, v0.y, v0.z, v0.w, v1.x, v1.y, v1.z, v1.w};
    uint32_t hw[4];
    #pragma unroll
    for (int j = 0; j < 4; j++) {
        us h0 = __half_as_ushort(__float2half_rn(e[j * 2]));
        us h1 = __half_as_ushort(__float2half_rn(e[j * 2 + 1]));
        hw[j] = (uint32_t)h0 | ((uint32_t)h1 << 16);
    }
    int row = r & 63;
    int chunk = (kc & 7) ^ (row & 7);
    size_t off = ((size_t)((r >> 6) * 8 + (kc >> 3)) << 12)
               + (size_t)row * 64 + (chunk << 3);
    *(uint4*)(g_Wh + off) = make_uint4(hw[0], hw[1], hw[2], hw[3]);
}

// ---------------------------------------------------------------------------
// Kernel 3: transpose x -> g_Xt (per-d [col=(b,c)][j], fp16, swizzled rows)
// ---------------------------------------------------------------------------
__global__ void xt_kernel() {
    const int blk = blockIdx.x;
    const int b = blk >> 8;
    const int c = (blk >> 4) & 15;
    const int dg = blk & 15;
    const int d0 = dg * 32;
    const int t = threadIdx.x;   // 256

    __shared__ float tile[128][33];
    #pragma unroll
    for (int it = 0; it < 16; it++) {
        int flat = t + it * 256;
        int j = flat >> 5, dd = flat & 31;
        tile[j][dd] = g_xn[((size_t)(b * 2048 + c * 128 + j)) * DM + d0 + dd];
    }
    __syncthreads();

    const int r = b * 16 + c;
    #pragma unroll
    for (int it = 0; it < 2; it++) {
        int flat = t + it * 256;
        int dd = flat >> 4, ch = flat & 15;
        us h8[8];
        #pragma unroll
        for (int e = 0; e < 8; e++)
            h8[e] = __half_as_ushort(__float2half_rn(tile[ch * 8 + e][dd]));
        us* dst = g_Xt + (size_t)(d0 + dd) * 16384 + r * 128 + ((ch ^ (r & 7)) << 3);
        *(uint4*)dst = *(const uint4*)h8;
    }
}

// ---------------------------------------------------------------------------
// Kernel 4: per-d matrix builder — PARALLEL version.
// Binary lambda-power table in SMEM; fills U, K (from closed form), V,
// Toeplitz(K); conflict-aware writeouts. 512 blocks x 128 threads.
// ---------------------------------------------------------------------------
__global__ void __launch_bounds__(128)
mats_kernel(const float* __restrict__ A_real,
            const float* __restrict__ A_imag,
            const float* __restrict__ Cp,
            const float* __restrict__ log_dt,
            const float* __restrict__ B_ssm,
            const float* __restrict__ D_skip) {
    const int d = blockIdx.x;
    const int t = threadIdx.x;
    const float dt = expf(log_dt[d]);

    __shared__ float2 sL[64][8];   // [n][0..6] = lam^(2^b), [n][7] = dt*Cc_n
    __shared__ float sK[128];
    __shared__ us sM[128 * 128];

    if (t < 64) {
        float ar = dt * A_real[d * NS + t];
        float ai = dt * A_imag[d * NS + t];
        float er = expf(ar), sb, cb;
        sincosf(ai, &sb, &cb);
        float pr = er * cb, pi = er * sb;
        #pragma unroll
        for (int b = 0; b < 7; b++) {
            sL[t][b] = make_float2(pr, pi);
            float nr = pr * pr - pi * pi;
            pi = 2.0f * pr * pi;
            pr = nr;
        }
        float bs = B_ssm[d * NS + t];
        sL[t][7] = make_float2(dt * Cp[(d * NS + t) * 2 + 0] * bs,
                               dt * Cp[(d * NS + t) * 2 + 1] * bs);
    }
    __syncthreads();

    // binary power: lam_n^e for e in [0,128)
    auto cpow = [&](int n, int e) -> float2 {
        float pr = 1.0f, pi = 0.0f;
        #pragma unroll
        for (int b = 0; b < 7; b++) {
            if (e & (1 << b)) {
                float2 w = sL[n][b];
                float nr = pr * w.x - pi * w.y;
                pi = pr * w.y + pi * w.x;
                pr = nr;
            }
        }
        return make_float2(pr, pi);
    };

    // vectorized sM -> global writeout, lane layout: 8 rows x 16 chunks
    auto writeout = [&](us* g) {
        #pragma unroll
        for (int pass = 0; pass < 16; pass++) {
            int task = pass * 128 + t;
            int row = task >> 4, ch = task & 15;
            uint4 v = *(const uint4*)&sM[row * 128 + ch * 8];
            *(uint4*)(g + row * 128 + ((ch ^ (row & 7)) << 3)) = v;
        }
    };

    // ---- Phase U: U[i][n] = Re(dtCc lam^(i+1)), U[i][n+64] = -Im(...) ----
    #pragma unroll
    for (int task = 0; task < 2; task++) {
        int id = t + task * 128;          // 256 tasks: strip = id>>6, n = id&63
        int n = id & 63, strip = id >> 6;
        int i0 = strip * 32;
        float2 cc = sL[n][7];
        float2 p = cpow(n, i0 + 1);
        float2 lam = sL[n][0];
        #pragma unroll 8
        for (int k = 0; k < 32; k++) {
            int i = i0 + k;
            float vr = cc.x * p.x - cc.y * p.y;
            float vi = cc.x * p.y + cc.y * p.x;
            sM[i * 128 + n]      = __half_as_ushort(__float2half_rn(vr));
            sM[i * 128 + n + 64] = __half_as_ushort(__float2half_rn(-vi));
            float nr = p.x * lam.x - p.y * lam.y;
            p.y = p.x * lam.y + p.y * lam.x;
            p.x = nr;
        }
    }

    // ---- K[delta] direct closed form (f32): thread t = delta ----
    {
        float acc = 0.0f;
        if (t == 0) {
            for (int n = 0; n < 64; n++) acc += sL[n][7].x;
            acc += D_skip[d];
        } else {
            for (int n = 0; n < 64; n++) {
                float2 q = cpow(n, t);
                float2 cc = sL[n][7];
                acc += cc.x * q.x - cc.y * q.y;
            }
        }
        sK[t] = acc;
    }
    __syncthreads();
    writeout(g_U + (size_t)d * 16384);
    __syncthreads();

    // ---- Phase V: V[n][j] = Re(lam^(127-j)), V[n+64][j] = Im ----
    #pragma unroll
    for (int task = 0; task < 2; task++) {
        int id = t + task * 128;
        int n = id & 63, strip = id >> 6;
        int e0 = strip * 32;
        float2 p = cpow(n, e0);
        float2 lam = sL[n][0];
        #pragma unroll 8
        for (int k = 0; k < 32; k++) {
            int j = 127 - (e0 + k);
            sM[n * 128 + j]        = __half_as_ushort(__float2half_rn(p.x));
            sM[(n + 64) * 128 + j] = __half_as_ushort(__float2half_rn(p.y));
            float nr = p.x * lam.x - p.y * lam.y;
            p.y = p.x * lam.y + p.y * lam.x;
            p.x = nr;
        }
    }
    __syncthreads();
    writeout(g_V + (size_t)d * 16384);
    __syncthreads();

    // ---- Toeplitz fill BY COLUMN (conflict-free): thread t = column j ----
    #pragma unroll 8
    for (int r = 0; r < 128; r++)
        sM[r * 128 + t] = __half_as_ushort(
            __float2half_rn(t <= r ? sK[r - t] : 0.0f));
    __syncthreads();
    writeout(g_KT + (size_t)d * 16384);
}

// ---------------------------------------------------------------------------
// Kernel 5: per-d fused conv (unchanged from R12).
// ---------------------------------------------------------------------------
#define CV_X   0
#define CV_A0  32768
#define CV_A1  65536
#define CV_S   98304
#define CV_SIN 163840
#define CV_BYTES 196608

__global__ void __launch_bounds__(256, 1)
conv_kernel(const float* __restrict__ A_real,
            const float* __restrict__ A_imag,
            const float* __restrict__ log_dt) {
    extern __shared__ __align__(1024) char smb[];
    __shared__ uint64_t cmb[2];
    const uint32_t sbs = (uint32_t)__cvta_generic_to_shared(smb);
    const uint32_t mb = (uint32_t)__cvta_generic_to_shared(cmb);

    const int d = blockIdx.x;
    const int tid = threadIdx.x;
    const int warp = tid >> 5, lane = tid & 31;
    const int wm = warp & 3;
    const int wn = warp >> 2;
    const int grp = lane >> 2, tig = lane & 3;

    if (tid == 0) {
        mbar_init(mb, 1);
        mbar_init(mb + 8, 1);
    }
    __syncthreads();

    if (tid == 0) {
        mbar_expect_tx(mb, 65536);
        bulk_cp(sbs + CV_X,  (const char*)g_Xt + (size_t)d * 32768, 32768, mb);
        bulk_cp(sbs + CV_A0, (const char*)g_V  + (size_t)d * 32768, 32768, mb);
        mbar_expect_tx(mb + 8, 32768);
        bulk_cp(sbs + CV_A1, (const char*)g_KT + (size_t)d * 32768, 32768, mb + 8);
    }

    float* sYf = (float*)(smb + CV_S);

    auto run_gemm = [&](uint32_t abase, uint32_t bbase, float acc[2][8][4]) {
        #pragma unroll 2
        for (int kk = 0; kk < 8; kk++) {
            uint32_t a[2][4];
            #pragma unroll
            for (int mt = 0; mt < 2; mt++) {
                int rowA = wm * 32 + mt * 16 + (lane & 15);
                int kc = kk * 2 + ((lane & 16) >> 4);
                ldsm4(a[mt], abase + (uint32_t)(rowA * 256 + (((kc) ^ (rowA & 7)) << 4)));
            }
            uint32_t bh[4][4];
            #pragma unroll
            for (int bb = 0; bb < 4; bb++) {
                int rowB = wn * 64 + bb * 16 + ((lane & 16) >> 1) + (lane & 7);
                int kcb = kk * 2 + ((lane >> 3) & 1);
                ldsm4(bh[bb], bbase + (uint32_t)(rowB * 256 + (((kcb) ^ (rowB & 7)) << 4)));
            }
            #pragma unroll
            for (int mt = 0; mt < 2; mt++)
                #pragma unroll
                for (int bb = 0; bb < 4; bb++) {
                    mma_f16(acc[mt][bb * 2 + 0], a[mt], bh[bb][0], bh[bb][1]);
                    mma_f16(acc[mt][bb * 2 + 1], a[mt], bh[bb][2], bh[bb][3]);
                }
        }
    };
    auto store_frags = [&](float acc[2][8][4]) {
        #pragma unroll
        for (int mt = 0; mt < 2; mt++)
            #pragma unroll
            for (int nt = 0; nt < 8; nt++) {
                int r0 = wm * 32 + mt * 16 + grp;
                int c0 = wn * 64 + nt * 8 + tig * 2;
                *(float2*)&sYf[r0 * 128 + c0] =
                    make_float2(acc[mt][nt][0], acc[mt][nt][1]);
                *(float2*)&sYf[(r0 + 8) * 128 + c0] =
                    make_float2(acc[mt][nt][2], acc[mt][nt][3]);
            }
    };

    float acc[2][8][4];
    #pragma unroll
    for (int mt = 0; mt < 2; mt++)
        #pragma unroll
        for (int nt = 0; nt < 8; nt++)
            #pragma unroll
            for (int r = 0; r < 4; r++) acc[mt][nt][r] = 0.0f;

    mbar_wait(mb, 0);
    run_gemm(sbs + CV_A0, sbs + CV_X, acc);
    store_frags(acc);
    __syncthreads();

    if (tid == 0) {
        mbar_expect_tx(mb, 32768);
        bulk_cp(sbs + CV_A0, (const char*)g_U + (size_t)d * 32768, 32768, mb);
    }

    {
        const float dt = expf(log_dt[d]);
        us* sIn = (us*)(smb + CV_SIN);
        #pragma unroll
        for (int it = 0; it < 2; it++) {
            int idx = tid + it * 256;
            int n = idx & 63, b = idx >> 6;
            float ar = dt * A_real[d * NS + n];
            float ai = dt * A_imag[d * NS + n];
            float er = expf(ar), sb, cb;
            sincosf(ai, &sb, &cb);
            float pr = er * cb, pi = er * sb;
            #pragma unroll
            for (int q = 0; q < 7; q++) {
                float nr = pr * pr - pi * pi;
                pi = 2.0f * pr * pi;
                pr = nr;
            }
            float runr = 0.0f, runi = 0.0f;
            for (int c = 0; c < NCH; c++) {
                int col = b * 16 + c;
                sIn[tswz(col, n)]      = __half_as_ushort(__float2half_rn(runr));
                sIn[tswz(col, n + 64)] = __half_as_ushort(__float2half_rn(runi));
                float s_re = sYf[n * 128 + col];
                float s_im = sYf[(n + 64) * 128 + col];
                float nr = pr * runr - pi * runi + s_re;
                runi = pr * runi + pi * runr + s_im;
                runr = nr;
            }
        }
    }
    __syncthreads();

    #pragma unroll
    for (int mt = 0; mt < 2; mt++)
        #pragma unroll
        for (int nt = 0; nt < 8; nt++)
            #pragma unroll
            for (int r = 0; r < 4; r++) acc[mt][nt][r] = 0.0f;

    mbar_wait(mb + 8, 0);
    run_gemm(sbs + CV_A1, sbs + CV_X, acc);
    mbar_wait(mb, 1);
    run_gemm(sbs + CV_A0, sbs + CV_SIN, acc);
    store_frags(acc);
    __syncthreads();

    {
        int col = tid & 127;
        int ib = tid >> 7;
        int b = col >> 4;
        float mult  = 1.0f + g_film[b * 2 * DM + d];
        float shift = g_film[b * 2 * DM + DM + d];
        size_t tbase = ((size_t)(col * 8 + (d >> 6)) << 13) + (d & 7);
        int dch = (d & 63) >> 3;
        #pragma unroll 4
        for (int ii = 0; ii < 64; ii++) {
            int i = ib * 64 + ii;
            float v = sYf[i * 128 + col] * mult + shift;
            g_y2h[tbase + i * 64 + ((dch ^ (i & 7)) << 3)] =
                __half_as_ushort(__float2half_rn(v));
        }
    }
}

// ---------------------------------------------------------------------------
// Kernel 6: out_proj GEMM (unchanged).
// ---------------------------------------------------------------------------
#define GSTG 24576
#define NSTG 2
#define GSM_BYTES (NSTG * GSTG)

__global__ void __launch_bounds__(256, 2)
gemm_glu_tc(const float* __restrict__ bo,
            const float* __restrict__ resid,
            float* __restrict__ out) {
    extern __shared__ __align__(1024) char smb[];
    __shared__ uint64_t mbar_store[2 * NSTG];
    const uint32_t sbs = (uint32_t)__cvta_generic_to_shared(smb);
    const uint32_t mb = (uint32_t)__cvta_generic_to_shared(mbar_store);

    const int tid = threadIdx.x;
    const int mblk = blockIdx.x;
    const int cblk = blockIdx.y;
    const int m0 = mblk * 64;
    const int c0 = cblk * 64;
    const int warp = tid >> 5, lane = tid & 31;
    const int wm = warp >> 2;
    const int wn = warp & 3;
    const int grp = lane >> 2, tig = lane & 3;

    if (tid == 0) {
        #pragma unroll
        for (int s = 0; s < NSTG; s++) {
            mbar_init(mb + s * 8, 1);
            mbar_init(mb + (NSTG + s) * 8, 256);
        }
    }
    __syncthreads();

    const size_t mtile = mblk >> 1;
    const size_t ahalf = (size_t)(mblk & 1) * 8192;

    auto issue_stage = [&](int it) {
        int s = it & 1;
        uint32_t full = mb + s * 8;
        mbar_expect_tx(full, GSTG);
        uint32_t st = sbs + s * GSTG;
        bulk_cp(st,         (const char*)g_y2h + ((mtile * 8 + it) << 14) + ahalf, 8192, full);
        bulk_cp(st + 8192,  (const char*)g_Wh + (((size_t)cblk * 8 + it) << 13), 8192, full);
        bulk_cp(st + 16384, (const char*)g_Wh + (((size_t)(8 + cblk) * 8 + it) << 13), 8192, full);
    };

    if (tid == 0) { issue_stage(0); issue_stage(1); }

    float dacc[2][4][4];
    #pragma unroll
    for (int mt = 0; mt < 2; mt++)
        #pragma unroll
        for (int nt = 0; nt < 4; nt++)
            #pragma unroll
            for (int r = 0; r < 4; r++) dacc[mt][nt][r] = 0.0f;

    const int rowA0 = wm * 32 + (lane & 15);
    const int chA0 = lane >> 4;
    const int rowB0 = wn * 32 + ((lane & 16) >> 1) + (lane & 7);
    const int chB0 = (lane >> 3) & 1;

    const int NKT = 8;
    for (int it = 0; it < NKT; it++) {
        const int s = it & 1;
        const int q = it >> 1;
        mbar_wait(mb + s * 8, q & 1);
        const uint32_t st = sbs + s * GSTG;

        #pragma unroll
        for (int kk = 0; kk < 4; kk++) {
            uint32_t ah[2][4];
            #pragma unroll
            for (int mt = 0; mt < 2; mt++) {
                int rowA = rowA0 + mt * 16;
                int ch = (2 * kk + chA0) ^ (rowA & 7);
                ldsm4(ah[mt], st + (uint32_t)(rowA * 128 + ch * 16));
            }
            uint32_t bh[8];
            #pragma unroll
            for (int go = 0; go < 2; go++) {
                int rr = rowB0 + go * 16;
                int cs = (2 * kk + chB0) ^ (rr & 7);
                ldsm4(&bh[go * 4], st + 8192 + (uint32_t)(rr * 128 + cs * 16));
            }
            #pragma unroll
            for (int mt = 0; mt < 2; mt++)
                #pragma unroll
                for (int nt = 0; nt < 4; nt++)
                    mma_f16(dacc[mt][nt], ah[mt], bh[nt * 2], bh[nt * 2 + 1]);
        }

        mbar_arrive(mb + (NSTG + s) * 8);
        if (tid == 0 && it + NSTG < NKT) {
            mbar_wait(mb + (NSTG + s) * 8, q & 1);
            issue_stage(it + NSTG);
        }
    }

    __syncthreads();
    float* sig = (float*)smb;

    if (wn >= 2) {
        #pragma unroll
        for (int mt = 0; mt < 2; mt++) {
            #pragma unroll
            for (int nt = 0; nt < 4; nt++) {
                int gcol = (wn - 2) * 32 + nt * 8 + tig * 2;
                float bg0 = bo[DM + c0 + gcol];
                float bg1 = bo[DM + c0 + gcol + 1];
                #pragma unroll
                for (int half = 0; half < 2; half++) {
                    int ml = wm * 32 + mt * 16 + grp + half * 8;
                    float g0 = dacc[mt][nt][half * 2 + 0] + bg0;
                    float g1 = dacc[mt][nt][half * 2 + 1] + bg1;
                    sig[ml * 68 + gcol]     = 1.0f / (1.0f + expf(-g0));
                    sig[ml * 68 + gcol + 1] = 1.0f / (1.0f + expf(-g1));
                }
            }
        }
    }
    __syncthreads();
    if (wn < 2) {
        #pragma unroll
        for (int mt = 0; mt < 2; mt++) {
            #pragma unroll
            for (int nt = 0; nt < 4; nt++) {
                int col = wn * 32 + nt * 8 + tig * 2;
                float ba0 = bo[c0 + col];
                float ba1 = bo[c0 + col + 1];
                #pragma unroll
                for (int half = 0; half < 2; half++) {
                    int ml = wm * 32 + mt * 16 + grp + half * 8;
                    int r = m0 + ml;
                    float a0 = dacc[mt][nt][half * 2 + 0] + ba0;
                    float a1 = dacc[mt][nt][half * 2 + 1] + ba1;
                    float s0 = sig[ml * 68 + col];
                    float s1 = sig[ml * 68 + col + 1];
                    float2 res = *(const float2*)(resid + (size_t)r * DM + c0 + col);
                    float2 o;
                    o.x = res.x + a0 * s0;
                    o.y = res.y + a1 * s1;
                    *(float2*)(out + (size_t)r * DM + c0 + col) = o;
                }
            }
        }
    }
}

// ---------------------------------------------------------------------------
extern "C" void kernel_launch(void* const* d_in, const int* in_sizes, int n_in,
                              void* d_out, int out_size) {
    const float* x      = (const float*)d_in[0];
    const float* emb    = (const float*)d_in[1];
    const float* A_real = (const float*)d_in[2];
    const float* A_imag = (const float*)d_in[3];
    const float* C      = (const float*)d_in[4];
    const float* log_dt = (const float*)d_in[5];
    const float* B_ssm  = (const float*)d_in[6];
    const float* D_skip = (const float*)d_in[7];
    const float* ln_g   = (const float*)d_in[8];
    const float* ln_b   = (const float*)d_in[9];
    const float* W_out  = (const float*)d_in[10];
    const float* b_out  = (const float*)d_in[11];
    const float* W_film = (const float*)d_in[12];
    const float* b_film = (const float*)d_in[13];
    float* out = (float*)d_out;

    static bool configured = false;
    if (!configured) {
        cudaFuncSetAttribute(gemm_glu_tc,
                             cudaFuncAttributeMaxDynamicSharedMemorySize,
                             GSM_BYTES);
        cudaFuncSetAttribute(conv_kernel,
                             cudaFuncAttributeMaxDynamicSharedMemorySize,
                             CV_BYTES);
        configured = true;
    }

    ln_kernel<<<BSZ * LSEQ, 128>>>(x, ln_g, ln_b);
    film_kernel<<<BSZ, 256>>>(emb, W_film, b_film);
    prep_w<<<256, 256>>>(W_out);
    mats_kernel<<<DM, 128>>>(A_real, A_imag, C, log_dt, B_ssm, D_skip);
    xt_kernel<<<BSZ * NCH * 16, 256>>>();
    conv_kernel<<<DM, 256, CV_BYTES>>>(A_real, A_imag, log_dt);
    gemm_glu_tc<<<dim3((BSZ * LSEQ) / 64, DM / 64), 256, GSM_BYTES>>>(b_out, x, out);
}

// round 14
// speedup vs baseline: 2.0348x; 1.0070x over previous
#include <cuda_runtime.h>
#include <cuda_fp16.h>
#include <math.h>
#include <stdint.h>

#define BSZ 8
#define LSEQ 2048
#define DM 512
#define NS 64
#define EMB 512
#define TCH 128
#define NCH 16

typedef unsigned long long ull;
typedef unsigned short us;

// ---------------------------------------------------------------------------
// Global scratch. fp16 matrices per-d: [128 rows][128 k], 256B rows,
// 16B chunks swizzled: chunk ^= (row & 7).
// ---------------------------------------------------------------------------
__device__ float g_mu[BSZ * LSEQ];
__device__ float g_rs[BSZ * LSEQ];
__device__ __align__(1024) us g_Xt[DM * 128 * 128];
__device__ __align__(1024) us g_KT[DM * 128 * 128];
__device__ __align__(1024) us g_V [DM * 128 * 128];
__device__ __align__(1024) us g_U [DM * 128 * 128];
__device__ __align__(1024) us g_y2h[BSZ * LSEQ * DM];
__device__ __align__(1024) us g_Wh[2 * DM * DM];
__device__ float g_film[BSZ * 2 * DM];

__device__ __forceinline__ int tswz(int r, int e) {
    return r * 128 + (((e >> 3) ^ (r & 7)) << 3) + (e & 7);
}

// mbarrier helpers
__device__ __forceinline__ void mbar_init(uint32_t a, uint32_t cnt) {
    asm volatile("mbarrier.init.shared.b64 [%0], %1;" :: "r"(a), "r"(cnt) : "memory");
}
__device__ __forceinline__ void mbar_expect_tx(uint32_t a, uint32_t tx) {
    asm volatile("mbarrier.arrive.expect_tx.shared.b64 _, [%0], %1;" :: "r"(a), "r"(tx) : "memory");
}
__device__ __forceinline__ void mbar_arrive(uint32_t a) {
    asm volatile("mbarrier.arrive.shared.b64 _, [%0];" :: "r"(a) : "memory");
}
__device__ __forceinline__ void mbar_wait(uint32_t a, int parity) {
    asm volatile(
        "{\n\t.reg .pred P;\n"
        "LW_%=:\n\t"
        "mbarrier.try_wait.parity.acquire.cta.shared::cta.b64 P, [%0], %1, 0x989680;\n\t"
        "@P bra.uni LD_%=;\n\t"
        "bra.uni LW_%=;\n"
        "LD_%=:\n\t}"
        :: "r"(a), "r"(parity) : "memory");
}
__device__ __forceinline__ void bulk_cp(uint32_t dst, const void* src,
                                        uint32_t bytes, uint32_t mbar) {
    asm volatile(
        "cp.async.bulk.shared::cta.global.mbarrier::complete_tx::bytes [%0], [%1], %2, [%3];"
        :: "r"(dst), "l"(src), "r"(bytes), "r"(mbar) : "memory");
}

__device__ __forceinline__ void mma_f16(float d[4], const uint32_t a[4],
                                        const uint32_t b0, const uint32_t b1) {
    asm volatile(
        "mma.sync.aligned.m16n8k16.row.col.f32.f16.f16.f32 "
        "{%0,%1,%2,%3}, {%4,%5,%6,%7}, {%8,%9}, {%0,%1,%2,%3};\n"
        : "+f"(d[0]), "+f"(d[1]), "+f"(d[2]), "+f"(d[3])
        : "r"(a[0]), "r"(a[1]), "r"(a[2]), "r"(a[3]), "r"(b0), "r"(b1));
}
__device__ __forceinline__ void ldsm4(uint32_t* r, uint32_t byteaddr) {
    asm volatile("ldmatrix.sync.aligned.m8n8.x4.shared.b16 {%0,%1,%2,%3}, [%4];"
        : "=r"(r[0]), "=r"(r[1]), "=r"(r[2]), "=r"(r[3]) : "r"(byteaddr));
}

// ---------------------------------------------------------------------------
// Kernel 1: LN stats only (mu, 1/sigma per row)
// ---------------------------------------------------------------------------
__global__ void ln_stats(const float* __restrict__ x) {
    const int row = blockIdx.x;
    const int t = threadIdx.x;
    float4 v = ((const float4*)(x + (size_t)row * DM))[t];
    float s  = v.x + v.y + v.z + v.w;
    float ss = v.x * v.x + v.y * v.y + v.z * v.z + v.w * v.w;

    __shared__ float sh[8];
    #pragma unroll
    for (int o = 16; o; o >>= 1) {
        s  += __shfl_xor_sync(0xffffffffu, s, o);
        ss += __shfl_xor_sync(0xffffffffu, ss, o);
    }
    int w = t >> 5;
    if ((t & 31) == 0) { sh[w] = s; sh[4 + w] = ss; }
    __syncthreads();
    if (t == 0) {
        float S  = sh[0] + sh[1] + sh[2] + sh[3];
        float SS = sh[4] + sh[5] + sh[6] + sh[7];
        const float inv = 1.0f / (float)DM;
        float mu = S * inv;
        float var = SS * inv - mu * mu;
        g_mu[row] = mu;
        g_rs[row] = rsqrtf(var + 1e-5f);
    }
}

// ---------------------------------------------------------------------------
// Kernel 2: FiLM params
// ---------------------------------------------------------------------------
__global__ void film_kernel(const float* __restrict__ emb,
                            const float* __restrict__ Wf,
                            const float* __restrict__ bf) {
    __shared__ float se[EMB];
    const int b = blockIdx.x;
    for (int i = threadIdx.x; i < EMB; i += blockDim.x) {
        float e = emb[b * EMB + i];
        se[i] = e / (1.0f + expf(-e));
    }
    __syncthreads();
    for (int j = threadIdx.x; j < 2 * DM; j += blockDim.x) {
        const float4* wr = (const float4*)(Wf + (size_t)j * EMB);
        const float4* sr = (const float4*)se;
        float acc = bf[j];
        #pragma unroll 4
        for (int q = 0; q < EMB / 4; q++) {
            float4 w = wr[q], sv = sr[q];
            acc += w.x * sv.x + w.y * sv.y + w.z * sv.z + w.w * sv.w;
        }
        g_film[b * 2 * DM + j] = acc;
    }
}

// ---------------------------------------------------------------------------
// Kernel 2b: W -> fp16, TILED
// ---------------------------------------------------------------------------
__global__ void prep_w(const float* __restrict__ W) {
    int i = blockIdx.x * blockDim.x + threadIdx.x;
    int r = i >> 6;
    int kc = i & 63;
    const float* src = W + (size_t)r * DM + kc * 8;
    float4 v0 = *(const float4*)src;
    float4 v1 = *(const float4*)(src + 4);
    float e[8] = {v0.x, v0.y, v0.z, v0.w, v1.x, v1.y, v1.z, v1.w};
    uint32_t hw[4];
    #pragma unroll
    for (int j = 0; j < 4; j++) {
        us h0 = __half_as_ushort(__float2half_rn(e[j * 2]));
        us h1 = __half_as_ushort(__float2half_rn(e[j * 2 + 1]));
        hw[j] = (uint32_t)h0 | ((uint32_t)h1 << 16);
    }
    int row = r & 63;
    int chunk = (kc & 7) ^ (row & 7);
    size_t off = ((size_t)((r >> 6) * 8 + (kc >> 3)) << 12)
               + (size_t)row * 64 + (chunk << 3);
    *(uint4*)(g_Wh + off) = make_uint4(hw[0], hw[1], hw[2], hw[3]);
}

// ---------------------------------------------------------------------------
// Kernel 3: fused LN-apply + transpose x -> g_Xt
// ---------------------------------------------------------------------------
__global__ void xt_kernel(const float* __restrict__ x,
                          const float* __restrict__ gamma,
                          const float* __restrict__ beta) {
    const int blk = blockIdx.x;
    const int b = blk >> 8;
    const int c = (blk >> 4) & 15;
    const int dg = blk & 15;
    const int d0 = dg * 32;
    const int t = threadIdx.x;   // 256

    __shared__ float tile[128][33];
    __shared__ float smu[128], srs[128];
    const int row0 = b * 2048 + c * 128;
    if (t < 128) {
        smu[t] = g_mu[row0 + t];
        srs[t] = g_rs[row0 + t];
    }
    #pragma unroll
    for (int it = 0; it < 16; it++) {
        int flat = t + it * 256;
        int j = flat >> 5, dd = flat & 31;
        tile[j][dd] = x[((size_t)(row0 + j)) * DM + d0 + dd];
    }
    __syncthreads();

    const int r = b * 16 + c;
    #pragma unroll
    for (int it = 0; it < 2; it++) {
        int flat = t + it * 256;
        int dd = flat >> 4, ch = flat & 15;
        float gm = gamma[d0 + dd], bt = beta[d0 + dd];
        us h8[8];
        #pragma unroll
        for (int e = 0; e < 8; e++) {
            int j = ch * 8 + e;
            float v = (tile[j][dd] - smu[j]) * srs[j] * gm + bt;
            h8[e] = __half_as_ushort(__float2half_rn(v));
        }
        us* dst = g_Xt + (size_t)(d0 + dd) * 16384 + r * 128 + ((ch ^ (r & 7)) << 3);
        *(uint4*)dst = *(const uint4*)h8;
    }
}

// ---------------------------------------------------------------------------
// Kernel 4: per-d matrix builder, 256 threads.
// ---------------------------------------------------------------------------
__global__ void __launch_bounds__(256)
mats_kernel(const float* __restrict__ A_real,
            const float* __restrict__ A_imag,
            const float* __restrict__ Cp,
            const float* __restrict__ log_dt,
            const float* __restrict__ B_ssm,
            const float* __restrict__ D_skip) {
    const int d = blockIdx.x;
    const int t = threadIdx.x;
    const float dt = expf(log_dt[d]);

    __shared__ float2 sL[64][8];   // [n][0..6] = lam^(2^b), [n][7] = dt*Cc_n
    __shared__ float sK[128];
    __shared__ float sKp[2][128];
    __shared__ us sM[128 * 128];

    if (t < 64) {
        float ar = dt * A_real[d * NS + t];
        float ai = dt * A_imag[d * NS + t];
        float er = expf(ar), sb, cb;
        sincosf(ai, &sb, &cb);
        float pr = er * cb, pi = er * sb;
        #pragma unroll
        for (int b = 0; b < 7; b++) {
            sL[t][b] = make_float2(pr, pi);
            float nr = pr * pr - pi * pi;
            pi = 2.0f * pr * pi;
            pr = nr;
        }
        float bs = B_ssm[d * NS + t];
        sL[t][7] = make_float2(dt * Cp[(d * NS + t) * 2 + 0] * bs,
                               dt * Cp[(d * NS + t) * 2 + 1] * bs);
    }
    __syncthreads();

    auto cpow = [&](int n, int e) -> float2 {
        float pr = 1.0f, pi = 0.0f;
        #pragma unroll
        for (int b = 0; b < 7; b++) {
            if (e & (1 << b)) {
                float2 w = sL[n][b];
                float nr = pr * w.x - pi * w.y;
                pi = pr * w.y + pi * w.x;
                pr = nr;
            }
        }
        return make_float2(pr, pi);
    };

    // writeout: 2048 uint4 tasks over 256 threads
    auto writeout = [&](us* g) {
        #pragma unroll
        for (int pass = 0; pass < 8; pass++) {
            int task = pass * 256 + t;
            int row = task >> 4, ch = task & 15;
            uint4 v = *(const uint4*)&sM[row * 128 + ch * 8];
            *(uint4*)(g + row * 128 + ((ch ^ (row & 7)) << 3)) = v;
        }
    };

    // ---- U: 256 tasks, 1 per thread: n = t&63, strip = t>>6 (32 rows) ----
    {
        int n = t & 63, strip = t >> 6;
        int i0 = strip * 32;
        float2 cc = sL[n][7];
        float2 p = cpow(n, i0 + 1);
        float2 lam = sL[n][0];
        #pragma unroll 8
        for (int k = 0; k < 32; k++) {
            int i = i0 + k;
            float vr = cc.x * p.x - cc.y * p.y;
            float vi = cc.x * p.y + cc.y * p.x;
            sM[i * 128 + n]      = __half_as_ushort(__float2half_rn(vr));
            sM[i * 128 + n + 64] = __half_as_ushort(__float2half_rn(-vi));
            float nr = p.x * lam.x - p.y * lam.y;
            p.y = p.x * lam.y + p.y * lam.x;
            p.x = nr;
        }
    }

    // ---- K[delta] split: delta = t&127, half = t>>7 sums 32 n's ----
    {
        int del = t & 127, half = t >> 7;
        float acc = 0.0f;
        if (del == 0) {
            for (int n = half * 32; n < half * 32 + 32; n++) acc += sL[n][7].x;
            if (half == 0) acc += D_skip[d];
        } else {
            for (int n = half * 32; n < half * 32 + 32; n++) {
                float2 q = cpow(n, del);
                float2 cc = sL[n][7];
                acc += cc.x * q.x - cc.y * q.y;
            }
        }
        sKp[half][del] = acc;
    }
    __syncthreads();
    if (t < 128) sK[t] = sKp[0][t] + sKp[1][t];
    writeout(g_U + (size_t)d * 16384);
    __syncthreads();

    // ---- V: 256 tasks, 1 per thread ----
    {
        int n = t & 63, strip = t >> 6;
        int e0 = strip * 32;
        float2 p = cpow(n, e0);
        float2 lam = sL[n][0];
        #pragma unroll 8
        for (int k = 0; k < 32; k++) {
            int j = 127 - (e0 + k);
            sM[n * 128 + j]        = __half_as_ushort(__float2half_rn(p.x));
            sM[(n + 64) * 128 + j] = __half_as_ushort(__float2half_rn(p.y));
            float nr = p.x * lam.x - p.y * lam.y;
            p.y = p.x * lam.y + p.y * lam.x;
            p.x = nr;
        }
    }
    __syncthreads();
    writeout(g_V + (size_t)d * 16384);
    __syncthreads();

    // ---- Toeplitz by column, rows split in halves ----
    {
        int j = t & 127, half = t >> 7;
        #pragma unroll 8
        for (int rr = half * 64; rr < half * 64 + 64; rr++)
            sM[rr * 128 + j] = __half_as_ushort(
                __float2half_rn(j <= rr ? sK[rr - j] : 0.0f));
    }
    __syncthreads();
    writeout(g_KT + (size_t)d * 16384);
}

// ---------------------------------------------------------------------------
// Kernel 5: per-d fused conv (unchanged from R13).
// ---------------------------------------------------------------------------
#define CV_X   0
#define CV_A0  32768
#define CV_A1  65536
#define CV_S   98304
#define CV_SIN 163840
#define CV_BYTES 196608

__global__ void __launch_bounds__(256, 1)
conv_kernel(const float* __restrict__ A_real,
            const float* __restrict__ A_imag,
            const float* __restrict__ log_dt) {
    extern __shared__ __align__(1024) char smb[];
    __shared__ uint64_t cmb[2];
    const uint32_t sbs = (uint32_t)__cvta_generic_to_shared(smb);
    const uint32_t mb = (uint32_t)__cvta_generic_to_shared(cmb);

    const int d = blockIdx.x;
    const int tid = threadIdx.x;
    const int warp = tid >> 5, lane = tid & 31;
    const int wm = warp & 3;
    const int wn = warp >> 2;
    const int grp = lane >> 2, tig = lane & 3;

    if (tid == 0) {
        mbar_init(mb, 1);
        mbar_init(mb + 8, 1);
    }
    __syncthreads();

    if (tid == 0) {
        mbar_expect_tx(mb, 65536);
        bulk_cp(sbs + CV_X,  (const char*)g_Xt + (size_t)d * 32768, 32768, mb);
        bulk_cp(sbs + CV_A0, (const char*)g_V  + (size_t)d * 32768, 32768, mb);
        mbar_expect_tx(mb + 8, 32768);
        bulk_cp(sbs + CV_A1, (const char*)g_KT + (size_t)d * 32768, 32768, mb + 8);
    }

    float* sYf = (float*)(smb + CV_S);

    auto run_gemm = [&](uint32_t abase, uint32_t bbase, float acc[2][8][4]) {
        #pragma unroll 2
        for (int kk = 0; kk < 8; kk++) {
            uint32_t a[2][4];
            #pragma unroll
            for (int mt = 0; mt < 2; mt++) {
                int rowA = wm * 32 + mt * 16 + (lane & 15);
                int kc = kk * 2 + ((lane & 16) >> 4);
                ldsm4(a[mt], abase + (uint32_t)(rowA * 256 + (((kc) ^ (rowA & 7)) << 4)));
            }
            uint32_t bh[4][4];
            #pragma unroll
            for (int bb = 0; bb < 4; bb++) {
                int rowB = wn * 64 + bb * 16 + ((lane & 16) >> 1) + (lane & 7);
                int kcb = kk * 2 + ((lane >> 3) & 1);
                ldsm4(bh[bb], bbase + (uint32_t)(rowB * 256 + (((kcb) ^ (rowB & 7)) << 4)));
            }
            #pragma unroll
            for (int mt = 0; mt < 2; mt++)
                #pragma unroll
                for (int bb = 0; bb < 4; bb++) {
                    mma_f16(acc[mt][bb * 2 + 0], a[mt], bh[bb][0], bh[bb][1]);
                    mma_f16(acc[mt][bb * 2 + 1], a[mt], bh[bb][2], bh[bb][3]);
                }
        }
    };
    auto store_frags = [&](float acc[2][8][4]) {
        #pragma unroll
        for (int mt = 0; mt < 2; mt++)
            #pragma unroll
            for (int nt = 0; nt < 8; nt++) {
                int r0 = wm * 32 + mt * 16 + grp;
                int c0 = wn * 64 + nt * 8 + tig * 2;
                *(float2*)&sYf[r0 * 128 + c0] =
                    make_float2(acc[mt][nt][0], acc[mt][nt][1]);
                *(float2*)&sYf[(r0 + 8) * 128 + c0] =
                    make_float2(acc[mt][nt][2], acc[mt][nt][3]);
            }
    };

    float acc[2][8][4];
    #pragma unroll
    for (int mt = 0; mt < 2; mt++)
        #pragma unroll
        for (int nt = 0; nt < 8; nt++)
            #pragma unroll
            for (int r = 0; r < 4; r++) acc[mt][nt][r] = 0.0f;

    mbar_wait(mb, 0);
    run_gemm(sbs + CV_A0, sbs + CV_X, acc);
    store_frags(acc);
    __syncthreads();

    if (tid == 0) {
        mbar_expect_tx(mb, 32768);
        bulk_cp(sbs + CV_A0, (const char*)g_U + (size_t)d * 32768, 32768, mb);
    }

    {
        const float dt = expf(log_dt[d]);
        us* sIn = (us*)(smb + CV_SIN);
        #pragma unroll
        for (int it = 0; it < 2; it++) {
            int idx = tid + it * 256;
            int n = idx & 63, b = idx >> 6;
            float ar = dt * A_real[d * NS + n];
            float ai = dt * A_imag[d * NS + n];
            float er = expf(ar), sb, cb;
            sincosf(ai, &sb, &cb);
            float pr = er * cb, pi = er * sb;
            #pragma unroll
            for (int q = 0; q < 7; q++) {
                float nr = pr * pr - pi * pi;
                pi = 2.0f * pr * pi;
                pr = nr;
            }
            float runr = 0.0f, runi = 0.0f;
            for (int c = 0; c < NCH; c++) {
                int col = b * 16 + c;
                sIn[tswz(col, n)]      = __half_as_ushort(__float2half_rn(runr));
                sIn[tswz(col, n + 64)] = __half_as_ushort(__float2half_rn(runi));
                float s_re = sYf[n * 128 + col];
                float s_im = sYf[(n + 64) * 128 + col];
                float nr = pr * runr - pi * runi + s_re;
                runi = pr * runi + pi * runr + s_im;
                runr = nr;
            }
        }
    }
    __syncthreads();

    #pragma unroll
    for (int mt = 0; mt < 2; mt++)
        #pragma unroll
        for (int nt = 0; nt < 8; nt++)
            #pragma unroll
            for (int r = 0; r < 4; r++) acc[mt][nt][r] = 0.0f;

    mbar_wait(mb + 8, 0);
    run_gemm(sbs + CV_A1, sbs + CV_X, acc);
    mbar_wait(mb, 1);
    run_gemm(sbs + CV_A0, sbs + CV_SIN, acc);
    store_frags(acc);
    __syncthreads();

    {
        int col = tid & 127;
        int ib = tid >> 7;
        int b = col >> 4;
        float mult  = 1.0f + g_film[b * 2 * DM + d];
        float shift = g_film[b * 2 * DM + DM + d];
        size_t tbase = ((size_t)(col * 8 + (d >> 6)) << 13) + (d & 7);
        int dch = (d & 63) >> 3;
        #pragma unroll 4
        for (int ii = 0; ii < 64; ii++) {
            int i = ib * 64 + ii;
            float v = sYf[i * 128 + col] * mult + shift;
            g_y2h[tbase + i * 64 + ((dch ^ (i & 7)) << 3)] =
                __half_as_ushort(__float2half_rn(v));
        }
    }
}

// ---------------------------------------------------------------------------
// Kernel 6: out_proj GEMM (unchanged).
// ---------------------------------------------------------------------------
#define GSTG 24576
#define NSTG 2
#define GSM_BYTES (NSTG * GSTG)

__global__ void __launch_bounds__(256, 2)
gemm_glu_tc(const float* __restrict__ bo,
            const float* __restrict__ resid,
            float* __restrict__ out) {
    extern __shared__ __align__(1024) char smb[];
    __shared__ uint64_t mbar_store[2 * NSTG];
    const uint32_t sbs = (uint32_t)__cvta_generic_to_shared(smb);
    const uint32_t mb = (uint32_t)__cvta_generic_to_shared(mbar_store);

    const int tid = threadIdx.x;
    const int mblk = blockIdx.x;
    const int cblk = blockIdx.y;
    const int m0 = mblk * 64;
    const int c0 = cblk * 64;
    const int warp = tid >> 5, lane = tid & 31;
    const int wm = warp >> 2;
    const int wn = warp & 3;
    const int grp = lane >> 2, tig = lane & 3;

    if (tid == 0) {
        #pragma unroll
        for (int s = 0; s < NSTG; s++) {
            mbar_init(mb + s * 8, 1);
            mbar_init(mb + (NSTG + s) * 8, 256);
        }
    }
    __syncthreads();

    const size_t mtile = mblk >> 1;
    const size_t ahalf = (size_t)(mblk & 1) * 8192;

    auto issue_stage = [&](int it) {
        int s = it & 1;
        uint32_t full = mb + s * 8;
        mbar_expect_tx(full, GSTG);
        uint32_t st = sbs + s * GSTG;
        bulk_cp(st,         (const char*)g_y2h + ((mtile * 8 + it) << 14) + ahalf, 8192, full);
        bulk_cp(st + 8192,  (const char*)g_Wh + (((size_t)cblk * 8 + it) << 13), 8192, full);
        bulk_cp(st + 16384, (const char*)g_Wh + (((size_t)(8 + cblk) * 8 + it) << 13), 8192, full);
    };

    if (tid == 0) { issue_stage(0); issue_stage(1); }

    float dacc[2][4][4];
    #pragma unroll
    for (int mt = 0; mt < 2; mt++)
        #pragma unroll
        for (int nt = 0; nt < 4; nt++)
            #pragma unroll
            for (int r = 0; r < 4; r++) dacc[mt][nt][r] = 0.0f;

    const int rowA0 = wm * 32 + (lane & 15);
    const int chA0 = lane >> 4;
    const int rowB0 = wn * 32 + ((lane & 16) >> 1) + (lane & 7);
    const int chB0 = (lane >> 3) & 1;

    const int NKT = 8;
    for (int it = 0; it < NKT; it++) {
        const int s = it & 1;
        const int q = it >> 1;
        mbar_wait(mb + s * 8, q & 1);
        const uint32_t st = sbs + s * GSTG;

        #pragma unroll
        for (int kk = 0; kk < 4; kk++) {
            uint32_t ah[2][4];
            #pragma unroll
            for (int mt = 0; mt < 2; mt++) {
                int rowA = rowA0 + mt * 16;
                int ch = (2 * kk + chA0) ^ (rowA & 7);
                ldsm4(ah[mt], st + (uint32_t)(rowA * 128 + ch * 16));
            }
            uint32_t bh[8];
            #pragma unroll
            for (int go = 0; go < 2; go++) {
                int rr = rowB0 + go * 16;
                int cs = (2 * kk + chB0) ^ (rr & 7);
                ldsm4(&bh[go * 4], st + 8192 + (uint32_t)(rr * 128 + cs * 16));
            }
            #pragma unroll
            for (int mt = 0; mt < 2; mt++)
                #pragma unroll
                for (int nt = 0; nt < 4; nt++)
                    mma_f16(dacc[mt][nt], ah[mt], bh[nt * 2], bh[nt * 2 + 1]);
        }

        mbar_arrive(mb + (NSTG + s) * 8);
        if (tid == 0 && it + NSTG < NKT) {
            mbar_wait(mb + (NSTG + s) * 8, q & 1);
            issue_stage(it + NSTG);
        }
    }

    __syncthreads();
    float* sig = (float*)smb;

    if (wn >= 2) {
        #pragma unroll
        for (int mt = 0; mt < 2; mt++) {
            #pragma unroll
            for (int nt = 0; nt < 4; nt++) {
                int gcol = (wn - 2) * 32 + nt * 8 + tig * 2;
                float bg0 = bo[DM + c0 + gcol];
                float bg1 = bo[DM + c0 + gcol + 1];
                #pragma unroll
                for (int half = 0; half < 2; half++) {
                    int ml = wm * 32 + mt * 16 + grp + half * 8;
                    float g0 = dacc[mt][nt][half * 2 + 0] + bg0;
                    float g1 = dacc[mt][nt][half * 2 + 1] + bg1;
                    sig[ml * 68 + gcol]     = 1.0f / (1.0f + expf(-g0));
                    sig[ml * 68 + gcol + 1] = 1.0f / (1.0f + expf(-g1));
                }
            }
        }
    }
    __syncthreads();
    if (wn < 2) {
        #pragma unroll
        for (int mt = 0; mt < 2; mt++) {
            #pragma unroll
            for (int nt = 0; nt < 4; nt++) {
                int col = wn * 32 + nt * 8 + tig * 2;
                float ba0 = bo[c0 + col];
                float ba1 = bo[c0 + col + 1];
                #pragma unroll
                for (int half = 0; half < 2; half++) {
                    int ml = wm * 32 + mt * 16 + grp + half * 8;
                    int r = m0 + ml;
                    float a0 = dacc[mt][nt][half * 2 + 0] + ba0;
                    float a1 = dacc[mt][nt][half * 2 + 1] + ba1;
                    float s0 = sig[ml * 68 + col];
                    float s1 = sig[ml * 68 + col + 1];
                    float2 res = *(const float2*)(resid + (size_t)r * DM + c0 + col);
                    float2 o;
                    o.x = res.x + a0 * s0;
                    o.y = res.y + a1 * s1;
                    *(float2*)(out + (size_t)r * DM + c0 + col) = o;
                }
            }
        }
    }
}

// ---------------------------------------------------------------------------
extern "C" void kernel_launch(void* const* d_in, const int* in_sizes, int n_in,
                              void* d_out, int out_size) {
    const float* x      = (const float*)d_in[0];
    const float* emb    = (const float*)d_in[1];
    const float* A_real = (const float*)d_in[2];
    const float* A_imag = (const float*)d_in[3];
    const float* C      = (const float*)d_in[4];
    const float* log_dt = (const float*)d_in[5];
    const float* B_ssm  = (const float*)d_in[6];
    const float* D_skip = (const float*)d_in[7];
    const float* ln_g   = (const float*)d_in[8];
    const float* ln_b   = (const float*)d_in[9];
    const float* W_out  = (const float*)d_in[10];
    const float* b_out  = (const float*)d_in[11];
    const float* W_film = (const float*)d_in[12];
    const float* b_film = (const float*)d_in[13];
    float* out = (float*)d_out;

    static bool configured = false;
    if (!configured) {
        cudaFuncSetAttribute(gemm_glu_tc,
                             cudaFuncAttributeMaxDynamicSharedMemorySize,
                             GSM_BYTES);
        cudaFuncSetAttribute(conv_kernel,
                             cudaFuncAttributeMaxDynamicSharedMemorySize,
                             CV_BYTES);
        configured = true;
    }

    ln_stats<<<BSZ * LSEQ, 128>>>(x);
    film_kernel<<<BSZ, 256>>>(emb, W_film, b_film);
    prep_w<<<256, 256>>>(W_out);
    mats_kernel<<<DM, 256>>>(A_real, A_imag, C, log_dt, B_ssm, D_skip);
    xt_kernel<<<BSZ * NCH * 16, 256>>>(x, ln_g, ln_b);
    conv_kernel<<<DM, 256, CV_BYTES>>>(A_real, A_imag, log_dt);
    gemm_glu_tc<<<dim3((BSZ * LSEQ) / 64, DM / 64), 256, GSM_BYTES>>>(b_out, x, out);
}

// round 17
// speedup vs baseline: 2.5549x; 1.2556x over previous
#include <cuda_runtime.h>
#include <cuda_fp16.h>
#include <math.h>
#include <stdint.h>

#define BSZ 8
#define LSEQ 2048
#define DM 512
#define NS 64
#define EMB 512
#define TCH 128
#define NCH 16

typedef unsigned long long ull;
typedef unsigned short us;

// ---------------------------------------------------------------------------
// Global scratch. Per-d fp16 matrices: [128 rows][128 k], 256B rows,
// 16B chunks swizzled: chunk ^= (row & 7).
// ---------------------------------------------------------------------------
__device__ float g_mu[BSZ * LSEQ];
__device__ float g_rs[BSZ * LSEQ];
__device__ __align__(1024) us g_Xt[DM * 128 * 128];
__device__ __align__(1024) us g_KT[DM * 128 * 128];
__device__ __align__(1024) us g_V [DM * 128 * 128];
__device__ __align__(1024) us g_U [DM * 128 * 128];
__device__ __align__(1024) us g_Yt[DM * 128 * 128];   // conv output [d][col][i]
__device__ __align__(1024) us g_y2h[BSZ * LSEQ * DM]; // GEMM-A tiled
__device__ __align__(1024) us g_Wh[2 * DM * DM];
__device__ float g_film[BSZ * 2 * DM];

__device__ __forceinline__ int tswz(int r, int e) {
    return r * 128 + (((e >> 3) ^ (r & 7)) << 3) + (e & 7);
}

// mbarrier helpers
__device__ __forceinline__ void mbar_init(uint32_t a, uint32_t cnt) {
    asm volatile("mbarrier.init.shared.b64 [%0], %1;" :: "r"(a), "r"(cnt) : "memory");
}
__device__ __forceinline__ void mbar_expect_tx(uint32_t a, uint32_t tx) {
    asm volatile("mbarrier.arrive.expect_tx.shared.b64 _, [%0], %1;" :: "r"(a), "r"(tx) : "memory");
}
__device__ __forceinline__ void mbar_arrive(uint32_t a) {
    asm volatile("mbarrier.arrive.shared.b64 _, [%0];" :: "r"(a) : "memory");
}
__device__ __forceinline__ void mbar_wait(uint32_t a, int parity) {
    asm volatile(
        "{\n\t.reg .pred P;\n"
        "LW_%=:\n\t"
        "mbarrier.try_wait.parity.acquire.cta.shared::cta.b64 P, [%0], %1, 0x989680;\n\t"
        "@P bra.uni LD_%=;\n\t"
        "bra.uni LW_%=;\n"
        "LD_%=:\n\t}"
        :: "r"(a), "r"(parity) : "memory");
}
__device__ __forceinline__ void bulk_cp(uint32_t dst, const void* src,
                                        uint32_t bytes, uint32_t mbar) {
    asm volatile(
        "cp.async.bulk.shared::cta.global.mbarrier::complete_tx::bytes [%0], [%1], %2, [%3];"
        :: "r"(dst), "l"(src), "r"(bytes), "r"(mbar) : "memory");
}

__device__ __forceinline__ void mma_f16(float d[4], const uint32_t a[4],
                                        const uint32_t b0, const uint32_t b1) {
    asm volatile(
        "mma.sync.aligned.m16n8k16.row.col.f32.f16.f16.f32 "
        "{%0,%1,%2,%3}, {%4,%5,%6,%7}, {%8,%9}, {%0,%1,%2,%3};\n"
        : "+f"(d[0]), "+f"(d[1]), "+f"(d[2]), "+f"(d[3])
        : "r"(a[0]), "r"(a[1]), "r"(a[2]), "r"(a[3]), "r"(b0), "r"(b1));
}
__device__ __forceinline__ void ldsm4(uint32_t* r, uint32_t byteaddr) {
    asm volatile("ldmatrix.sync.aligned.m8n8.x4.shared.b16 {%0,%1,%2,%3}, [%4];"
        : "=r"(r[0]), "=r"(r[1]), "=r"(r[2]), "=r"(r[3]) : "r"(byteaddr));
}

// ---------------------------------------------------------------------------
// Kernel 1: LN stats (mu, 1/sigma per row)
// ---------------------------------------------------------------------------
__global__ void ln_stats(const float* __restrict__ x) {
    const int row = blockIdx.x;
    const int t = threadIdx.x;
    float4 v = ((const float4*)(x + (size_t)row * DM))[t];
    float s  = v.x + v.y + v.z + v.w;
    float ss = v.x * v.x + v.y * v.y + v.z * v.z + v.w * v.w;

    __shared__ float sh[8];
    #pragma unroll
    for (int o = 16; o; o >>= 1) {
        s  += __shfl_xor_sync(0xffffffffu, s, o);
        ss += __shfl_xor_sync(0xffffffffu, ss, o);
    }
    int w = t >> 5;
    if ((t & 31) == 0) { sh[w] = s; sh[4 + w] = ss; }
    __syncthreads();
    if (t == 0) {
        float S  = sh[0] + sh[1] + sh[2] + sh[3];
        float SS = sh[4] + sh[5] + sh[6] + sh[7];
        const float inv = 1.0f / (float)DM;
        float mu = S * inv;
        float var = SS * inv - mu * mu;
        g_mu[row] = mu;
        g_rs[row] = rsqrtf(var + 1e-5f);
    }
}

// ---------------------------------------------------------------------------
// Kernel 2: FiLM params
// ---------------------------------------------------------------------------
__global__ void film_kernel(const float* __restrict__ emb,
                            const float* __restrict__ Wf,
                            const float* __restrict__ bf) {
    __shared__ float se[EMB];
    const int b = blockIdx.x;
    for (int i = threadIdx.x; i < EMB; i += blockDim.x) {
        float e = emb[b * EMB + i];
        se[i] = e / (1.0f + expf(-e));
    }
    __syncthreads();
    for (int j = threadIdx.x; j < 2 * DM; j += blockDim.x) {
        const float4* wr = (const float4*)(Wf + (size_t)j * EMB);
        const float4* sr = (const float4*)se;
        float acc = bf[j];
        #pragma unroll 4
        for (int q = 0; q < EMB / 4; q++) {
            float4 w = wr[q], sv = sr[q];
            acc += w.x * sv.x + w.y * sv.y + w.z * sv.z + w.w * sv.w;
        }
        g_film[b * 2 * DM + j] = acc;
    }
}

// ---------------------------------------------------------------------------
// Kernel 2b: W -> fp16, TILED
// ---------------------------------------------------------------------------
__global__ void prep_w(const float* __restrict__ W) {
    int i = blockIdx.x * blockDim.x + threadIdx.x;
    int r = i >> 6;
    int kc = i & 63;
    const float* src = W + (size_t)r * DM + kc * 8;
    float4 v0 = *(const float4*)src;
    float4 v1 = *(const float4*)(src + 4);
    float e[8] = {v0.x, v0.y, v0.z, v0.w, v1.x, v1.y, v1.z, v1.w};
    uint32_t hw[4];
    #pragma unroll
    for (int j = 0; j < 4; j++) {
        us h0 = __half_as_ushort(__float2half_rn(e[j * 2]));
        us h1 = __half_as_ushort(__float2half_rn(e[j * 2 + 1]));
        hw[j] = (uint32_t)h0 | ((uint32_t)h1 << 16);
    }
    int row = r & 63;
    int chunk = (kc & 7) ^ (row & 7);
    size_t off = ((size_t)((r >> 6) * 8 + (kc >> 3)) << 12)
               + (size_t)row * 64 + (chunk << 3);
    *(uint4*)(g_Wh + off) = make_uint4(hw[0], hw[1], hw[2], hw[3]);
}

// ---------------------------------------------------------------------------
// Kernel 3: fused LN-apply + transpose x -> g_Xt
// ---------------------------------------------------------------------------
__global__ void xt_kernel(const float* __restrict__ x,
                          const float* __restrict__ gamma,
                          const float* __restrict__ beta) {
    const int blk = blockIdx.x;
    const int b = blk >> 8;
    const int c = (blk >> 4) & 15;
    const int dg = blk & 15;
    const int d0 = dg * 32;
    const int t = threadIdx.x;   // 256

    __shared__ float tile[128][33];
    __shared__ float smu[128], srs[128];
    const int row0 = b * 2048 + c * 128;
    if (t < 128) {
        smu[t] = g_mu[row0 + t];
        srs[t] = g_rs[row0 + t];
    }
    #pragma unroll
    for (int it = 0; it < 16; it++) {
        int flat = t + it * 256;
        int j = flat >> 5, dd = flat & 31;
        tile[j][dd] = x[((size_t)(row0 + j)) * DM + d0 + dd];
    }
    __syncthreads();

    const int r = b * 16 + c;
    #pragma unroll
    for (int it = 0; it < 2; it++) {
        int flat = t + it * 256;
        int dd = flat >> 4, ch = flat & 15;
        float gm = gamma[d0 + dd], bt = beta[d0 + dd];
        us h8[8];
        #pragma unroll
        for (int e = 0; e < 8; e++) {
            int j = ch * 8 + e;
            float v = (tile[j][dd] - smu[j]) * srs[j] * gm + bt;
            h8[e] = __half_as_ushort(__float2half_rn(v));
        }
        us* dst = g_Xt + (size_t)(d0 + dd) * 16384 + r * 128 + ((ch ^ (r & 7)) << 3);
        *(uint4*)dst = *(const uint4*)h8;
    }
}

// ---------------------------------------------------------------------------
// Kernel 4: per-d matrix builder (unchanged from R14).
// ---------------------------------------------------------------------------
__global__ void __launch_bounds__(256)
mats_kernel(const float* __restrict__ A_real,
            const float* __restrict__ A_imag,
            const float* __restrict__ Cp,
            const float* __restrict__ log_dt,
            const float* __restrict__ B_ssm,
            const float* __restrict__ D_skip) {
    const int d = blockIdx.x;
    const int t = threadIdx.x;
    const float dt = expf(log_dt[d]);

    __shared__ float2 sL[64][8];
    __shared__ float sK[128];
    __shared__ float sKp[2][128];
    __shared__ us sM[128 * 128];

    if (t < 64) {
        float ar = dt * A_real[d * NS + t];
        float ai = dt * A_imag[d * NS + t];
        float er = expf(ar), sb, cb;
        sincosf(ai, &sb, &cb);
        float pr = er * cb, pi = er * sb;
        #pragma unroll
        for (int b = 0; b < 7; b++) {
            sL[t][b] = make_float2(pr, pi);
            float nr = pr * pr - pi * pi;
            pi = 2.0f * pr * pi;
            pr = nr;
        }
        float bs = B_ssm[d * NS + t];
        sL[t][7] = make_float2(dt * Cp[(d * NS + t) * 2 + 0] * bs,
                               dt * Cp[(d * NS + t) * 2 + 1] * bs);
    }
    __syncthreads();

    auto cpow = [&](int n, int e) -> float2 {
        float pr = 1.0f, pi = 0.0f;
        #pragma unroll
        for (int b = 0; b < 7; b++) {
            if (e & (1 << b)) {
                float2 w = sL[n][b];
                float nr = pr * w.x - pi * w.y;
                pi = pr * w.y + pi * w.x;
                pr = nr;
            }
        }
        return make_float2(pr, pi);
    };

    auto writeout = [&](us* g) {
        #pragma unroll
        for (int pass = 0; pass < 8; pass++) {
            int task = pass * 256 + t;
            int row = task >> 4, ch = task & 15;
            uint4 v = *(const uint4*)&sM[row * 128 + ch * 8];
            *(uint4*)(g + row * 128 + ((ch ^ (row & 7)) << 3)) = v;
        }
    };

    // U
    {
        int n = t & 63, strip = t >> 6;
        int i0 = strip * 32;
        float2 cc = sL[n][7];
        float2 p = cpow(n, i0 + 1);
        float2 lam = sL[n][0];
        #pragma unroll 8
        for (int k = 0; k < 32; k++) {
            int i = i0 + k;
            float vr = cc.x * p.x - cc.y * p.y;
            float vi = cc.x * p.y + cc.y * p.x;
            sM[i * 128 + n]      = __half_as_ushort(__float2half_rn(vr));
            sM[i * 128 + n + 64] = __half_as_ushort(__float2half_rn(-vi));
            float nr = p.x * lam.x - p.y * lam.y;
            p.y = p.x * lam.y + p.y * lam.x;
            p.x = nr;
        }
    }

    // K[delta]
    {
        int del = t & 127, half = t >> 7;
        float acc = 0.0f;
        if (del == 0) {
            for (int n = half * 32; n < half * 32 + 32; n++) acc += sL[n][7].x;
            if (half == 0) acc += D_skip[d];
        } else {
            for (int n = half * 32; n < half * 32 + 32; n++) {
                float2 q = cpow(n, del);
                float2 cc = sL[n][7];
                acc += cc.x * q.x - cc.y * q.y;
            }
        }
        sKp[half][del] = acc;
    }
    __syncthreads();
    if (t < 128) sK[t] = sKp[0][t] + sKp[1][t];
    writeout(g_U + (size_t)d * 16384);
    __syncthreads();

    // V
    {
        int n = t & 63, strip = t >> 6;
        int e0 = strip * 32;
        float2 p = cpow(n, e0);
        float2 lam = sL[n][0];
        #pragma unroll 8
        for (int k = 0; k < 32; k++) {
            int j = 127 - (e0 + k);
            sM[n * 128 + j]        = __half_as_ushort(__float2half_rn(p.x));
            sM[(n + 64) * 128 + j] = __half_as_ushort(__float2half_rn(p.y));
            float nr = p.x * lam.x - p.y * lam.y;
            p.y = p.x * lam.y + p.y * lam.x;
            p.x = nr;
        }
    }
    __syncthreads();
    writeout(g_V + (size_t)d * 16384);
    __syncthreads();

    // Toeplitz
    {
        int j = t & 127, half = t >> 7;
        #pragma unroll 8
        for (int rr = half * 64; rr < half * 64 + 64; rr++)
            sM[rr * 128 + j] = __half_as_ushort(
                __float2half_rn(j <= rr ? sK[rr - j] : 0.0f));
    }
    __syncthreads();
    writeout(g_KT + (size_t)d * 16384);
}

// ---------------------------------------------------------------------------
// Kernel 5: per-d fused conv. Coalesced epilogue to g_Yt[d][col][i].
// ---------------------------------------------------------------------------
#define CV_X   0
#define CV_A0  32768
#define CV_A1  65536
#define CV_S   98304
#define CV_SIN 163840
#define CV_BYTES 196608

__global__ void __launch_bounds__(256, 1)
conv_kernel(const float* __restrict__ A_real,
            const float* __restrict__ A_imag,
            const float* __restrict__ log_dt) {
    extern __shared__ __align__(1024) char smb[];
    __shared__ uint64_t cmb[2];
    const uint32_t sbs = (uint32_t)__cvta_generic_to_shared(smb);
    const uint32_t mb = (uint32_t)__cvta_generic_to_shared(cmb);

    const int d = blockIdx.x;
    const int tid = threadIdx.x;
    const int warp = tid >> 5, lane = tid & 31;
    const int wm = warp & 3;
    const int wn = warp >> 2;
    const int grp = lane >> 2, tig = lane & 3;

    if (tid == 0) {
        mbar_init(mb, 1);
        mbar_init(mb + 8, 1);
    }
    __syncthreads();

    if (tid == 0) {
        mbar_expect_tx(mb, 65536);
        bulk_cp(sbs + CV_X,  (const char*)g_Xt + (size_t)d * 32768, 32768, mb);
        bulk_cp(sbs + CV_A0, (const char*)g_V  + (size_t)d * 32768, 32768, mb);
        mbar_expect_tx(mb + 8, 32768);
        bulk_cp(sbs + CV_A1, (const char*)g_KT + (size_t)d * 32768, 32768, mb + 8);
    }

    float* sYf = (float*)(smb + CV_S);

    auto run_gemm = [&](uint32_t abase, uint32_t bbase, float acc[2][8][4]) {
        #pragma unroll 2
        for (int kk = 0; kk < 8; kk++) {
            uint32_t a[2][4];
            #pragma unroll
            for (int mt = 0; mt < 2; mt++) {
                int rowA = wm * 32 + mt * 16 + (lane & 15);
                int kc = kk * 2 + ((lane & 16) >> 4);
                ldsm4(a[mt], abase + (uint32_t)(rowA * 256 + (((kc) ^ (rowA & 7)) << 4)));
            }
            uint32_t bh[4][4];
            #pragma unroll
            for (int bb = 0; bb < 4; bb++) {
                int rowB = wn * 64 + bb * 16 + ((lane & 16) >> 1) + (lane & 7);
                int kcb = kk * 2 + ((lane >> 3) & 1);
                ldsm4(bh[bb], bbase + (uint32_t)(rowB * 256 + (((kcb) ^ (rowB & 7)) << 4)));
            }
            #pragma unroll
            for (int mt = 0; mt < 2; mt++)
                #pragma unroll
                for (int bb = 0; bb < 4; bb++) {
                    mma_f16(acc[mt][bb * 2 + 0], a[mt], bh[bb][0], bh[bb][1]);
                    mma_f16(acc[mt][bb * 2 + 1], a[mt], bh[bb][2], bh[bb][3]);
                }
        }
    };
    auto store_frags = [&](float acc[2][8][4]) {
        #pragma unroll
        for (int mt = 0; mt < 2; mt++)
            #pragma unroll
            for (int nt = 0; nt < 8; nt++) {
                int r0 = wm * 32 + mt * 16 + grp;
                int c0 = wn * 64 + nt * 8 + tig * 2;
                *(float2*)&sYf[r0 * 128 + c0] =
                    make_float2(acc[mt][nt][0], acc[mt][nt][1]);
                *(float2*)&sYf[(r0 + 8) * 128 + c0] =
                    make_float2(acc[mt][nt][2], acc[mt][nt][3]);
            }
    };

    float acc[2][8][4];
    #pragma unroll
    for (int mt = 0; mt < 2; mt++)
        #pragma unroll
        for (int nt = 0; nt < 8; nt++)
            #pragma unroll
            for (int r = 0; r < 4; r++) acc[mt][nt][r] = 0.0f;

    mbar_wait(mb, 0);
    run_gemm(sbs + CV_A0, sbs + CV_X, acc);
    store_frags(acc);
    __syncthreads();

    if (tid == 0) {
        mbar_expect_tx(mb, 32768);
        bulk_cp(sbs + CV_A0, (const char*)g_U + (size_t)d * 32768, 32768, mb);
    }

    {
        const float dt = expf(log_dt[d]);
        us* sIn = (us*)(smb + CV_SIN);
        #pragma unroll
        for (int it = 0; it < 2; it++) {
            int idx = tid + it * 256;
            int n = idx & 63, b = idx >> 6;
            float ar = dt * A_real[d * NS + n];
            float ai = dt * A_imag[d * NS + n];
            float er = expf(ar), sb, cb;
            sincosf(ai, &sb, &cb);
            float pr = er * cb, pi = er * sb;
            #pragma unroll
            for (int q = 0; q < 7; q++) {
                float nr = pr * pr - pi * pi;
                pi = 2.0f * pr * pi;
                pr = nr;
            }
            float runr = 0.0f, runi = 0.0f;
            for (int c = 0; c < NCH; c++) {
                int col = b * 16 + c;
                sIn[tswz(col, n)]      = __half_as_ushort(__float2half_rn(runr));
                sIn[tswz(col, n + 64)] = __half_as_ushort(__float2half_rn(runi));
                float s_re = sYf[n * 128 + col];
                float s_im = sYf[(n + 64) * 128 + col];
                float nr = pr * runr - pi * runi + s_re;
                runi = pr * runi + pi * runr + s_im;
                runr = nr;
            }
        }
    }
    __syncthreads();

    #pragma unroll
    for (int mt = 0; mt < 2; mt++)
        #pragma unroll
        for (int nt = 0; nt < 8; nt++)
            #pragma unroll
            for (int r = 0; r < 4; r++) acc[mt][nt][r] = 0.0f;

    mbar_wait(mb + 8, 0);
    run_gemm(sbs + CV_A1, sbs + CV_X, acc);
    mbar_wait(mb, 1);
    run_gemm(sbs + CV_A0, sbs + CV_SIN, acc);
    store_frags(acc);
    __syncthreads();

    // ---- Epilogue: FiLM + coalesced write to g_Yt[d][col][i] ----
    {
        int col = tid & 127;
        int ih = tid >> 7;
        int b = col >> 4;
        float mult  = 1.0f + g_film[b * 2 * DM + d];
        float shift = g_film[b * 2 * DM + DM + d];
        us* dst = g_Yt + (size_t)d * 16384 + col * 128 + ih * 64;
        #pragma unroll
        for (int c8 = 0; c8 < 8; c8++) {
            us h8[8];
            #pragma unroll
            for (int j = 0; j < 8; j++) {
                float v = sYf[(ih * 64 + c8 * 8 + j) * 128 + col] * mult + shift;
                h8[j] = __half_as_ushort(__float2half_rn(v));
            }
            *(uint4*)(dst + c8 * 8) = *(const uint4*)h8;
        }
    }
}

// ---------------------------------------------------------------------------
// Kernel 5b: repack g_Yt[d][col][i] -> g_y2h (A-tiled, swizzled).
// block = (col, dtile): 128 x 8 = 1024 blocks, 128 threads.
// A tile: 128 i-rows x 64 d-cols (8 chunks of 8).
// ---------------------------------------------------------------------------
__global__ void __launch_bounds__(128)
repack_kernel() {
    const int blk = blockIdx.x;
    const int col = blk >> 3;
    const int dtile = blk & 7;
    const int d0 = dtile * 64;
    const int t = threadIdx.x;

    __shared__ us sT[64][136];   // [d'][i], padded

    // read: thread t -> d' = t>>1, half = t&1 : 8 uint4 (64 us per half)
    {
        int dp = t >> 1, half = t & 1;
        const us* src = g_Yt + (size_t)(d0 + dp) * 16384 + col * 128 + half * 64;
        #pragma unroll
        for (int q = 0; q < 8; q++) {
            uint4 v = *(const uint4*)(src + q * 8);
            *(uint4*)&sT[dp][half * 64 + q * 8] = v;
        }
    }
    __syncthreads();

    // write: 1024 chunk tasks: i = task>>3 (0..127), c8 = task&7 (0..7)
    us* tile = g_y2h + ((size_t)(col * 8 + dtile) << 13);
    #pragma unroll
    for (int pass = 0; pass < 8; pass++) {
        int task = pass * 128 + t;
        int i = task >> 3, c8 = task & 7;
        us h8[8];
        #pragma unroll
        for (int j = 0; j < 8; j++)
            h8[j] = sT[c8 * 8 + j][i];
        int ch = c8 ^ (i & 7);
        *(uint4*)(tile + i * 64 + ch * 8) = *(const uint4*)h8;
    }
}

// ---------------------------------------------------------------------------
// Kernel 6: out_proj GEMM, fp16 1-pass, 128m x 128n tile, 2-stage bulk pipe.
// Stage (32KB): A 16K (128x64), B 16K (64 a-rows + 64 g-rows).
// ---------------------------------------------------------------------------
#define GSTG 32768
#define NSTG 2
#define GSM_BYTES (NSTG * GSTG)

__global__ void __launch_bounds__(256, 2)
gemm_glu_tc(const float* __restrict__ bo,
            const float* __restrict__ resid,
            float* __restrict__ out) {
    extern __shared__ __align__(1024) char smb[];
    __shared__ uint64_t mbar_store[2 * NSTG];
    const uint32_t sbs = (uint32_t)__cvta_generic_to_shared(smb);
    const uint32_t mb = (uint32_t)__cvta_generic_to_shared(mbar_store);

    const int tid = threadIdx.x;
    const int mblk = blockIdx.x;          // m0 = mblk*128
    const int cblk = blockIdx.y;          // c0 = cblk*64
    const int m0 = mblk * 128;
    const int c0 = cblk * 64;
    const int warp = tid >> 5, lane = tid & 31;
    const int wm = warp & 3;              // 4 x 32 m-rows
    const int wn = warp >> 2;             // 0 = a-cols, 1 = g-cols
    const int grp = lane >> 2, tig = lane & 3;

    if (tid == 0) {
        #pragma unroll
        for (int s = 0; s < NSTG; s++) {
            mbar_init(mb + s * 8, 1);
            mbar_init(mb + (NSTG + s) * 8, 256);
        }
    }
    __syncthreads();

    auto issue_stage = [&](int it) {
        int s = it & 1;
        uint32_t full = mb + s * 8;
        mbar_expect_tx(full, GSTG);
        uint32_t st = sbs + s * GSTG;
        bulk_cp(st,         (const char*)g_y2h + (((size_t)mblk * 8 + it) << 14), 16384, full);
        bulk_cp(st + 16384, (const char*)g_Wh + (((size_t)cblk * 8 + it) << 13), 8192, full);
        bulk_cp(st + 24576, (const char*)g_Wh + (((size_t)(8 + cblk) * 8 + it) << 13), 8192, full);
    };

    if (tid == 0) { issue_stage(0); issue_stage(1); }

    float dacc[2][8][4];
    #pragma unroll
    for (int mt = 0; mt < 2; mt++)
        #pragma unroll
        for (int nt = 0; nt < 8; nt++)
            #pragma unroll
            for (int r = 0; r < 4; r++) dacc[mt][nt][r] = 0.0f;

    const int rowA0 = wm * 32 + (lane & 15);
    const int chA0 = lane >> 4;
    const int rowB0 = wn * 64 + ((lane & 16) >> 1) + (lane & 7);
    const int chB0 = (lane >> 3) & 1;

    const int NKT = 8;
    for (int it = 0; it < NKT; it++) {
        const int s = it & 1;
        const int q = it >> 1;
        mbar_wait(mb + s * 8, q & 1);
        const uint32_t st = sbs + s * GSTG;

        #pragma unroll
        for (int kk = 0; kk < 4; kk++) {
            uint32_t ah[2][4];
            #pragma unroll
            for (int mt = 0; mt < 2; mt++) {
                int rowA = rowA0 + mt * 16;
                int ch = (2 * kk + chA0) ^ (rowA & 7);
                ldsm4(ah[mt], st + (uint32_t)(rowA * 128 + ch * 16));
            }
            uint32_t bh[4][4];
            #pragma unroll
            for (int bb = 0; bb < 4; bb++) {
                int rr = rowB0 + bb * 16;
                int cs = (2 * kk + chB0) ^ (rr & 7);
                ldsm4(bh[bb], st + 16384 + (uint32_t)(rr * 128 + cs * 16));
            }
            #pragma unroll
            for (int mt = 0; mt < 2; mt++)
                #pragma unroll
                for (int bb = 0; bb < 4; bb++) {
                    mma_f16(dacc[mt][bb * 2 + 0], ah[mt], bh[bb][0], bh[bb][1]);
                    mma_f16(dacc[mt][bb * 2 + 1], ah[mt], bh[bb][2], bh[bb][3]);
                }
        }

        mbar_arrive(mb + (NSTG + s) * 8);
        if (tid == 0 && it + NSTG < NKT) {
            mbar_wait(mb + (NSTG + s) * 8, q & 1);
            issue_stage(it + NSTG);
        }
    }

    // ---- epilogue: GLU + residual ----
    __syncthreads();
    float* sig = (float*)smb;        // [128][68] padded = 34816B

    if (wn == 1) {                   // g-gate warps
        #pragma unroll
        for (int mt = 0; mt < 2; mt++) {
            #pragma unroll
            for (int nt = 0; nt < 8; nt++) {
                int gcol = nt * 8 + tig * 2;
                float bg0 = bo[DM + c0 + gcol];
                float bg1 = bo[DM + c0 + gcol + 1];
                #pragma unroll
                for (int half = 0; half < 2; half++) {
                    int ml = wm * 32 + mt * 16 + grp + half * 8;
                    float g0 = dacc[mt][nt][half * 2 + 0] + bg0;
                    float g1 = dacc[mt][nt][half * 2 + 1] + bg1;
                    sig[ml * 68 + gcol]     = 1.0f / (1.0f + expf(-g0));
                    sig[ml * 68 + gcol + 1] = 1.0f / (1.0f + expf(-g1));
                }
            }
        }
    }
    __syncthreads();
    if (wn == 0) {                   // a-gate warps
        #pragma unroll
        for (int mt = 0; mt < 2; mt++) {
            #pragma unroll
            for (int nt = 0; nt < 8; nt++) {
                int col = nt * 8 + tig * 2;
                float ba0 = bo[c0 + col];
                float ba1 = bo[c0 + col + 1];
                #pragma unroll
                for (int half = 0; half < 2; half++) {
                    int ml = wm * 32 + mt * 16 + grp + half * 8;
                    int r = m0 + ml;
                    float a0 = dacc[mt][nt][half * 2 + 0] + ba0;
                    float a1 = dacc[mt][nt][half * 2 + 1] + ba1;
                    float s0 = sig[ml * 68 + col];
                    float s1 = sig[ml * 68 + col + 1];
                    float2 res = *(const float2*)(resid + (size_t)r * DM + c0 + col);
                    float2 o;
                    o.x = res.x + a0 * s0;
                    o.y = res.y + a1 * s1;
                    *(float2*)(out + (size_t)r * DM + c0 + col) = o;
                }
            }
        }
    }
}

// ---------------------------------------------------------------------------
extern "C" void kernel_launch(void* const* d_in, const int* in_sizes, int n_in,
                              void* d_out, int out_size) {
    const float* x      = (const float*)d_in[0];
    const float* emb    = (const float*)d_in[1];
    const float* A_real = (const float*)d_in[2];
    const float* A_imag = (const float*)d_in[3];
    const float* C      = (const float*)d_in[4];
    const float* log_dt = (const float*)d_in[5];
    const float* B_ssm  = (const float*)d_in[6];
    const float* D_skip = (const float*)d_in[7];
    const float* ln_g   = (const float*)d_in[8];
    const float* ln_b   = (const float*)d_in[9];
    const float* W_out  = (const float*)d_in[10];
    const float* b_out  = (const float*)d_in[11];
    const float* W_film = (const float*)d_in[12];
    const float* b_film = (const float*)d_in[13];
    float* out = (float*)d_out;

    static bool configured = false;
    if (!configured) {
        cudaFuncSetAttribute(gemm_glu_tc,
                             cudaFuncAttributeMaxDynamicSharedMemorySize,
                             GSM_BYTES);
        cudaFuncSetAttribute(conv_kernel,
                             cudaFuncAttributeMaxDynamicSharedMemorySize,
                             CV_BYTES);
        configured = true;
    }

    ln_stats<<<BSZ * LSEQ, 128>>>(x);
    film_kernel<<<BSZ, 256>>>(emb, W_film, b_film);
    prep_w<<<256, 256>>>(W_out);
    mats_kernel<<<DM, 256>>>(A_real, A_imag, C, log_dt, B_ssm, D_skip);
    xt_kernel<<<BSZ * NCH * 16, 256>>>(x, ln_g, ln_b);
    conv_kernel<<<DM, 256, CV_BYTES>>>(A_real, A_imag, log_dt);
    repack_kernel<<<128 * 8, 128>>>();
    gemm_glu_tc<<<dim3((BSZ * LSEQ) / 128, DM / 64), 256, GSM_BYTES>>>(b_out, x, out);
}